// round 1
// baseline (speedup 1.0000x reference)
#include <cuda_runtime.h>
#include <math.h>
#include <float.h>

#define Bb      1024
#define NW      300
#define NT      100      // tokens
#define Ed      5        // embed dim
#define Hh      4        // heads
#define Dd      64       // head dim
#define Ll      3        // layers
#define NTHREADS 256
#define RPW     13       // rows per warp (ceil(100/8))

struct SMem {
    float feat[NT][Ed];      // 500 floats
    float attn[NT][Ed];      // 500
    float maskf[NT];         // 100   -> 1100 floats = 4400 B (16B aligned next)
    float q[NT][Dd];         // 6400  (row stride 256 B, float4-aligned)
    float kT[Dd][NT + 1];    // 6464  (stride 101: banks 5*d+r mod 32, conflict-free)
    float v[NT][Dd];         // 6400  (row stride 256 B, float2-aligned)
    float S[NT][NT];         // 10000 (row stride 400 B, float4-aligned)
};                           // total 121,456 B

__global__ __launch_bounds__(NTHREADS, 1)
void encoder_kernel(const float* __restrict__ x,
                    const float* __restrict__ Wq, const float* __restrict__ Wk,
                    const float* __restrict__ Wv, const float* __restrict__ Wo,
                    const float* __restrict__ Wf, const float* __restrict__ bfb,
                    const float* __restrict__ g1, const float* __restrict__ b1,
                    const float* __restrict__ g2, const float* __restrict__ b2,
                    float* __restrict__ out)
{
    extern __shared__ unsigned char smem_raw[];
    SMem& sm = *reinterpret_cast<SMem*>(smem_raw);

    const int b    = blockIdx.x;
    const int tid  = threadIdx.x;
    const int lane = tid & 31;
    const int w    = tid >> 5;

    // ---------------- embedding + mask ----------------
    if (tid < NT) {
        float k0 = x[b * NW + tid * 3 + 0];
        float k1 = x[b * NW + tid * 3 + 1];
        float k2 = x[b * NW + tid * 3 + 2];
        bool  m  = k2 > 0.0f;
        float sn, cs;
        sincosf((float)tid, &sn, &cs);
        sm.maskf[tid]   = m ? 1.0f : 0.0f;
        sm.feat[tid][0] = m ? k0 : 0.0f;
        sm.feat[tid][1] = m ? k1 : 0.0f;
        sm.feat[tid][2] = m ? k2 : 0.0f;
        sm.feat[tid][3] = m ? sn : 0.0f;
        sm.feat[tid][4] = m ? cs : 0.0f;
    }
    __syncthreads();

    const int i0    = w * RPW;
    const int nrows = (NT - i0) < RPW ? ((NT - i0) > 0 ? (NT - i0) : 0) : RPW;
    const float scale = 0.125f;  // 1/sqrt(64)

    for (int l = 0; l < Ll; ++l) {
        // zero attention-output accumulator
        for (int idx = tid; idx < NT * Ed; idx += NTHREADS)
            (&sm.attn[0][0])[idx] = 0.0f;
        __syncthreads();

        for (int h = 0; h < Hh; ++h) {
            // ---------------- QKV projection ----------------
            {
                const int d       = tid & 63;
                const int quarter = tid >> 6;
                const float* wqp = Wq + ((size_t)((l * Hh + h) * Dd + d)) * Ed;
                const float* wkp = Wk + ((size_t)((l * Hh + h) * Dd + d)) * Ed;
                const float* wvp = Wv + ((size_t)((l * Hh + h) * Dd + d)) * Ed;
                float wq[Ed], wk[Ed], wv[Ed];
                #pragma unroll
                for (int e = 0; e < Ed; ++e) { wq[e] = wqp[e]; wk[e] = wkp[e]; wv[e] = wvp[e]; }
                for (int r = quarter; r < NT; r += 4) {
                    float f[Ed];
                    #pragma unroll
                    for (int e = 0; e < Ed; ++e) f[e] = sm.feat[r][e];
                    float qv = 0.f, kv = 0.f, vv = 0.f;
                    #pragma unroll
                    for (int e = 0; e < Ed; ++e) {
                        qv = fmaf(wq[e], f[e], qv);
                        kv = fmaf(wk[e], f[e], kv);
                        vv = fmaf(wv[e], f[e], vv);
                    }
                    sm.q[r][d]  = qv;
                    sm.kT[d][r] = kv;
                    sm.v[r][d]  = vv;
                }
            }
            __syncthreads();

            // ---------------- scores: S = (Q Kt) * scale, masked ----------------
            for (int jt = 0; jt < 4; ++jt) {
                const int j  = lane + jt * 32;
                const int jj = (j < NT) ? j : 0;
                float acc[RPW];
                #pragma unroll
                for (int r = 0; r < RPW; ++r) acc[r] = 0.0f;
                #pragma unroll 4
                for (int d4 = 0; d4 < Dd / 4; ++d4) {
                    float k0 = sm.kT[d4 * 4 + 0][jj];
                    float k1 = sm.kT[d4 * 4 + 1][jj];
                    float k2 = sm.kT[d4 * 4 + 2][jj];
                    float k3 = sm.kT[d4 * 4 + 3][jj];
                    #pragma unroll
                    for (int r = 0; r < RPW; ++r) {
                        int row = i0 + r;
                        row = (row < NT) ? row : (NT - 1);
                        float4 qv = *reinterpret_cast<const float4*>(&sm.q[row][d4 * 4]);
                        acc[r] = fmaf(qv.x, k0, acc[r]);
                        acc[r] = fmaf(qv.y, k1, acc[r]);
                        acc[r] = fmaf(qv.z, k2, acc[r]);
                        acc[r] = fmaf(qv.w, k3, acc[r]);
                    }
                }
                if (j < NT) {
                    const float mj = sm.maskf[j];
                    #pragma unroll
                    for (int r = 0; r < RPW; ++r) {
                        if (r < nrows) {
                            const float mi = sm.maskf[i0 + r];
                            sm.S[i0 + r][j] = (mi * mj > 0.5f) ? acc[r] * scale : -FLT_MAX;
                        }
                    }
                }
            }
            __syncwarp();

            // ---------------- softmax per row ----------------
            for (int r = 0; r < nrows; ++r) {
                const int i = i0 + r;
                const bool v3ok = (lane + 96) < NT;
                float s0 = sm.S[i][lane];
                float s1 = sm.S[i][lane + 32];
                float s2 = sm.S[i][lane + 64];
                float s3 = v3ok ? sm.S[i][lane + 96] : -FLT_MAX;
                float m = fmaxf(fmaxf(s0, s1), fmaxf(s2, s3));
                #pragma unroll
                for (int off = 16; off > 0; off >>= 1)
                    m = fmaxf(m, __shfl_xor_sync(0xffffffffu, m, off));
                float p0 = expf(s0 - m);
                float p1 = expf(s1 - m);
                float p2 = expf(s2 - m);
                float p3 = v3ok ? expf(s3 - m) : 0.0f;
                float sum = p0 + p1 + p2 + p3;
                #pragma unroll
                for (int off = 16; off > 0; off >>= 1)
                    sum += __shfl_xor_sync(0xffffffffu, sum, off);
                const float inv = 1.0f / sum;
                sm.S[i][lane]      = p0 * inv;
                sm.S[i][lane + 32] = p1 * inv;
                sm.S[i][lane + 64] = p2 * inv;
                if (v3ok) sm.S[i][lane + 96] = p3 * inv;
            }
            __syncwarp();

            // ---------------- AV + output projection (accumulate into attn) ----------------
            float woA[Ed], woB[Ed];
            #pragma unroll
            for (int e = 0; e < Ed; ++e) {
                const float* wop = Wo + ((size_t)(l * Ed + e)) * (Hh * Dd) + h * Dd + 2 * lane;
                woA[e] = wop[0];
                woB[e] = wop[1];
            }
            for (int r = 0; r < nrows; r += 2) {
                const int  i1   = i0 + r;
                const bool has2 = (r + 1) < nrows;
                const int  i2   = has2 ? (i1 + 1) : i1;
                float o1x = 0.f, o1y = 0.f, o2x = 0.f, o2y = 0.f;
                for (int j = 0; j < NT; j += 4) {
                    float4 p1 = *reinterpret_cast<const float4*>(&sm.S[i1][j]);
                    float4 p2 = *reinterpret_cast<const float4*>(&sm.S[i2][j]);
                    float2 v0 = *reinterpret_cast<const float2*>(&sm.v[j + 0][2 * lane]);
                    float2 v1 = *reinterpret_cast<const float2*>(&sm.v[j + 1][2 * lane]);
                    float2 v2 = *reinterpret_cast<const float2*>(&sm.v[j + 2][2 * lane]);
                    float2 v3 = *reinterpret_cast<const float2*>(&sm.v[j + 3][2 * lane]);
                    o1x = fmaf(p1.x, v0.x, o1x); o1y = fmaf(p1.x, v0.y, o1y);
                    o2x = fmaf(p2.x, v0.x, o2x); o2y = fmaf(p2.x, v0.y, o2y);
                    o1x = fmaf(p1.y, v1.x, o1x); o1y = fmaf(p1.y, v1.y, o1y);
                    o2x = fmaf(p2.y, v1.x, o2x); o2y = fmaf(p2.y, v1.y, o2y);
                    o1x = fmaf(p1.z, v2.x, o1x); o1y = fmaf(p1.z, v2.y, o1y);
                    o2x = fmaf(p2.z, v2.x, o2x); o2y = fmaf(p2.z, v2.y, o2y);
                    o1x = fmaf(p1.w, v3.x, o1x); o1y = fmaf(p1.w, v3.y, o1y);
                    o2x = fmaf(p2.w, v3.x, o2x); o2y = fmaf(p2.w, v3.y, o2y);
                }
                #pragma unroll
                for (int e = 0; e < Ed; ++e) {
                    float part = fmaf(o1x, woA[e], o1y * woB[e]);
                    #pragma unroll
                    for (int off = 16; off > 0; off >>= 1)
                        part += __shfl_xor_sync(0xffffffffu, part, off);
                    if (lane == 0) sm.attn[i1][e] += part;
                }
                if (has2) {
                    #pragma unroll
                    for (int e = 0; e < Ed; ++e) {
                        float part = fmaf(o2x, woA[e], o2y * woB[e]);
                        #pragma unroll
                        for (int off = 16; off > 0; off >>= 1)
                            part += __shfl_xor_sync(0xffffffffu, part, off);
                        if (lane == 0) sm.attn[i2][e] += part;
                    }
                }
            }
            __syncthreads();
        } // heads

        // ---------------- residual + LN1 + FFN + residual + LN2 ----------------
        if (tid < NT) {
            float a[Ed], ln1[Ed], fo[Ed];
            #pragma unroll
            for (int e = 0; e < Ed; ++e) a[e] = sm.attn[tid][e] + sm.feat[tid][e];
            float mu = 0.f;
            #pragma unroll
            for (int e = 0; e < Ed; ++e) mu += a[e];
            mu *= 0.2f;
            float var = 0.f;
            #pragma unroll
            for (int e = 0; e < Ed; ++e) { float dd = a[e] - mu; var = fmaf(dd, dd, var); }
            var *= 0.2f;
            float rinv = rsqrtf(var + 1e-5f);
            #pragma unroll
            for (int e = 0; e < Ed; ++e)
                ln1[e] = (a[e] - mu) * rinv * g1[l * Ed + e] + b1[l * Ed + e];
            #pragma unroll
            for (int e = 0; e < Ed; ++e) {
                float s = bfb[l * Ed + e];
                #pragma unroll
                for (int e2 = 0; e2 < Ed; ++e2)
                    s = fmaf(Wf[((size_t)(l * Ed + e)) * Ed + e2], ln1[e2], s);
                fo[e] = fmaxf(s, 0.0f) + ln1[e];
            }
            float mu2 = 0.f;
            #pragma unroll
            for (int e = 0; e < Ed; ++e) mu2 += fo[e];
            mu2 *= 0.2f;
            float var2 = 0.f;
            #pragma unroll
            for (int e = 0; e < Ed; ++e) { float dd = fo[e] - mu2; var2 = fmaf(dd, dd, var2); }
            var2 *= 0.2f;
            float rinv2 = rsqrtf(var2 + 1e-5f);
            #pragma unroll
            for (int e = 0; e < Ed; ++e)
                sm.feat[tid][e] = (fo[e] - mu2) * rinv2 * g2[l * Ed + e] + b2[l * Ed + e];
        }
        __syncthreads();
    } // layers

    // ---------------- write output ----------------
    for (int idx = tid; idx < NT * Ed; idx += NTHREADS)
        out[(size_t)b * (NT * Ed) + idx] = (&sm.feat[0][0])[idx];
}

extern "C" void kernel_launch(void* const* d_in, const int* in_sizes, int n_in,
                              void* d_out, int out_size)
{
    const float* x   = (const float*)d_in[0];
    const float* Wq  = (const float*)d_in[1];
    const float* Wk  = (const float*)d_in[2];
    const float* Wv  = (const float*)d_in[3];
    const float* Wo  = (const float*)d_in[4];
    const float* Wf  = (const float*)d_in[5];
    const float* bfb = (const float*)d_in[6];
    const float* g1  = (const float*)d_in[7];
    const float* b1  = (const float*)d_in[8];
    const float* g2  = (const float*)d_in[9];
    const float* b2  = (const float*)d_in[10];
    float* out = (float*)d_out;

    cudaFuncSetAttribute(encoder_kernel,
                         cudaFuncAttributeMaxDynamicSharedMemorySize,
                         (int)sizeof(SMem));
    encoder_kernel<<<Bb, NTHREADS, sizeof(SMem)>>>(x, Wq, Wk, Wv, Wo, Wf, bfb,
                                                   g1, b1, g2, b2, out);
}

// round 2
// speedup vs baseline: 1.1465x; 1.1465x over previous
#include <cuda_runtime.h>
#include <math.h>
#include <float.h>

#define Bb      1024
#define NW      300
#define NT      100      // tokens
#define Ed      5        // embed dim
#define Hh      4        // heads
#define Dd      64       // head dim
#define Ll      3        // layers
#define NTHREADS 512
#define NWARP   16
#define RPW     7        // rows per warp (ceil(100/16))

struct SMem {
    float feat[NT][Ed];      // 500 floats
    float attn[NT][Ed];      // 500
    float maskf[NT];         // 100
    float q[NT][Dd];         // 6400  (row stride 256 B, float4-aligned)
    float kT[Dd][NT + 1];    // 6464  (stride 101 -> conflict-free both ways)
    float v[NT][Dd];         // 6400
    float S[NT][NT];         // 10000 (row stride 400 B, float4-aligned)
};                           // ~121.5 KB

__global__ __launch_bounds__(NTHREADS, 1)
void encoder_kernel(const float* __restrict__ x,
                    const float* __restrict__ Wq, const float* __restrict__ Wk,
                    const float* __restrict__ Wv, const float* __restrict__ Wo,
                    const float* __restrict__ Wf, const float* __restrict__ bfb,
                    const float* __restrict__ g1, const float* __restrict__ b1,
                    const float* __restrict__ g2, const float* __restrict__ b2,
                    float* __restrict__ out)
{
    extern __shared__ unsigned char smem_raw[];
    SMem& sm = *reinterpret_cast<SMem*>(smem_raw);

    const int b    = blockIdx.x;
    const int tid  = threadIdx.x;
    const int lane = tid & 31;
    const int w    = tid >> 5;

    // ---------------- embedding + mask ----------------
    if (tid < NT) {
        float k0 = x[b * NW + tid * 3 + 0];
        float k1 = x[b * NW + tid * 3 + 1];
        float k2 = x[b * NW + tid * 3 + 2];
        bool  m  = k2 > 0.0f;
        float sn, cs;
        sincosf((float)tid, &sn, &cs);
        sm.maskf[tid]   = m ? 1.0f : 0.0f;
        sm.feat[tid][0] = m ? k0 : 0.0f;
        sm.feat[tid][1] = m ? k1 : 0.0f;
        sm.feat[tid][2] = m ? k2 : 0.0f;
        sm.feat[tid][3] = m ? sn : 0.0f;
        sm.feat[tid][4] = m ? cs : 0.0f;
    }
    __syncthreads();

    const int i0    = w * RPW;
    const int nrows = (NT - i0) < RPW ? ((NT - i0) > 0 ? (NT - i0) : 0) : RPW;
    const float scale = 0.125f;  // 1/sqrt(64)

    for (int l = 0; l < Ll; ++l) {
        // zero attention-output accumulator
        for (int idx = tid; idx < NT * Ed; idx += NTHREADS)
            (&sm.attn[0][0])[idx] = 0.0f;
        __syncthreads();

        for (int h = 0; h < Hh; ++h) {
            // ---------------- QKV projection ----------------
            {
                const int d     = tid & 63;
                const int part8 = tid >> 6;           // 0..7
                const float* wqp = Wq + ((size_t)((l * Hh + h) * Dd + d)) * Ed;
                const float* wkp = Wk + ((size_t)((l * Hh + h) * Dd + d)) * Ed;
                const float* wvp = Wv + ((size_t)((l * Hh + h) * Dd + d)) * Ed;
                float wq[Ed], wk[Ed], wv[Ed];
                #pragma unroll
                for (int e = 0; e < Ed; ++e) { wq[e] = wqp[e]; wk[e] = wkp[e]; wv[e] = wvp[e]; }
                for (int r = part8; r < NT; r += 8) {
                    float f[Ed];
                    #pragma unroll
                    for (int e = 0; e < Ed; ++e) f[e] = sm.feat[r][e];
                    float qv = 0.f, kv = 0.f, vv = 0.f;
                    #pragma unroll
                    for (int e = 0; e < Ed; ++e) {
                        qv = fmaf(wq[e], f[e], qv);
                        kv = fmaf(wk[e], f[e], kv);
                        vv = fmaf(wv[e], f[e], vv);
                    }
                    sm.q[r][d]  = qv;
                    sm.kT[d][r] = kv;
                    sm.v[r][d]  = vv;
                }
            }
            __syncthreads();

            // ---------------- scores: S = (Q Kt) * scale, masked ----------------
            for (int jt = 0; jt < 4; ++jt) {
                const int j  = lane + jt * 32;
                const int jj = (j < NT) ? j : 0;
                float acc[RPW];
                #pragma unroll
                for (int r = 0; r < RPW; ++r) acc[r] = 0.0f;
                #pragma unroll 4
                for (int d4 = 0; d4 < Dd / 4; ++d4) {
                    float k0 = sm.kT[d4 * 4 + 0][jj];
                    float k1 = sm.kT[d4 * 4 + 1][jj];
                    float k2 = sm.kT[d4 * 4 + 2][jj];
                    float k3 = sm.kT[d4 * 4 + 3][jj];
                    #pragma unroll
                    for (int r = 0; r < RPW; ++r) {
                        int row = i0 + r;
                        row = (row < NT) ? row : (NT - 1);
                        float4 qv = *reinterpret_cast<const float4*>(&sm.q[row][d4 * 4]);
                        acc[r] = fmaf(qv.x, k0, acc[r]);
                        acc[r] = fmaf(qv.y, k1, acc[r]);
                        acc[r] = fmaf(qv.z, k2, acc[r]);
                        acc[r] = fmaf(qv.w, k3, acc[r]);
                    }
                }
                if (j < NT) {
                    const float mj = sm.maskf[j];
                    #pragma unroll
                    for (int r = 0; r < RPW; ++r) {
                        if (r < nrows) {
                            const float mi = sm.maskf[i0 + r];
                            sm.S[i0 + r][j] = (mi * mj > 0.5f) ? acc[r] * scale : -FLT_MAX;
                        }
                    }
                }
            }
            __syncwarp();

            // ---------------- softmax per row ----------------
            for (int r = 0; r < nrows; ++r) {
                const int i = i0 + r;
                const bool v3ok = (lane + 96) < NT;
                float s0 = sm.S[i][lane];
                float s1 = sm.S[i][lane + 32];
                float s2 = sm.S[i][lane + 64];
                float s3 = v3ok ? sm.S[i][lane + 96] : -FLT_MAX;
                float m = fmaxf(fmaxf(s0, s1), fmaxf(s2, s3));
                #pragma unroll
                for (int off = 16; off > 0; off >>= 1)
                    m = fmaxf(m, __shfl_xor_sync(0xffffffffu, m, off));
                float p0 = __expf(s0 - m);
                float p1 = __expf(s1 - m);
                float p2 = __expf(s2 - m);
                float p3 = v3ok ? __expf(s3 - m) : 0.0f;
                float sum = p0 + p1 + p2 + p3;
                #pragma unroll
                for (int off = 16; off > 0; off >>= 1)
                    sum += __shfl_xor_sync(0xffffffffu, sum, off);
                const float inv = 1.0f / sum;
                sm.S[i][lane]      = p0 * inv;
                sm.S[i][lane + 32] = p1 * inv;
                sm.S[i][lane + 64] = p2 * inv;
                if (v3ok) sm.S[i][lane + 96] = p3 * inv;
            }
            __syncwarp();

            // ---------------- AV (7-row register block) + output projection ----------------
            {
                // accumulators for all RPW rows, 2 d-columns per lane
                float ox[RPW], oy[RPW];
                #pragma unroll
                for (int r = 0; r < RPW; ++r) { ox[r] = 0.f; oy[r] = 0.f; }

                for (int j = 0; j < NT; j += 4) {
                    float2 v0 = *reinterpret_cast<const float2*>(&sm.v[j + 0][2 * lane]);
                    float2 v1 = *reinterpret_cast<const float2*>(&sm.v[j + 1][2 * lane]);
                    float2 v2 = *reinterpret_cast<const float2*>(&sm.v[j + 2][2 * lane]);
                    float2 v3 = *reinterpret_cast<const float2*>(&sm.v[j + 3][2 * lane]);
                    #pragma unroll
                    for (int r = 0; r < RPW; ++r) {
                        int row = i0 + r;
                        row = (row < NT) ? row : (NT - 1);
                        float4 p = *reinterpret_cast<const float4*>(&sm.S[row][j]);
                        ox[r] = fmaf(p.x, v0.x, ox[r]); oy[r] = fmaf(p.x, v0.y, oy[r]);
                        ox[r] = fmaf(p.y, v1.x, ox[r]); oy[r] = fmaf(p.y, v1.y, oy[r]);
                        ox[r] = fmaf(p.z, v2.x, ox[r]); oy[r] = fmaf(p.z, v2.y, oy[r]);
                        ox[r] = fmaf(p.w, v3.x, ox[r]); oy[r] = fmaf(p.w, v3.y, oy[r]);
                    }
                }

                float woA[Ed], woB[Ed];
                #pragma unroll
                for (int e = 0; e < Ed; ++e) {
                    const float* wop = Wo + ((size_t)(l * Ed + e)) * (Hh * Dd) + h * Dd + 2 * lane;
                    woA[e] = wop[0];
                    woB[e] = wop[1];
                }
                for (int r = 0; r < nrows; ++r) {
                    #pragma unroll
                    for (int e = 0; e < Ed; ++e) {
                        float part = fmaf(ox[r], woA[e], oy[r] * woB[e]);
                        #pragma unroll
                        for (int off = 16; off > 0; off >>= 1)
                            part += __shfl_xor_sync(0xffffffffu, part, off);
                        if (lane == 0) sm.attn[i0 + r][e] += part;
                    }
                }
            }
            __syncthreads();
        } // heads

        // ---------------- residual + LN1 + FFN + residual + LN2 ----------------
        if (tid < NT) {
            float a[Ed], ln1[Ed], fo[Ed];
            #pragma unroll
            for (int e = 0; e < Ed; ++e) a[e] = sm.attn[tid][e] + sm.feat[tid][e];
            float mu = 0.f;
            #pragma unroll
            for (int e = 0; e < Ed; ++e) mu += a[e];
            mu *= 0.2f;
            float var = 0.f;
            #pragma unroll
            for (int e = 0; e < Ed; ++e) { float dd = a[e] - mu; var = fmaf(dd, dd, var); }
            var *= 0.2f;
            float rinv = rsqrtf(var + 1e-5f);
            #pragma unroll
            for (int e = 0; e < Ed; ++e)
                ln1[e] = (a[e] - mu) * rinv * g1[l * Ed + e] + b1[l * Ed + e];
            #pragma unroll
            for (int e = 0; e < Ed; ++e) {
                float s = bfb[l * Ed + e];
                #pragma unroll
                for (int e2 = 0; e2 < Ed; ++e2)
                    s = fmaf(Wf[((size_t)(l * Ed + e)) * Ed + e2], ln1[e2], s);
                fo[e] = fmaxf(s, 0.0f) + ln1[e];
            }
            float mu2 = 0.f;
            #pragma unroll
            for (int e = 0; e < Ed; ++e) mu2 += fo[e];
            mu2 *= 0.2f;
            float var2 = 0.f;
            #pragma unroll
            for (int e = 0; e < Ed; ++e) { float dd = fo[e] - mu2; var2 = fmaf(dd, dd, var2); }
            var2 *= 0.2f;
            float rinv2 = rsqrtf(var2 + 1e-5f);
            #pragma unroll
            for (int e = 0; e < Ed; ++e)
                sm.feat[tid][e] = (fo[e] - mu2) * rinv2 * g2[l * Ed + e] + b2[l * Ed + e];
        }
        __syncthreads();
    } // layers

    // ---------------- write output ----------------
    for (int idx = tid; idx < NT * Ed; idx += NTHREADS)
        out[(size_t)b * (NT * Ed) + idx] = (&sm.feat[0][0])[idx];
}

extern "C" void kernel_launch(void* const* d_in, const int* in_sizes, int n_in,
                              void* d_out, int out_size)
{
    const float* x   = (const float*)d_in[0];
    const float* Wq  = (const float*)d_in[1];
    const float* Wk  = (const float*)d_in[2];
    const float* Wv  = (const float*)d_in[3];
    const float* Wo  = (const float*)d_in[4];
    const float* Wf  = (const float*)d_in[5];
    const float* bfb = (const float*)d_in[6];
    const float* g1  = (const float*)d_in[7];
    const float* b1  = (const float*)d_in[8];
    const float* g2  = (const float*)d_in[9];
    const float* b2  = (const float*)d_in[10];
    float* out = (float*)d_out;

    cudaFuncSetAttribute(encoder_kernel,
                         cudaFuncAttributeMaxDynamicSharedMemorySize,
                         (int)sizeof(SMem));
    encoder_kernel<<<Bb, NTHREADS, sizeof(SMem)>>>(x, Wq, Wk, Wv, Wo, Wf, bfb,
                                                   g1, b1, g2, b2, out);
}

// round 3
// speedup vs baseline: 1.5661x; 1.3661x over previous
#include <cuda_runtime.h>
#include <math.h>
#include <float.h>

#define Bb      1024
#define NW      300
#define NT      100      // tokens
#define Ed      5        // embed dim
#define Hh      4        // heads
#define Dd      64       // head dim
#define Ll      3        // layers
#define NTHREADS 512
#define NWARP   16
#define RPW     7        // real rows per warp (warp w owns tokens 7w..7w+6)
#define SLOTS   8        // padded row slots per warp (for float2-aligned pairs)
#define QSTRIDE (NWARP * SLOTS + 2)   // 130 floats per qT row (even -> 8B aligned pairs)
#define KSTRIDE (NT + 1)              // 101

struct SMem {
    float feat[NT][Ed];          // 500
    float attn[NT][Ed];          // 500
    float maskf[NT];             // 100   (offset 1100 floats, 8B aligned)
    float qT[Dd][QSTRIDE];       // 8320  (slot-major transposed q)
    float kT[Dd][KSTRIDE];       // 6464
    float v[NT][Dd];             // 6400
    float S[NWARP * SLOTS][NT];  // 12800 (slot rows; stride 100 floats, 16B ok)
};                               // 35,084 floats = 140,336 B

// ---- packed f32x2 helpers (FFMA2 path, PTX-only) ----
__device__ __forceinline__ unsigned long long pk2(float lo, float hi) {
    unsigned long long r;
    asm("mov.b64 %0, {%1, %2};" : "=l"(r) : "f"(lo), "f"(hi));
    return r;
}
__device__ __forceinline__ unsigned long long splat2(float v) {
    unsigned long long r;
    asm("mov.b64 %0, {%1, %1};" : "=l"(r) : "f"(v));
    return r;
}
__device__ __forceinline__ void unpk2(unsigned long long p, float& lo, float& hi) {
    asm("mov.b64 {%0, %1}, %2;" : "=f"(lo), "=f"(hi) : "l"(p));
}
__device__ __forceinline__ unsigned long long ffma2(unsigned long long a,
                                                    unsigned long long b,
                                                    unsigned long long c) {
    unsigned long long d;
    asm("fma.rn.f32x2 %0, %1, %2, %3;" : "=l"(d) : "l"(a), "l"(b), "l"(c));
    return d;
}

__global__ __launch_bounds__(NTHREADS, 1)
void encoder_kernel(const float* __restrict__ x,
                    const float* __restrict__ Wq, const float* __restrict__ Wk,
                    const float* __restrict__ Wv, const float* __restrict__ Wo,
                    const float* __restrict__ Wf, const float* __restrict__ bfb,
                    const float* __restrict__ g1, const float* __restrict__ b1,
                    const float* __restrict__ g2, const float* __restrict__ b2,
                    float* __restrict__ out)
{
    extern __shared__ unsigned char smem_raw[];
    SMem& sm = *reinterpret_cast<SMem*>(smem_raw);

    const int b    = blockIdx.x;
    const int tid  = threadIdx.x;
    const int lane = tid & 31;
    const int w    = tid >> 5;

    // ---------------- embedding + mask ----------------
    if (tid < NT) {
        float k0 = x[b * NW + tid * 3 + 0];
        float k1 = x[b * NW + tid * 3 + 1];
        float k2 = x[b * NW + tid * 3 + 2];
        bool  m  = k2 > 0.0f;
        float sn, cs;
        sincosf((float)tid, &sn, &cs);
        sm.maskf[tid]   = m ? 1.0f : 0.0f;
        sm.feat[tid][0] = m ? k0 : 0.0f;
        sm.feat[tid][1] = m ? k1 : 0.0f;
        sm.feat[tid][2] = m ? k2 : 0.0f;
        sm.feat[tid][3] = m ? sn : 0.0f;
        sm.feat[tid][4] = m ? cs : 0.0f;
    }
    __syncthreads();

    const int t0    = w * RPW;                 // first token of this warp
    const int s0    = w * SLOTS;               // first S/qT slot of this warp
    int nr          = NT - t0;
    const int nrows = nr < 0 ? 0 : (nr > RPW ? RPW : nr);
    const float scale = 0.125f;                // 1/sqrt(64)

    for (int l = 0; l < Ll; ++l) {
        for (int idx = tid; idx < NT * Ed; idx += NTHREADS)
            (&sm.attn[0][0])[idx] = 0.0f;
        __syncthreads();

        for (int h = 0; h < Hh; ++h) {
            // ---------------- QKV projection ----------------
            {
                const int d     = tid & 63;
                const int part8 = tid >> 6;           // 0..7
                const float* wqp = Wq + ((size_t)((l * Hh + h) * Dd + d)) * Ed;
                const float* wkp = Wk + ((size_t)((l * Hh + h) * Dd + d)) * Ed;
                const float* wvp = Wv + ((size_t)((l * Hh + h) * Dd + d)) * Ed;
                float wq[Ed], wk[Ed], wv[Ed];
                #pragma unroll
                for (int e = 0; e < Ed; ++e) { wq[e] = wqp[e]; wk[e] = wkp[e]; wv[e] = wvp[e]; }
                for (int r = part8; r < NT; r += 8) {
                    float f[Ed];
                    #pragma unroll
                    for (int e = 0; e < Ed; ++e) f[e] = sm.feat[r][e];
                    float qv = 0.f, kv = 0.f, vv = 0.f;
                    #pragma unroll
                    for (int e = 0; e < Ed; ++e) {
                        qv = fmaf(wq[e], f[e], qv);
                        kv = fmaf(wk[e], f[e], kv);
                        vv = fmaf(wv[e], f[e], vv);
                    }
                    const int slot = (r / RPW) * SLOTS + (r % RPW);
                    sm.qT[d][slot] = qv;
                    sm.kT[d][r]    = kv;
                    sm.v[r][d]     = vv;
                }
            }
            __syncthreads();

            if (nrows > 0) {
                // ---------------- scores: S = (Q Kt)*scale, masked (f32x2) ---------
                int jj[4];
                #pragma unroll
                for (int jt = 0; jt < 4; ++jt) {
                    int j = lane + jt * 32;
                    jj[jt] = (j < NT) ? j : 0;
                }
                unsigned long long acc[4][4];
                #pragma unroll
                for (int jt = 0; jt < 4; ++jt)
                    #pragma unroll
                    for (int p = 0; p < 4; ++p) acc[jt][p] = 0ULL;

                #pragma unroll 2
                for (int d = 0; d < Dd; ++d) {
                    unsigned long long qp[4];
                    #pragma unroll
                    for (int p = 0; p < 4; ++p) {
                        float2 qv = *reinterpret_cast<const float2*>(&sm.qT[d][s0 + 2 * p]);
                        qp[p] = pk2(qv.x, qv.y);
                    }
                    #pragma unroll
                    for (int jt = 0; jt < 4; ++jt) {
                        unsigned long long ks = splat2(sm.kT[d][jj[jt]]);
                        #pragma unroll
                        for (int p = 0; p < 4; ++p)
                            acc[jt][p] = ffma2(qp[p], ks, acc[jt][p]);
                    }
                }

                #pragma unroll
                for (int jt = 0; jt < 4; ++jt) {
                    const int j = lane + jt * 32;
                    if (j < NT) {
                        const float mj = sm.maskf[j];
                        #pragma unroll
                        for (int p = 0; p < 4; ++p) {
                            float a0, a1;
                            unpk2(acc[jt][p], a0, a1);
                            const int r0 = 2 * p, r1 = 2 * p + 1;
                            if (r0 < nrows) {
                                const float mi = sm.maskf[t0 + r0];
                                sm.S[s0 + r0][j] = (mi * mj > 0.5f) ? a0 * scale : -FLT_MAX;
                            }
                            if (r1 < nrows) {
                                const float mi = sm.maskf[t0 + r1];
                                sm.S[s0 + r1][j] = (mi * mj > 0.5f) ? a1 * scale : -FLT_MAX;
                            }
                        }
                    }
                }
                __syncwarp();

                // ---------------- softmax per row ----------------
                for (int r = 0; r < nrows; ++r) {
                    const int si = s0 + r;
                    const bool v3ok = (lane + 96) < NT;
                    float sa = sm.S[si][lane];
                    float sb = sm.S[si][lane + 32];
                    float sc = sm.S[si][lane + 64];
                    float sd = v3ok ? sm.S[si][lane + 96] : -FLT_MAX;
                    float m = fmaxf(fmaxf(sa, sb), fmaxf(sc, sd));
                    #pragma unroll
                    for (int off = 16; off > 0; off >>= 1)
                        m = fmaxf(m, __shfl_xor_sync(0xffffffffu, m, off));
                    float p0 = __expf(sa - m);
                    float p1 = __expf(sb - m);
                    float p2 = __expf(sc - m);
                    float p3 = v3ok ? __expf(sd - m) : 0.0f;
                    float sum = p0 + p1 + p2 + p3;
                    #pragma unroll
                    for (int off = 16; off > 0; off >>= 1)
                        sum += __shfl_xor_sync(0xffffffffu, sum, off);
                    const float inv = 1.0f / sum;
                    sm.S[si][lane]      = p0 * inv;
                    sm.S[si][lane + 32] = p1 * inv;
                    sm.S[si][lane + 64] = p2 * inv;
                    if (v3ok) sm.S[si][lane + 96] = p3 * inv;
                }
                __syncwarp();

                // ---------------- AV (f32x2, splat-P) + output projection -------
                unsigned long long o[RPW];
                #pragma unroll
                for (int r = 0; r < RPW; ++r) o[r] = 0ULL;

                for (int j = 0; j < NT; j += 4) {
                    float2 va = *reinterpret_cast<const float2*>(&sm.v[j + 0][2 * lane]);
                    float2 vb = *reinterpret_cast<const float2*>(&sm.v[j + 1][2 * lane]);
                    float2 vc = *reinterpret_cast<const float2*>(&sm.v[j + 2][2 * lane]);
                    float2 vd = *reinterpret_cast<const float2*>(&sm.v[j + 3][2 * lane]);
                    unsigned long long v0 = pk2(va.x, va.y);
                    unsigned long long v1 = pk2(vb.x, vb.y);
                    unsigned long long v2 = pk2(vc.x, vc.y);
                    unsigned long long v3 = pk2(vd.x, vd.y);
                    #pragma unroll
                    for (int r = 0; r < RPW; ++r) {
                        float4 p = *reinterpret_cast<const float4*>(&sm.S[s0 + r][j]);
                        o[r] = ffma2(splat2(p.x), v0, o[r]);
                        o[r] = ffma2(splat2(p.y), v1, o[r]);
                        o[r] = ffma2(splat2(p.z), v2, o[r]);
                        o[r] = ffma2(splat2(p.w), v3, o[r]);
                    }
                }

                float woA[Ed], woB[Ed];
                #pragma unroll
                for (int e = 0; e < Ed; ++e) {
                    const float* wop = Wo + ((size_t)(l * Ed + e)) * (Hh * Dd) + h * Dd + 2 * lane;
                    woA[e] = wop[0];
                    woB[e] = wop[1];
                }
                for (int r = 0; r < nrows; ++r) {
                    float ox, oy;
                    unpk2(o[r], ox, oy);
                    #pragma unroll
                    for (int e = 0; e < Ed; ++e) {
                        float part = fmaf(ox, woA[e], oy * woB[e]);
                        #pragma unroll
                        for (int off = 16; off > 0; off >>= 1)
                            part += __shfl_xor_sync(0xffffffffu, part, off);
                        if (lane == 0) sm.attn[t0 + r][e] += part;
                    }
                }
            }
            __syncthreads();
        } // heads

        // ---------------- residual + LN1 + FFN + residual + LN2 ----------------
        if (tid < NT) {
            float a[Ed], ln1[Ed], fo[Ed];
            #pragma unroll
            for (int e = 0; e < Ed; ++e) a[e] = sm.attn[tid][e] + sm.feat[tid][e];
            float mu = 0.f;
            #pragma unroll
            for (int e = 0; e < Ed; ++e) mu += a[e];
            mu *= 0.2f;
            float var = 0.f;
            #pragma unroll
            for (int e = 0; e < Ed; ++e) { float dd = a[e] - mu; var = fmaf(dd, dd, var); }
            var *= 0.2f;
            float rinv = rsqrtf(var + 1e-5f);
            #pragma unroll
            for (int e = 0; e < Ed; ++e)
                ln1[e] = (a[e] - mu) * rinv * g1[l * Ed + e] + b1[l * Ed + e];
            #pragma unroll
            for (int e = 0; e < Ed; ++e) {
                float s = bfb[l * Ed + e];
                #pragma unroll
                for (int e2 = 0; e2 < Ed; ++e2)
                    s = fmaf(Wf[((size_t)(l * Ed + e)) * Ed + e2], ln1[e2], s);
                fo[e] = fmaxf(s, 0.0f) + ln1[e];
            }
            float mu2 = 0.f;
            #pragma unroll
            for (int e = 0; e < Ed; ++e) mu2 += fo[e];
            mu2 *= 0.2f;
            float var2 = 0.f;
            #pragma unroll
            for (int e = 0; e < Ed; ++e) { float dd = fo[e] - mu2; var2 = fmaf(dd, dd, var2); }
            var2 *= 0.2f;
            float rinv2 = rsqrtf(var2 + 1e-5f);
            #pragma unroll
            for (int e = 0; e < Ed; ++e)
                sm.feat[tid][e] = (fo[e] - mu2) * rinv2 * g2[l * Ed + e] + b2[l * Ed + e];
        }
        __syncthreads();
    } // layers

    // ---------------- write output ----------------
    for (int idx = tid; idx < NT * Ed; idx += NTHREADS)
        out[(size_t)b * (NT * Ed) + idx] = (&sm.feat[0][0])[idx];
}

extern "C" void kernel_launch(void* const* d_in, const int* in_sizes, int n_in,
                              void* d_out, int out_size)
{
    const float* x   = (const float*)d_in[0];
    const float* Wq  = (const float*)d_in[1];
    const float* Wk  = (const float*)d_in[2];
    const float* Wv  = (const float*)d_in[3];
    const float* Wo  = (const float*)d_in[4];
    const float* Wf  = (const float*)d_in[5];
    const float* bfb = (const float*)d_in[6];
    const float* g1  = (const float*)d_in[7];
    const float* b1  = (const float*)d_in[8];
    const float* g2  = (const float*)d_in[9];
    const float* b2  = (const float*)d_in[10];
    float* out = (float*)d_out;

    cudaFuncSetAttribute(encoder_kernel,
                         cudaFuncAttributeMaxDynamicSharedMemorySize,
                         (int)sizeof(SMem));
    encoder_kernel<<<Bb, NTHREADS, sizeof(SMem)>>>(x, Wq, Wk, Wv, Wo, Wf, bfb,
                                                   g1, b1, g2, b2, out);
}

// round 5
// speedup vs baseline: 1.6227x; 1.0361x over previous
#include <cuda_runtime.h>
#include <math.h>
#include <float.h>

#define Bb      1024
#define NW      300
#define NT      100      // tokens
#define Ed      5        // embed dim
#define Hh      4        // heads
#define Dd      64       // head dim
#define Ll      3        // layers
#define NTHREADS 512
#define NWARP   16
#define RPW     7        // real rows per warp (warp w owns tokens 7w..7w+6)
#define SLOTS   8        // padded row slots per warp
#define QSTRIDE (NWARP * SLOTS + 4)   // 132 floats -> 528 B rows, 16B aligned
#define KSTRIDE (NT + 1)              // 101 (odd -> conflict-free lane reads)

struct SMem {
    float feat[NT][Ed];          // 500
    float attn[NT][Ed];          // 500
    float maskf[NT];             // 100
    float qT[Dd][QSTRIDE];       // 8448  (slot-major transposed q, scale folded in)
    float kT[Dd][KSTRIDE];       // 6464
    float v[NT][Dd];             // 6400
    float S[NWARP * SLOTS][NT];  // 12800 (normalized attention probs P)
};                               // 35,212 floats = 140,848 B

// ---- packed f32x2 helpers (FFMA2 path, PTX-only) ----
__device__ __forceinline__ unsigned long long pk2(float lo, float hi) {
    unsigned long long r;
    asm("mov.b64 %0, {%1, %2};" : "=l"(r) : "f"(lo), "f"(hi));
    return r;
}
__device__ __forceinline__ unsigned long long splat2(float v) {
    unsigned long long r;
    asm("mov.b64 %0, {%1, %1};" : "=l"(r) : "f"(v));
    return r;
}
__device__ __forceinline__ void unpk2(unsigned long long p, float& lo, float& hi) {
    asm("mov.b64 {%0, %1}, %2;" : "=f"(lo), "=f"(hi) : "l"(p));
}
__device__ __forceinline__ unsigned long long ffma2(unsigned long long a,
                                                    unsigned long long b,
                                                    unsigned long long c) {
    unsigned long long d;
    asm("fma.rn.f32x2 %0, %1, %2, %3;" : "=l"(d) : "l"(a), "l"(b), "l"(c));
    return d;
}

__global__ __launch_bounds__(NTHREADS, 1)
void encoder_kernel(const float* __restrict__ x,
                    const float* __restrict__ Wq, const float* __restrict__ Wk,
                    const float* __restrict__ Wv, const float* __restrict__ Wo,
                    const float* __restrict__ Wf, const float* __restrict__ bfb,
                    const float* __restrict__ g1, const float* __restrict__ b1,
                    const float* __restrict__ g2, const float* __restrict__ b2,
                    float* __restrict__ out)
{
    extern __shared__ unsigned char smem_raw[];
    SMem& sm = *reinterpret_cast<SMem*>(smem_raw);

    const int b    = blockIdx.x;
    const int tid  = threadIdx.x;
    const int lane = tid & 31;
    const int w    = tid >> 5;

    // ---------------- embedding + mask ----------------
    if (tid < NT) {
        float k0 = x[b * NW + tid * 3 + 0];
        float k1 = x[b * NW + tid * 3 + 1];
        float k2 = x[b * NW + tid * 3 + 2];
        bool  m  = k2 > 0.0f;
        float sn, cs;
        sincosf((float)tid, &sn, &cs);
        sm.maskf[tid]   = m ? 1.0f : 0.0f;
        sm.feat[tid][0] = m ? k0 : 0.0f;
        sm.feat[tid][1] = m ? k1 : 0.0f;
        sm.feat[tid][2] = m ? k2 : 0.0f;
        sm.feat[tid][3] = m ? sn : 0.0f;
        sm.feat[tid][4] = m ? cs : 0.0f;
    }
    __syncthreads();

    const int t0    = w * RPW;                 // first token of this warp
    const int s0    = w * SLOTS;               // first P/qT slot of this warp
    int nr          = NT - t0;
    const int nrows = nr < 0 ? 0 : (nr > RPW ? RPW : nr);

    for (int l = 0; l < Ll; ++l) {
        for (int idx = tid; idx < NT * Ed; idx += NTHREADS)
            (&sm.attn[0][0])[idx] = 0.0f;
        __syncthreads();

        for (int h = 0; h < Hh; ++h) {
            // ---------------- QKV projection (scale folded into q) ----------
            {
                const int d     = tid & 63;
                const int part8 = tid >> 6;           // 0..7
                const float* wqp = Wq + ((size_t)((l * Hh + h) * Dd + d)) * Ed;
                const float* wkp = Wk + ((size_t)((l * Hh + h) * Dd + d)) * Ed;
                const float* wvp = Wv + ((size_t)((l * Hh + h) * Dd + d)) * Ed;
                float wq[Ed], wk[Ed], wv[Ed];
                #pragma unroll
                for (int e = 0; e < Ed; ++e) {
                    wq[e] = wqp[e] * 0.125f;   // 1/sqrt(64) folded
                    wk[e] = wkp[e];
                    wv[e] = wvp[e];
                }
                for (int r = part8; r < NT; r += 8) {
                    float f[Ed];
                    #pragma unroll
                    for (int e = 0; e < Ed; ++e) f[e] = sm.feat[r][e];
                    float qv = 0.f, kv = 0.f, vv = 0.f;
                    #pragma unroll
                    for (int e = 0; e < Ed; ++e) {
                        qv = fmaf(wq[e], f[e], qv);
                        kv = fmaf(wk[e], f[e], kv);
                        vv = fmaf(wv[e], f[e], vv);
                    }
                    const int slot = (r / RPW) * SLOTS + (r % RPW);
                    sm.qT[d][slot] = qv;
                    sm.kT[d][r]    = kv;
                    sm.v[r][d]     = vv;
                }
            }
            __syncthreads();

            if (nrows > 0) {
                // ------------- scores: acc[jt][p] = packed row-pair dot ------
                int jj[4];
                #pragma unroll
                for (int jt = 0; jt < 4; ++jt) {
                    int j = lane + jt * 32;
                    jj[jt] = (j < NT) ? j : 0;
                }
                unsigned long long acc[4][4];
                #pragma unroll
                for (int jt = 0; jt < 4; ++jt)
                    #pragma unroll
                    for (int p = 0; p < 4; ++p) acc[jt][p] = 0ULL;

                #pragma unroll 2
                for (int d = 0; d < Dd; ++d) {
                    float4 qA = *reinterpret_cast<const float4*>(&sm.qT[d][s0]);
                    float4 qB = *reinterpret_cast<const float4*>(&sm.qT[d][s0 + 4]);
                    unsigned long long qp0 = pk2(qA.x, qA.y);
                    unsigned long long qp1 = pk2(qA.z, qA.w);
                    unsigned long long qp2 = pk2(qB.x, qB.y);
                    unsigned long long qp3 = pk2(qB.z, qB.w);
                    #pragma unroll
                    for (int jt = 0; jt < 4; ++jt) {
                        unsigned long long ks = splat2(sm.kT[d][jj[jt]]);
                        acc[jt][0] = ffma2(qp0, ks, acc[jt][0]);
                        acc[jt][1] = ffma2(qp1, ks, acc[jt][1]);
                        acc[jt][2] = ffma2(qp2, ks, acc[jt][2]);
                        acc[jt][3] = ffma2(qp3, ks, acc[jt][3]);
                    }
                }

                // ------------- fused mask + softmax on registers -------------
                const bool v3ok = (lane + 96) < NT;
                float mj0 = sm.maskf[jj[0]];
                float mj1 = sm.maskf[jj[1]];
                float mj2 = sm.maskf[jj[2]];
                float mj3 = sm.maskf[jj[3]];
                #pragma unroll
                for (int r = 0; r < RPW; ++r) {
                    if (r < nrows) {
                        const float mi = sm.maskf[t0 + r];
                        float lo, hi, s0v, s1v, s2v, s3v;
                        unpk2(acc[0][r >> 1], lo, hi);
                        s0v = (mi * mj0 > 0.5f) ? ((r & 1) ? hi : lo) : -FLT_MAX;
                        unpk2(acc[1][r >> 1], lo, hi);
                        s1v = (mi * mj1 > 0.5f) ? ((r & 1) ? hi : lo) : -FLT_MAX;
                        unpk2(acc[2][r >> 1], lo, hi);
                        s2v = (mi * mj2 > 0.5f) ? ((r & 1) ? hi : lo) : -FLT_MAX;
                        unpk2(acc[3][r >> 1], lo, hi);
                        s3v = (v3ok && (mi * mj3 > 0.5f)) ? ((r & 1) ? hi : lo) : -FLT_MAX;

                        float m = fmaxf(fmaxf(s0v, s1v), fmaxf(s2v, s3v));
                        #pragma unroll
                        for (int off = 16; off > 0; off >>= 1)
                            m = fmaxf(m, __shfl_xor_sync(0xffffffffu, m, off));
                        float p0 = __expf(s0v - m);
                        float p1 = __expf(s1v - m);
                        float p2 = __expf(s2v - m);
                        float p3 = v3ok ? __expf(s3v - m) : 0.0f;
                        float sum = p0 + p1 + p2 + p3;
                        #pragma unroll
                        for (int off = 16; off > 0; off >>= 1)
                            sum += __shfl_xor_sync(0xffffffffu, sum, off);
                        const float inv = 1.0f / sum;
                        sm.S[s0 + r][lane]      = p0 * inv;
                        sm.S[s0 + r][lane + 32] = p1 * inv;
                        sm.S[s0 + r][lane + 64] = p2 * inv;
                        if (v3ok) sm.S[s0 + r][lane + 96] = p3 * inv;
                    }
                }
                __syncwarp();

                // ------------- AV (f32x2, splat-P) + output projection -------
                unsigned long long o[RPW];
                #pragma unroll
                for (int r = 0; r < RPW; ++r) o[r] = 0ULL;

                for (int j = 0; j < NT; j += 4) {
                    float2 va = *reinterpret_cast<const float2*>(&sm.v[j + 0][2 * lane]);
                    float2 vb = *reinterpret_cast<const float2*>(&sm.v[j + 1][2 * lane]);
                    float2 vc = *reinterpret_cast<const float2*>(&sm.v[j + 2][2 * lane]);
                    float2 vd = *reinterpret_cast<const float2*>(&sm.v[j + 3][2 * lane]);
                    unsigned long long v0 = pk2(va.x, va.y);
                    unsigned long long v1 = pk2(vb.x, vb.y);
                    unsigned long long v2 = pk2(vc.x, vc.y);
                    unsigned long long v3 = pk2(vd.x, vd.y);
                    #pragma unroll
                    for (int r = 0; r < RPW; ++r) {
                        float4 p = *reinterpret_cast<const float4*>(&sm.S[s0 + r][j]);
                        o[r] = ffma2(splat2(p.x), v0, o[r]);
                        o[r] = ffma2(splat2(p.y), v1, o[r]);
                        o[r] = ffma2(splat2(p.z), v2, o[r]);
                        o[r] = ffma2(splat2(p.w), v3, o[r]);
                    }
                }

                float woA[Ed], woB[Ed];
                #pragma unroll
                for (int e = 0; e < Ed; ++e) {
                    const float* wop = Wo + ((size_t)(l * Ed + e)) * (Hh * Dd) + h * Dd + 2 * lane;
                    woA[e] = wop[0];
                    woB[e] = wop[1];
                }
                for (int r = 0; r < nrows; ++r) {
                    float ox, oy;
                    unpk2(o[r], ox, oy);
                    #pragma unroll
                    for (int e = 0; e < Ed; ++e) {
                        float part = fmaf(ox, woA[e], oy * woB[e]);
                        #pragma unroll
                        for (int off = 16; off > 0; off >>= 1)
                            part += __shfl_xor_sync(0xffffffffu, part, off);
                        if (lane == 0) sm.attn[t0 + r][e] += part;
                    }
                }
            }
            __syncthreads();
        } // heads

        // ---------------- residual + LN1 + FFN + residual + LN2 ----------------
        if (tid < NT) {
            float a[Ed], ln1[Ed], fo[Ed];
            #pragma unroll
            for (int e = 0; e < Ed; ++e) a[e] = sm.attn[tid][e] + sm.feat[tid][e];
            float mu = 0.f;
            #pragma unroll
            for (int e = 0; e < Ed; ++e) mu += a[e];
            mu *= 0.2f;
            float var = 0.f;
            #pragma unroll
            for (int e = 0; e < Ed; ++e) { float dd = a[e] - mu; var = fmaf(dd, dd, var); }
            var *= 0.2f;
            float rinv = rsqrtf(var + 1e-5f);
            #pragma unroll
            for (int e = 0; e < Ed; ++e)
                ln1[e] = (a[e] - mu) * rinv * g1[l * Ed + e] + b1[l * Ed + e];
            #pragma unroll
            for (int e = 0; e < Ed; ++e) {
                float s = bfb[l * Ed + e];
                #pragma unroll
                for (int e2 = 0; e2 < Ed; ++e2)
                    s = fmaf(Wf[((size_t)(l * Ed + e)) * Ed + e2], ln1[e2], s);
                fo[e] = fmaxf(s, 0.0f) + ln1[e];
            }
            float mu2 = 0.f;
            #pragma unroll
            for (int e = 0; e < Ed; ++e) mu2 += fo[e];
            mu2 *= 0.2f;
            float var2 = 0.f;
            #pragma unroll
            for (int e = 0; e < Ed; ++e) { float dd = fo[e] - mu2; var2 = fmaf(dd, dd, var2); }
            var2 *= 0.2f;
            float rinv2 = rsqrtf(var2 + 1e-5f);
            #pragma unroll
            for (int e = 0; e < Ed; ++e)
                sm.feat[tid][e] = (fo[e] - mu2) * rinv2 * g2[l * Ed + e] + b2[l * Ed + e];
        }
        __syncthreads();
    } // layers

    // ---------------- write output ----------------
    for (int idx = tid; idx < NT * Ed; idx += NTHREADS)
        out[(size_t)b * (NT * Ed) + idx] = (&sm.feat[0][0])[idx];
}

extern "C" void kernel_launch(void* const* d_in, const int* in_sizes, int n_in,
                              void* d_out, int out_size)
{
    const float* x   = (const float*)d_in[0];
    const float* Wq  = (const float*)d_in[1];
    const float* Wk  = (const float*)d_in[2];
    const float* Wv  = (const float*)d_in[3];
    const float* Wo  = (const float*)d_in[4];
    const float* Wf  = (const float*)d_in[5];
    const float* bfb = (const float*)d_in[6];
    const float* g1  = (const float*)d_in[7];
    const float* b1  = (const float*)d_in[8];
    const float* g2  = (const float*)d_in[9];
    const float* b2  = (const float*)d_in[10];
    float* out = (float*)d_out;

    cudaFuncSetAttribute(encoder_kernel,
                         cudaFuncAttributeMaxDynamicSharedMemorySize,
                         (int)sizeof(SMem));
    encoder_kernel<<<Bb, NTHREADS, sizeof(SMem)>>>(x, Wq, Wk, Wv, Wo, Wf, bfb,
                                                   g1, b1, g2, b2, out);
}

// round 6
// speedup vs baseline: 2.3013x; 1.4182x over previous
#include <cuda_runtime.h>
#include <math.h>
#include <float.h>

#define Bb      1024
#define NW      300
#define NT      100      // tokens
#define Ed      5        // embed dim
#define Hh      4        // heads
#define Dd      64       // head dim
#define Ll      3        // layers
#define NTHREADS 512
#define NWARP   16
#define RPW     7        // real rows per warp (warp w owns tokens 7w..7w+6)
#define SLOTS   8        // padded row slots per warp
#define QSTRIDE 132      // qT row stride in floats (16B-aligned rows)
#define KSTRIDE (NT + 1) // 101 (odd -> conflict-free lane reads)
#define USTRIDE 9        // u row stride (9 coprime 32 -> conflict-free lane reads)

// folded W' = Wo_h · Wv_h  (per layer, per head, 5x5)
__device__ float Wp_g[Ll * Hh * Ed * Ed];

struct SMem {
    float feat[NT][Ed];          // 500
    float attn[NT][Ed];          // 500
    float maskf[NT];             // 100
    float wp[Ll * Hh * Ed * Ed]; // 300  (folded weights, staged once)
    float qT[Dd][QSTRIDE];       // 8448 (slot-major transposed q, scale folded)
    float kT[Dd][KSTRIDE];       // 6464
    float u[NT][USTRIDE];        // 900  (u = feat @ W'^T for current head)
};                               // 17,212 floats = 68,848 B

// ---- packed f32x2 helpers (FFMA2 path, PTX-only) ----
__device__ __forceinline__ unsigned long long pk2(float lo, float hi) {
    unsigned long long r;
    asm("mov.b64 %0, {%1, %2};" : "=l"(r) : "f"(lo), "f"(hi));
    return r;
}
__device__ __forceinline__ unsigned long long splat2(float v) {
    unsigned long long r;
    asm("mov.b64 %0, {%1, %1};" : "=l"(r) : "f"(v));
    return r;
}
__device__ __forceinline__ void unpk2(unsigned long long p, float& lo, float& hi) {
    asm("mov.b64 {%0, %1}, %2;" : "=f"(lo), "=f"(hi) : "l"(p));
}
__device__ __forceinline__ unsigned long long ffma2(unsigned long long a,
                                                    unsigned long long b,
                                                    unsigned long long c) {
    unsigned long long d;
    asm("fma.rn.f32x2 %0, %1, %2, %3;" : "=l"(d) : "l"(a), "l"(b), "l"(c));
    return d;
}

// ---- pre-pass: W'[l][h][e][e2] = sum_d Wo[l][e][h*D+d] * Wv[l][h][d][e2] ----
__global__ void fold_kernel(const float* __restrict__ Wo,
                            const float* __restrict__ Wv)
{
    int idx = threadIdx.x;
    if (idx < Ll * Hh * Ed * Ed) {
        int l   = idx / (Hh * Ed * Ed);
        int rem = idx % (Hh * Ed * Ed);
        int h   = rem / (Ed * Ed);
        int e   = (rem / Ed) % Ed;
        int e2  = rem % Ed;
        float s = 0.0f;
        for (int d = 0; d < Dd; ++d)
            s = fmaf(Wo[((size_t)(l * Ed + e)) * (Hh * Dd) + h * Dd + d],
                     Wv[((size_t)((l * Hh + h) * Dd + d)) * Ed + e2], s);
        Wp_g[idx] = s;
    }
}

__global__ __launch_bounds__(NTHREADS, 1)
void encoder_kernel(const float* __restrict__ x,
                    const float* __restrict__ Wq, const float* __restrict__ Wk,
                    const float* __restrict__ Wf, const float* __restrict__ bfb,
                    const float* __restrict__ g1, const float* __restrict__ b1,
                    const float* __restrict__ g2, const float* __restrict__ b2,
                    float* __restrict__ out)
{
    extern __shared__ unsigned char smem_raw[];
    SMem& sm = *reinterpret_cast<SMem*>(smem_raw);

    const int b    = blockIdx.x;
    const int tid  = threadIdx.x;
    const int lane = tid & 31;
    const int w    = tid >> 5;

    // ---------------- embedding + mask + stage folded weights ----------------
    if (tid < NT) {
        float k0 = x[b * NW + tid * 3 + 0];
        float k1 = x[b * NW + tid * 3 + 1];
        float k2 = x[b * NW + tid * 3 + 2];
        bool  m  = k2 > 0.0f;
        float sn, cs;
        sincosf((float)tid, &sn, &cs);
        sm.maskf[tid]   = m ? 1.0f : 0.0f;
        sm.feat[tid][0] = m ? k0 : 0.0f;
        sm.feat[tid][1] = m ? k1 : 0.0f;
        sm.feat[tid][2] = m ? k2 : 0.0f;
        sm.feat[tid][3] = m ? sn : 0.0f;
        sm.feat[tid][4] = m ? cs : 0.0f;
    }
    if (tid < Ll * Hh * Ed * Ed) sm.wp[tid] = Wp_g[tid];
    __syncthreads();

    const int t0    = w * RPW;
    const int s0    = w * SLOTS;
    int nr          = NT - t0;
    const int nrows = nr < 0 ? 0 : (nr > RPW ? RPW : nr);

    for (int l = 0; l < Ll; ++l) {
        // per-layer output accumulators (all heads folded in)
        float part[RPW][Ed];
        #pragma unroll
        for (int r = 0; r < RPW; ++r)
            #pragma unroll
            for (int e = 0; e < Ed; ++e) part[r][e] = 0.0f;

        for (int h = 0; h < Hh; ++h) {
            // -------- projection phase: q,k (scale folded into q) + u --------
            {
                const int d     = tid & 63;
                const int part8 = tid >> 6;           // 0..7
                const float* wqp = Wq + ((size_t)((l * Hh + h) * Dd + d)) * Ed;
                const float* wkp = Wk + ((size_t)((l * Hh + h) * Dd + d)) * Ed;
                float wq[Ed], wk[Ed];
                #pragma unroll
                for (int e = 0; e < Ed; ++e) {
                    wq[e] = wqp[e] * 0.125f;
                    wk[e] = wkp[e];
                }
                for (int r = part8; r < NT; r += 8) {
                    float f[Ed];
                    #pragma unroll
                    for (int e = 0; e < Ed; ++e) f[e] = sm.feat[r][e];
                    float qv = 0.f, kv = 0.f;
                    #pragma unroll
                    for (int e = 0; e < Ed; ++e) {
                        qv = fmaf(wq[e], f[e], qv);
                        kv = fmaf(wk[e], f[e], kv);
                    }
                    const int slot = (r / RPW) * SLOTS + (r % RPW);
                    sm.qT[d][slot] = qv;
                    sm.kT[d][r]    = kv;
                }
            }
            // u[j][e] = feat[j] . W'[l][h][e][:]
            if (tid < NT * Ed) {
                const int j = tid / Ed;
                const int e = tid % Ed;
                const float* wpp = &sm.wp[((l * Hh + h) * Ed + e) * Ed];
                float s = 0.0f;
                #pragma unroll
                for (int e2 = 0; e2 < Ed; ++e2)
                    s = fmaf(sm.feat[j][e2], wpp[e2], s);
                sm.u[j][e] = s;
            }
            __syncthreads();

            if (nrows > 0) {
                // ------------- scores: packed row-pair dot products ----------
                int jj[4];
                #pragma unroll
                for (int jt = 0; jt < 4; ++jt) {
                    int j = lane + jt * 32;
                    jj[jt] = (j < NT) ? j : 0;
                }
                unsigned long long acc[4][4];
                #pragma unroll
                for (int jt = 0; jt < 4; ++jt)
                    #pragma unroll
                    for (int p = 0; p < 4; ++p) acc[jt][p] = 0ULL;

                #pragma unroll 2
                for (int d = 0; d < Dd; ++d) {
                    float4 qA = *reinterpret_cast<const float4*>(&sm.qT[d][s0]);
                    float4 qB = *reinterpret_cast<const float4*>(&sm.qT[d][s0 + 4]);
                    unsigned long long qp0 = pk2(qA.x, qA.y);
                    unsigned long long qp1 = pk2(qA.z, qA.w);
                    unsigned long long qp2 = pk2(qB.x, qB.y);
                    unsigned long long qp3 = pk2(qB.z, qB.w);
                    #pragma unroll
                    for (int jt = 0; jt < 4; ++jt) {
                        unsigned long long ks = splat2(sm.kT[d][jj[jt]]);
                        acc[jt][0] = ffma2(qp0, ks, acc[jt][0]);
                        acc[jt][1] = ffma2(qp1, ks, acc[jt][1]);
                        acc[jt][2] = ffma2(qp2, ks, acc[jt][2]);
                        acc[jt][3] = ffma2(qp3, ks, acc[jt][3]);
                    }
                }

                // ------- fused mask + softmax, P kept in registers -----------
                const bool v3ok = (lane + 96) < NT;
                const float mj0 = sm.maskf[jj[0]];
                const float mj1 = sm.maskf[jj[1]];
                const float mj2 = sm.maskf[jj[2]];
                const float mj3 = sm.maskf[jj[3]];
                float P0[RPW], P1[RPW], P2[RPW], P3[RPW];
                #pragma unroll
                for (int r = 0; r < RPW; ++r) {
                    if (r < nrows) {
                        const float mi = sm.maskf[t0 + r];
                        float lo, hi, s0v, s1v, s2v, s3v;
                        unpk2(acc[0][r >> 1], lo, hi);
                        s0v = (mi * mj0 > 0.5f) ? ((r & 1) ? hi : lo) : -FLT_MAX;
                        unpk2(acc[1][r >> 1], lo, hi);
                        s1v = (mi * mj1 > 0.5f) ? ((r & 1) ? hi : lo) : -FLT_MAX;
                        unpk2(acc[2][r >> 1], lo, hi);
                        s2v = (mi * mj2 > 0.5f) ? ((r & 1) ? hi : lo) : -FLT_MAX;
                        unpk2(acc[3][r >> 1], lo, hi);
                        s3v = (v3ok && (mi * mj3 > 0.5f)) ? ((r & 1) ? hi : lo) : -FLT_MAX;

                        float m = fmaxf(fmaxf(s0v, s1v), fmaxf(s2v, s3v));
                        #pragma unroll
                        for (int off = 16; off > 0; off >>= 1)
                            m = fmaxf(m, __shfl_xor_sync(0xffffffffu, m, off));
                        float p0 = __expf(s0v - m);
                        float p1 = __expf(s1v - m);
                        float p2 = __expf(s2v - m);
                        float p3 = v3ok ? __expf(s3v - m) : 0.0f;
                        float sum = p0 + p1 + p2 + p3;
                        #pragma unroll
                        for (int off = 16; off > 0; off >>= 1)
                            sum += __shfl_xor_sync(0xffffffffu, sum, off);
                        const float inv = 1.0f / sum;
                        P0[r] = p0 * inv;
                        P1[r] = p1 * inv;
                        P2[r] = p2 * inv;
                        P3[r] = p3 * inv;
                    } else {
                        P0[r] = P1[r] = P2[r] = P3[r] = 0.0f;
                    }
                }

                // ------- AV' : part[r][e] += P[r][j] * u[j][e] ---------------
                #pragma unroll
                for (int jt = 0; jt < 4; ++jt) {
                    const int j = jj[jt];
                    float u0 = sm.u[j][0];
                    float u1 = sm.u[j][1];
                    float u2 = sm.u[j][2];
                    float u3 = sm.u[j][3];
                    float u4 = sm.u[j][4];
                    const float* Pj = (jt == 0) ? P0 : (jt == 1) ? P1 : (jt == 2) ? P2 : P3;
                    #pragma unroll
                    for (int r = 0; r < RPW; ++r) {
                        const float p = Pj[r];
                        part[r][0] = fmaf(p, u0, part[r][0]);
                        part[r][1] = fmaf(p, u1, part[r][1]);
                        part[r][2] = fmaf(p, u2, part[r][2]);
                        part[r][3] = fmaf(p, u3, part[r][3]);
                        part[r][4] = fmaf(p, u4, part[r][4]);
                    }
                }
            }
            __syncthreads();
        } // heads

        // ---- cross-lane reduce part (all heads included), write attn --------
        for (int r = 0; r < nrows; ++r) {
            #pragma unroll
            for (int e = 0; e < Ed; ++e) {
                float s = part[r][e];
                #pragma unroll
                for (int off = 16; off > 0; off >>= 1)
                    s += __shfl_xor_sync(0xffffffffu, s, off);
                if (lane == 0) sm.attn[t0 + r][e] = s;
            }
        }
        __syncthreads();

        // ---------------- residual + LN1 + FFN + residual + LN2 --------------
        if (tid < NT) {
            float a[Ed], ln1[Ed], fo[Ed];
            #pragma unroll
            for (int e = 0; e < Ed; ++e) a[e] = sm.attn[tid][e] + sm.feat[tid][e];
            float mu = 0.f;
            #pragma unroll
            for (int e = 0; e < Ed; ++e) mu += a[e];
            mu *= 0.2f;
            float var = 0.f;
            #pragma unroll
            for (int e = 0; e < Ed; ++e) { float dd = a[e] - mu; var = fmaf(dd, dd, var); }
            var *= 0.2f;
            float rinv = rsqrtf(var + 1e-5f);
            #pragma unroll
            for (int e = 0; e < Ed; ++e)
                ln1[e] = (a[e] - mu) * rinv * g1[l * Ed + e] + b1[l * Ed + e];
            #pragma unroll
            for (int e = 0; e < Ed; ++e) {
                float s = bfb[l * Ed + e];
                #pragma unroll
                for (int e2 = 0; e2 < Ed; ++e2)
                    s = fmaf(Wf[((size_t)(l * Ed + e)) * Ed + e2], ln1[e2], s);
                fo[e] = fmaxf(s, 0.0f) + ln1[e];
            }
            float mu2 = 0.f;
            #pragma unroll
            for (int e = 0; e < Ed; ++e) mu2 += fo[e];
            mu2 *= 0.2f;
            float var2 = 0.f;
            #pragma unroll
            for (int e = 0; e < Ed; ++e) { float dd = fo[e] - mu2; var2 = fmaf(dd, dd, var2); }
            var2 *= 0.2f;
            float rinv2 = rsqrtf(var2 + 1e-5f);
            #pragma unroll
            for (int e = 0; e < Ed; ++e)
                sm.feat[tid][e] = (fo[e] - mu2) * rinv2 * g2[l * Ed + e] + b2[l * Ed + e];
        }
        __syncthreads();
    } // layers

    // ---------------- write output ----------------
    for (int idx = tid; idx < NT * Ed; idx += NTHREADS)
        out[(size_t)b * (NT * Ed) + idx] = (&sm.feat[0][0])[idx];
}

extern "C" void kernel_launch(void* const* d_in, const int* in_sizes, int n_in,
                              void* d_out, int out_size)
{
    const float* x   = (const float*)d_in[0];
    const float* Wq  = (const float*)d_in[1];
    const float* Wk  = (const float*)d_in[2];
    const float* Wv  = (const float*)d_in[3];
    const float* Wo  = (const float*)d_in[4];
    const float* Wf  = (const float*)d_in[5];
    const float* bfb = (const float*)d_in[6];
    const float* g1  = (const float*)d_in[7];
    const float* b1  = (const float*)d_in[8];
    const float* g2  = (const float*)d_in[9];
    const float* b2  = (const float*)d_in[10];
    float* out = (float*)d_out;

    fold_kernel<<<1, 320>>>(Wo, Wv);

    cudaFuncSetAttribute(encoder_kernel,
                         cudaFuncAttributeMaxDynamicSharedMemorySize,
                         (int)sizeof(SMem));
    encoder_kernel<<<Bb, NTHREADS, sizeof(SMem)>>>(x, Wq, Wk, Wf, bfb,
                                                   g1, b1, g2, b2, out);
}

// round 7
// speedup vs baseline: 6.9758x; 3.0313x over previous
#include <cuda_runtime.h>
#include <math.h>
#include <float.h>

#define Bb      1024
#define NW      300
#define NT      100      // tokens
#define Ed      5        // embed dim
#define Hh      4        // heads
#define Dd      64       // head dim
#define Ll      3        // layers
#define NTHREADS 512
#define NWARP   16
#define RPW     7        // real rows per warp (warp w owns tokens 7w..7w+6)
#define SLOTS   8        // padded row slots per warp
#define QSTRIDE 132      // featT row stride (16B-aligned row starts)

// folded 5x5 matrices per (layer, head):
//   Mqk = scale * Wq_h^T * Wk_h   (score bilinear form)
//   Wp  = Wo_h * Wv_h             (value+output fold)
__device__ float Mqk_g[Ll * Hh * Ed * Ed];
__device__ float Wp_g [Ll * Hh * Ed * Ed];

struct SMem {
    float feat[NT][Ed];           // 500
    float attn[NT][Ed];           // 500
    float maskf[NT];              // 100
    float mqk[Ll * Hh * Ed * Ed]; // 300
    float wp [Ll * Hh * Ed * Ed]; // 300
    float featT[Ed][QSTRIDE];     // 660 (slot-major transposed feat)
    float g[Hh * NT * Ed];        // 2000  g[h][j][e] = Mqk . feat[j]
    float u[Hh * NT * Ed];        // 2000  u[h][j][e] = Wp  . feat[j]
};                                // 6360 floats = 25,440 B (static smem OK)

// ---- packed f32x2 helpers (FFMA2 path, PTX-only) ----
__device__ __forceinline__ unsigned long long pk2(float lo, float hi) {
    unsigned long long r;
    asm("mov.b64 %0, {%1, %2};" : "=l"(r) : "f"(lo), "f"(hi));
    return r;
}
__device__ __forceinline__ unsigned long long splat2(float v) {
    unsigned long long r;
    asm("mov.b64 %0, {%1, %1};" : "=l"(r) : "f"(v));
    return r;
}
__device__ __forceinline__ void unpk2(unsigned long long p, float& lo, float& hi) {
    asm("mov.b64 {%0, %1}, %2;" : "=f"(lo), "=f"(hi) : "l"(p));
}
__device__ __forceinline__ unsigned long long ffma2(unsigned long long a,
                                                    unsigned long long b,
                                                    unsigned long long c) {
    unsigned long long d;
    asm("fma.rn.f32x2 %0, %1, %2, %3;" : "=l"(d) : "l"(a), "l"(b), "l"(c));
    return d;
}

// ---- pre-pass: fold the 64-dim head space into 5x5 matrices ----
__global__ void fold_kernel(const float* __restrict__ Wq,
                            const float* __restrict__ Wk,
                            const float* __restrict__ Wv,
                            const float* __restrict__ Wo)
{
    int idx = threadIdx.x;                 // 0 .. 299
    if (idx < Ll * Hh * Ed * Ed) {
        int l   = idx / (Hh * Ed * Ed);
        int rem = idx % (Hh * Ed * Ed);
        int h   = rem / (Ed * Ed);
        int e1  = (rem / Ed) % Ed;
        int e2  = rem % Ed;
        float sq = 0.0f, sp = 0.0f;
        for (int d = 0; d < Dd; ++d) {
            sq = fmaf(Wq[((size_t)((l * Hh + h) * Dd + d)) * Ed + e1],
                      Wk[((size_t)((l * Hh + h) * Dd + d)) * Ed + e2], sq);
            sp = fmaf(Wo[((size_t)(l * Ed + e1)) * (Hh * Dd) + h * Dd + d],
                      Wv[((size_t)((l * Hh + h) * Dd + d)) * Ed + e2], sp);
        }
        Mqk_g[idx] = sq * 0.125f;          // 1/sqrt(64) folded in
        Wp_g[idx]  = sp;
    }
}

__global__ __launch_bounds__(NTHREADS, 1)
void encoder_kernel(const float* __restrict__ x,
                    const float* __restrict__ Wf, const float* __restrict__ bfb,
                    const float* __restrict__ g1, const float* __restrict__ b1,
                    const float* __restrict__ g2, const float* __restrict__ b2,
                    float* __restrict__ out)
{
    __shared__ SMem sm;

    const int b    = blockIdx.x;
    const int tid  = threadIdx.x;
    const int lane = tid & 31;
    const int w    = tid >> 5;

    // ---------------- embedding + mask + stage folded weights ----------------
    if (tid < NT) {
        float k0 = x[b * NW + tid * 3 + 0];
        float k1 = x[b * NW + tid * 3 + 1];
        float k2 = x[b * NW + tid * 3 + 2];
        bool  m  = k2 > 0.0f;
        float sn, cs;
        sincosf((float)tid, &sn, &cs);
        sm.maskf[tid]   = m ? 1.0f : 0.0f;
        sm.feat[tid][0] = m ? k0 : 0.0f;
        sm.feat[tid][1] = m ? k1 : 0.0f;
        sm.feat[tid][2] = m ? k2 : 0.0f;
        sm.feat[tid][3] = m ? sn : 0.0f;
        sm.feat[tid][4] = m ? cs : 0.0f;
    }
    if (tid < Ll * Hh * Ed * Ed) {
        sm.mqk[tid] = Mqk_g[tid];
        sm.wp[tid]  = Wp_g[tid];
    }
    __syncthreads();

    const int t0    = w * RPW;
    const int s0    = w * SLOTS;
    int nr          = NT - t0;
    const int nrows = nr < 0 ? 0 : (nr > RPW ? RPW : nr);

    int jj[4];
    #pragma unroll
    for (int jt = 0; jt < 4; ++jt) {
        int j = lane + jt * 32;
        jj[jt] = (j < NT) ? j : 0;
    }
    const bool v3ok = (lane + 96) < NT;

    for (int l = 0; l < Ll; ++l) {
        // ---- phase A: g/u for ALL heads + featT, one barrier ----------------
        if (tid < Hh * NT) {
            const int h = tid / NT;
            const int j = tid % NT;
            float f0 = sm.feat[j][0], f1 = sm.feat[j][1], f2 = sm.feat[j][2];
            float f3 = sm.feat[j][3], f4 = sm.feat[j][4];
            const float* mq  = &sm.mqk[(l * Hh + h) * 25];
            const float* wpp = &sm.wp [(l * Hh + h) * 25];
            #pragma unroll
            for (int e = 0; e < Ed; ++e) {
                float gs = mq[e * 5 + 0] * f0;
                gs = fmaf(mq[e * 5 + 1], f1, gs);
                gs = fmaf(mq[e * 5 + 2], f2, gs);
                gs = fmaf(mq[e * 5 + 3], f3, gs);
                gs = fmaf(mq[e * 5 + 4], f4, gs);
                float us = wpp[e * 5 + 0] * f0;
                us = fmaf(wpp[e * 5 + 1], f1, us);
                us = fmaf(wpp[e * 5 + 2], f2, us);
                us = fmaf(wpp[e * 5 + 3], f3, us);
                us = fmaf(wpp[e * 5 + 4], f4, us);
                sm.g[(h * NT + j) * Ed + e] = gs;
                sm.u[(h * NT + j) * Ed + e] = us;
            }
        } else if (tid < Hh * NT + NT) {
            const int j    = tid - Hh * NT;
            const int slot = (j / RPW) * SLOTS + (j % RPW);
            #pragma unroll
            for (int e = 0; e < Ed; ++e)
                sm.featT[e][slot] = sm.feat[j][e];
        }
        __syncthreads();

        // ---- head loop: no internal barriers ------------------------------
        float part[RPW][Ed];
        #pragma unroll
        for (int r = 0; r < RPW; ++r)
            #pragma unroll
            for (int e = 0; e < Ed; ++e) part[r][e] = 0.0f;

        if (nrows > 0) {
            const float mi0 = sm.maskf[t0 + 0];
            const float mj0 = sm.maskf[jj[0]];
            const float mj1 = sm.maskf[jj[1]];
            const float mj2 = sm.maskf[jj[2]];
            const float mj3 = sm.maskf[jj[3]];
            (void)mi0;

            for (int h = 0; h < Hh; ++h) {
                const float* gh = &sm.g[h * NT * Ed];
                const float* uh = &sm.u[h * NT * Ed];

                // scores: S[i][j] = featT[:, i] . g[j]   (5-wide!)
                unsigned long long acc[4][4];
                #pragma unroll
                for (int jt = 0; jt < 4; ++jt)
                    #pragma unroll
                    for (int p = 0; p < 4; ++p) acc[jt][p] = 0ULL;

                #pragma unroll
                for (int e = 0; e < Ed; ++e) {
                    float4 qA = *reinterpret_cast<const float4*>(&sm.featT[e][s0]);
                    float4 qB = *reinterpret_cast<const float4*>(&sm.featT[e][s0 + 4]);
                    unsigned long long qp0 = pk2(qA.x, qA.y);
                    unsigned long long qp1 = pk2(qA.z, qA.w);
                    unsigned long long qp2 = pk2(qB.x, qB.y);
                    unsigned long long qp3 = pk2(qB.z, qB.w);
                    #pragma unroll
                    for (int jt = 0; jt < 4; ++jt) {
                        unsigned long long ks = splat2(gh[jj[jt] * Ed + e]);
                        acc[jt][0] = ffma2(qp0, ks, acc[jt][0]);
                        acc[jt][1] = ffma2(qp1, ks, acc[jt][1]);
                        acc[jt][2] = ffma2(qp2, ks, acc[jt][2]);
                        acc[jt][3] = ffma2(qp3, ks, acc[jt][3]);
                    }
                }

                // fused mask + softmax, P in registers
                float P0[RPW], P1[RPW], P2[RPW], P3[RPW];
                #pragma unroll
                for (int r = 0; r < RPW; ++r) {
                    if (r < nrows) {
                        const float mi = sm.maskf[t0 + r];
                        float lo, hi, s0v, s1v, s2v, s3v;
                        unpk2(acc[0][r >> 1], lo, hi);
                        s0v = (mi * mj0 > 0.5f) ? ((r & 1) ? hi : lo) : -FLT_MAX;
                        unpk2(acc[1][r >> 1], lo, hi);
                        s1v = (mi * mj1 > 0.5f) ? ((r & 1) ? hi : lo) : -FLT_MAX;
                        unpk2(acc[2][r >> 1], lo, hi);
                        s2v = (mi * mj2 > 0.5f) ? ((r & 1) ? hi : lo) : -FLT_MAX;
                        unpk2(acc[3][r >> 1], lo, hi);
                        s3v = (v3ok && (mi * mj3 > 0.5f)) ? ((r & 1) ? hi : lo) : -FLT_MAX;

                        float m = fmaxf(fmaxf(s0v, s1v), fmaxf(s2v, s3v));
                        #pragma unroll
                        for (int off = 16; off > 0; off >>= 1)
                            m = fmaxf(m, __shfl_xor_sync(0xffffffffu, m, off));
                        float p0 = __expf(s0v - m);
                        float p1 = __expf(s1v - m);
                        float p2 = __expf(s2v - m);
                        float p3 = v3ok ? __expf(s3v - m) : 0.0f;
                        float sum = p0 + p1 + p2 + p3;
                        #pragma unroll
                        for (int off = 16; off > 0; off >>= 1)
                            sum += __shfl_xor_sync(0xffffffffu, sum, off);
                        const float inv = __fdividef(1.0f, sum);
                        P0[r] = p0 * inv;
                        P1[r] = p1 * inv;
                        P2[r] = p2 * inv;
                        P3[r] = p3 * inv;
                    } else {
                        P0[r] = P1[r] = P2[r] = P3[r] = 0.0f;
                    }
                }

                // AV' : part[r][e] += P[r][j] * u[j][e]
                #pragma unroll
                for (int jt = 0; jt < 4; ++jt) {
                    const float* uj = &uh[jj[jt] * Ed];
                    float u0 = uj[0], u1 = uj[1], u2 = uj[2], u3 = uj[3], u4 = uj[4];
                    const float* Pj = (jt == 0) ? P0 : (jt == 1) ? P1 : (jt == 2) ? P2 : P3;
                    #pragma unroll
                    for (int r = 0; r < RPW; ++r) {
                        const float p = Pj[r];
                        part[r][0] = fmaf(p, u0, part[r][0]);
                        part[r][1] = fmaf(p, u1, part[r][1]);
                        part[r][2] = fmaf(p, u2, part[r][2]);
                        part[r][3] = fmaf(p, u3, part[r][3]);
                        part[r][4] = fmaf(p, u4, part[r][4]);
                    }
                }
            } // heads
        }

        // ---- cross-lane reduce part (all heads included), write attn --------
        for (int r = 0; r < nrows; ++r) {
            #pragma unroll
            for (int e = 0; e < Ed; ++e) {
                float s = part[r][e];
                #pragma unroll
                for (int off = 16; off > 0; off >>= 1)
                    s += __shfl_xor_sync(0xffffffffu, s, off);
                if (lane == 0) sm.attn[t0 + r][e] = s;
            }
        }
        __syncthreads();

        // ---------------- residual + LN1 + FFN + residual + LN2 --------------
        if (tid < NT) {
            float a[Ed], ln1[Ed], fo[Ed];
            #pragma unroll
            for (int e = 0; e < Ed; ++e) a[e] = sm.attn[tid][e] + sm.feat[tid][e];
            float mu = 0.f;
            #pragma unroll
            for (int e = 0; e < Ed; ++e) mu += a[e];
            mu *= 0.2f;
            float var = 0.f;
            #pragma unroll
            for (int e = 0; e < Ed; ++e) { float dd = a[e] - mu; var = fmaf(dd, dd, var); }
            var *= 0.2f;
            float rinv = rsqrtf(var + 1e-5f);
            #pragma unroll
            for (int e = 0; e < Ed; ++e)
                ln1[e] = (a[e] - mu) * rinv * g1[l * Ed + e] + b1[l * Ed + e];
            #pragma unroll
            for (int e = 0; e < Ed; ++e) {
                float s = bfb[l * Ed + e];
                #pragma unroll
                for (int e2 = 0; e2 < Ed; ++e2)
                    s = fmaf(Wf[((size_t)(l * Ed + e)) * Ed + e2], ln1[e2], s);
                fo[e] = fmaxf(s, 0.0f) + ln1[e];
            }
            float mu2 = 0.f;
            #pragma unroll
            for (int e = 0; e < Ed; ++e) mu2 += fo[e];
            mu2 *= 0.2f;
            float var2 = 0.f;
            #pragma unroll
            for (int e = 0; e < Ed; ++e) { float dd = fo[e] - mu2; var2 = fmaf(dd, dd, var2); }
            var2 *= 0.2f;
            float rinv2 = rsqrtf(var2 + 1e-5f);
            #pragma unroll
            for (int e = 0; e < Ed; ++e)
                sm.feat[tid][e] = (fo[e] - mu2) * rinv2 * g2[l * Ed + e] + b2[l * Ed + e];
        }
        __syncthreads();
    } // layers

    // ---------------- write output ----------------
    for (int idx = tid; idx < NT * Ed; idx += NTHREADS)
        out[(size_t)b * (NT * Ed) + idx] = (&sm.feat[0][0])[idx];
}

extern "C" void kernel_launch(void* const* d_in, const int* in_sizes, int n_in,
                              void* d_out, int out_size)
{
    const float* x   = (const float*)d_in[0];
    const float* Wq  = (const float*)d_in[1];
    const float* Wk  = (const float*)d_in[2];
    const float* Wv  = (const float*)d_in[3];
    const float* Wo  = (const float*)d_in[4];
    const float* Wf  = (const float*)d_in[5];
    const float* bfb = (const float*)d_in[6];
    const float* g1  = (const float*)d_in[7];
    const float* b1  = (const float*)d_in[8];
    const float* g2  = (const float*)d_in[9];
    const float* b2  = (const float*)d_in[10];
    float* out = (float*)d_out;

    fold_kernel<<<1, 320>>>(Wq, Wk, Wv, Wo);
    encoder_kernel<<<Bb, NTHREADS>>>(x, Wf, bfb, g1, b1, g2, b2, out);
}

// round 9
// speedup vs baseline: 9.3722x; 1.3435x over previous
#include <cuda_runtime.h>
#include <math.h>
#include <float.h>

#define Bb      1024
#define NW      300
#define NT      100      // tokens
#define Ed      5        // embed dim
#define Hh      4        // heads
#define Dd      64       // head dim
#define Ll      3        // layers
#define NTHREADS 512
#define NWARP   16
#define RPW     7        // real rows per warp (warp w owns tokens 7w..7w+6)
#define SLOTS   8        // padded row slots per warp
#define QSTRIDE 132      // featT row stride (16B-aligned row starts)

// folded 5x5 matrices per (layer, head):
//   Mqk = scale * Wq_h^T * Wk_h   (score bilinear form)
//   Wp  = Wo_h * Wv_h             (value+output fold)
__device__ float Mqk_g[Ll * Hh * Ed * Ed];
__device__ float Wp_g [Ll * Hh * Ed * Ed];

struct SMem {
    float feat[NT][Ed];           // 500
    float attn[NT][Ed];           // 500
    float maskf[NT];              // 100
    float mqk[Ll * Hh * Ed * Ed]; // 300
    float wp [Ll * Hh * Ed * Ed]; // 300
    float featT[Ed][QSTRIDE];     // 660 (slot-major transposed feat)
    float g[Hh * NT * Ed];        // 2000  g[h][j][e] = Mqk . feat[j]
    float u[Hh * NT * Ed];        // 2000  u[h][j][e] = Wp  . feat[j]
};                                // 6360 floats = 25,440 B

// ---- packed f32x2 helpers (FFMA2/FADD2 path, PTX-only) ----
__device__ __forceinline__ unsigned long long pk2(float lo, float hi) {
    unsigned long long r;
    asm("mov.b64 %0, {%1, %2};" : "=l"(r) : "f"(lo), "f"(hi));
    return r;
}
__device__ __forceinline__ unsigned long long splat2(float v) {
    unsigned long long r;
    asm("mov.b64 %0, {%1, %1};" : "=l"(r) : "f"(v));
    return r;
}
__device__ __forceinline__ void unpk2(unsigned long long p, float& lo, float& hi) {
    asm("mov.b64 {%0, %1}, %2;" : "=f"(lo), "=f"(hi) : "l"(p));
}
__device__ __forceinline__ unsigned long long ffma2(unsigned long long a,
                                                    unsigned long long b,
                                                    unsigned long long c) {
    unsigned long long d;
    asm("fma.rn.f32x2 %0, %1, %2, %3;" : "=l"(d) : "l"(a), "l"(b), "l"(c));
    return d;
}
__device__ __forceinline__ unsigned long long fadd2(unsigned long long a,
                                                    unsigned long long b) {
    unsigned long long d;
    asm("add.rn.f32x2 %0, %1, %2;" : "=l"(d) : "l"(a), "l"(b));
    return d;
}

// ---- pre-pass: fold the 64-dim head space into 5x5 matrices ----
__global__ void fold_kernel(const float* __restrict__ Wq,
                            const float* __restrict__ Wk,
                            const float* __restrict__ Wv,
                            const float* __restrict__ Wo)
{
    int idx = threadIdx.x;                 // 0 .. 299
    if (idx < Ll * Hh * Ed * Ed) {
        int l   = idx / (Hh * Ed * Ed);
        int rem = idx % (Hh * Ed * Ed);
        int h   = rem / (Ed * Ed);
        int e1  = (rem / Ed) % Ed;
        int e2  = rem % Ed;
        float sq = 0.0f, sp = 0.0f;
        for (int d = 0; d < Dd; ++d) {
            sq = fmaf(Wq[((size_t)((l * Hh + h) * Dd + d)) * Ed + e1],
                      Wk[((size_t)((l * Hh + h) * Dd + d)) * Ed + e2], sq);
            sp = fmaf(Wo[((size_t)(l * Ed + e1)) * (Hh * Dd) + h * Dd + d],
                      Wv[((size_t)((l * Hh + h) * Dd + d)) * Ed + e2], sp);
        }
        Mqk_g[idx] = sq * 0.125f;          // 1/sqrt(64) folded in
        Wp_g[idx]  = sp;
    }
}

__global__ __launch_bounds__(NTHREADS, 1)
void encoder_kernel(const float* __restrict__ x,
                    const float* __restrict__ Wf, const float* __restrict__ bfb,
                    const float* __restrict__ g1, const float* __restrict__ b1,
                    const float* __restrict__ g2, const float* __restrict__ b2,
                    float* __restrict__ out)
{
    __shared__ SMem sm;

    const int b    = blockIdx.x;
    const int tid  = threadIdx.x;
    const int lane = tid & 31;
    const int w    = tid >> 5;

    // ---------------- embedding + mask + stage folded weights ----------------
    if (tid < NT) {
        float k0 = x[b * NW + tid * 3 + 0];
        float k1 = x[b * NW + tid * 3 + 1];
        float k2 = x[b * NW + tid * 3 + 2];
        bool  m  = k2 > 0.0f;
        float sn, cs;
        sincosf((float)tid, &sn, &cs);
        sm.maskf[tid]   = m ? 1.0f : 0.0f;
        sm.feat[tid][0] = m ? k0 : 0.0f;
        sm.feat[tid][1] = m ? k1 : 0.0f;
        sm.feat[tid][2] = m ? k2 : 0.0f;
        sm.feat[tid][3] = m ? sn : 0.0f;
        sm.feat[tid][4] = m ? cs : 0.0f;
    }
    if (tid < Ll * Hh * Ed * Ed) {
        sm.mqk[tid] = Mqk_g[tid];
        sm.wp[tid]  = Wp_g[tid];
    }
    __syncthreads();

    const int t0    = w * RPW;
    const int s0    = w * SLOTS;
    int nr          = NT - t0;
    const int nrows = nr < 0 ? 0 : (nr > RPW ? RPW : nr);

    int jj[4];
    #pragma unroll
    for (int jt = 0; jt < 4; ++jt) {
        int j = lane + jt * 32;
        jj[jt] = (j < NT) ? j : 0;
    }
    const bool v3ok = (lane + 96) < NT;

    // masks are constant across layers/heads: hoist
    const float mj0 = sm.maskf[jj[0]];
    const float mj1 = sm.maskf[jj[1]];
    const float mj2 = sm.maskf[jj[2]];
    const float mj3 = sm.maskf[jj[3]];
    float miR[RPW];
    #pragma unroll
    for (int r = 0; r < RPW; ++r)
        miR[r] = (r < nrows) ? sm.maskf[t0 + r] : 0.0f;

    for (int l = 0; l < Ll; ++l) {
        // ---- phase A: g/u for ALL heads + featT, one barrier ----------------
        if (tid < Hh * NT) {
            const int h = tid / NT;
            const int j = tid % NT;
            float f0 = sm.feat[j][0], f1 = sm.feat[j][1], f2 = sm.feat[j][2];
            float f3 = sm.feat[j][3], f4 = sm.feat[j][4];
            const float* mq  = &sm.mqk[(l * Hh + h) * 25];
            const float* wpp = &sm.wp [(l * Hh + h) * 25];
            #pragma unroll
            for (int e = 0; e < Ed; ++e) {
                float gs = mq[e * 5 + 0] * f0;
                gs = fmaf(mq[e * 5 + 1], f1, gs);
                gs = fmaf(mq[e * 5 + 2], f2, gs);
                gs = fmaf(mq[e * 5 + 3], f3, gs);
                gs = fmaf(mq[e * 5 + 4], f4, gs);
                float us = wpp[e * 5 + 0] * f0;
                us = fmaf(wpp[e * 5 + 1], f1, us);
                us = fmaf(wpp[e * 5 + 2], f2, us);
                us = fmaf(wpp[e * 5 + 3], f3, us);
                us = fmaf(wpp[e * 5 + 4], f4, us);
                sm.g[(h * NT + j) * Ed + e] = gs;
                sm.u[(h * NT + j) * Ed + e] = us;
            }
        } else if (tid < Hh * NT + NT) {
            const int j    = tid - Hh * NT;
            const int slot = (j / RPW) * SLOTS + (j % RPW);
            #pragma unroll
            for (int e = 0; e < Ed; ++e)
                sm.featT[e][slot] = sm.feat[j][e];
        }
        __syncthreads();

        // ---- head loop: no internal barriers ------------------------------
        unsigned long long part01[RPW], part23[RPW];
        float part4[RPW];
        #pragma unroll
        for (int r = 0; r < RPW; ++r) { part01[r] = 0ULL; part23[r] = 0ULL; part4[r] = 0.0f; }

        if (nrows > 0) {
            for (int h = 0; h < Hh; ++h) {
                const float* gh = &sm.g[h * NT * Ed];
                const float* uh = &sm.u[h * NT * Ed];

                // scores: S[i][j] = featT[:, i] . g[j]   (5-wide)
                unsigned long long acc[4][4];
                #pragma unroll
                for (int jt = 0; jt < 4; ++jt)
                    #pragma unroll
                    for (int p = 0; p < 4; ++p) acc[jt][p] = 0ULL;

                #pragma unroll
                for (int e = 0; e < Ed; ++e) {
                    float4 qA = *reinterpret_cast<const float4*>(&sm.featT[e][s0]);
                    float4 qB = *reinterpret_cast<const float4*>(&sm.featT[e][s0 + 4]);
                    unsigned long long qp0 = pk2(qA.x, qA.y);
                    unsigned long long qp1 = pk2(qA.z, qA.w);
                    unsigned long long qp2 = pk2(qB.x, qB.y);
                    unsigned long long qp3 = pk2(qB.z, qB.w);
                    #pragma unroll
                    for (int jt = 0; jt < 4; ++jt) {
                        unsigned long long ks = splat2(gh[jj[jt] * Ed + e]);
                        acc[jt][0] = ffma2(qp0, ks, acc[jt][0]);
                        acc[jt][1] = ffma2(qp1, ks, acc[jt][1]);
                        acc[jt][2] = ffma2(qp2, ks, acc[jt][2]);
                        acc[jt][3] = ffma2(qp3, ks, acc[jt][3]);
                    }
                }

                // ---- softmax without max-subtraction (scores bounded) ------
                // masked row (mi==0, warp-uniform): exact uniform 1/N
                float P0[RPW], P1[RPW], P2[RPW], P3[RPW];
                #pragma unroll
                for (int r = 0; r < RPW; ++r) {
                    if (r < nrows) {
                        float lo, hi, s0v, s1v, s2v, s3v;
                        unpk2(acc[0][r >> 1], lo, hi); s0v = (r & 1) ? hi : lo;
                        unpk2(acc[1][r >> 1], lo, hi); s1v = (r & 1) ? hi : lo;
                        unpk2(acc[2][r >> 1], lo, hi); s2v = (r & 1) ? hi : lo;
                        unpk2(acc[3][r >> 1], lo, hi); s3v = (r & 1) ? hi : lo;
                        if (miR[r] > 0.5f) {
                            float p0 = (mj0 > 0.5f) ? __expf(s0v) : 0.0f;
                            float p1 = (mj1 > 0.5f) ? __expf(s1v) : 0.0f;
                            float p2 = (mj2 > 0.5f) ? __expf(s2v) : 0.0f;
                            float p3 = (v3ok && mj3 > 0.5f) ? __expf(s3v) : 0.0f;
                            float sum = (p0 + p1) + (p2 + p3);
                            #pragma unroll
                            for (int off = 16; off > 0; off >>= 1)
                                sum += __shfl_xor_sync(0xffffffffu, sum, off);
                            const float inv = __fdividef(1.0f, sum);
                            P0[r] = p0 * inv;
                            P1[r] = p1 * inv;
                            P2[r] = p2 * inv;
                            P3[r] = p3 * inv;
                        } else {
                            P0[r] = P1[r] = P2[r] = 0.01f;
                            P3[r] = v3ok ? 0.01f : 0.0f;
                        }
                    } else {
                        P0[r] = P1[r] = P2[r] = P3[r] = 0.0f;
                    }
                }

                // ---- AV' packed: part[r][:] += P[r][j] * u[j][:] ------------
                #pragma unroll
                for (int jt = 0; jt < 4; ++jt) {
                    const float* uj = &uh[jj[jt] * Ed];
                    unsigned long long u01 = pk2(uj[0], uj[1]);
                    unsigned long long u23 = pk2(uj[2], uj[3]);
                    float u4 = uj[4];
                    const float* Pj = (jt == 0) ? P0 : (jt == 1) ? P1 : (jt == 2) ? P2 : P3;
                    #pragma unroll
                    for (int r = 0; r < RPW; ++r) {
                        const float p = Pj[r];
                        unsigned long long ps = splat2(p);
                        part01[r] = ffma2(ps, u01, part01[r]);
                        part23[r] = ffma2(ps, u23, part23[r]);
                        part4[r]  = fmaf(p, u4, part4[r]);
                    }
                }
            } // heads
        }

        // ---- cross-lane reduce part (packed f32x2 butterfly), write attn ----
        for (int r = 0; r < nrows; ++r) {
            unsigned long long a01 = part01[r];
            unsigned long long a23 = part23[r];
            float a4 = part4[r];
            #pragma unroll
            for (int off = 16; off > 0; off >>= 1) {
                a01 = fadd2(a01, __shfl_xor_sync(0xffffffffu, a01, off));
                a23 = fadd2(a23, __shfl_xor_sync(0xffffffffu, a23, off));
                a4 += __shfl_xor_sync(0xffffffffu, a4, off);
            }
            if (lane == 0) {
                float s_0, s_1, s_2, s_3;
                unpk2(a01, s_0, s_1);
                unpk2(a23, s_2, s_3);
                sm.attn[t0 + r][0] = s_0;
                sm.attn[t0 + r][1] = s_1;
                sm.attn[t0 + r][2] = s_2;
                sm.attn[t0 + r][3] = s_3;
                sm.attn[t0 + r][4] = a4;
            }
        }
        __syncthreads();

        // ---------------- residual + LN1 + FFN + residual + LN2 --------------
        if (tid < NT) {
            float a[Ed], ln1[Ed], fo[Ed];
            #pragma unroll
            for (int e = 0; e < Ed; ++e) a[e] = sm.attn[tid][e] + sm.feat[tid][e];
            float mu = 0.f;
            #pragma unroll
            for (int e = 0; e < Ed; ++e) mu += a[e];
            mu *= 0.2f;
            float var = 0.f;
            #pragma unroll
            for (int e = 0; e < Ed; ++e) { float dd = a[e] - mu; var = fmaf(dd, dd, var); }
            var *= 0.2f;
            float rinv = rsqrtf(var + 1e-5f);
            #pragma unroll
            for (int e = 0; e < Ed; ++e)
                ln1[e] = (a[e] - mu) * rinv * g1[l * Ed + e] + b1[l * Ed + e];
            #pragma unroll
            for (int e = 0; e < Ed; ++e) {
                float s = bfb[l * Ed + e];
                #pragma unroll
                for (int e2 = 0; e2 < Ed; ++e2)
                    s = fmaf(Wf[((size_t)(l * Ed + e)) * Ed + e2], ln1[e2], s);
                fo[e] = fmaxf(s, 0.0f) + ln1[e];
            }
            float mu2 = 0.f;
            #pragma unroll
            for (int e = 0; e < Ed; ++e) mu2 += fo[e];
            mu2 *= 0.2f;
            float var2 = 0.f;
            #pragma unroll
            for (int e = 0; e < Ed; ++e) { float dd = fo[e] - mu2; var2 = fmaf(dd, dd, var2); }
            var2 *= 0.2f;
            float rinv2 = rsqrtf(var2 + 1e-5f);
            #pragma unroll
            for (int e = 0; e < Ed; ++e)
                sm.feat[tid][e] = (fo[e] - mu2) * rinv2 * g2[l * Ed + e] + b2[l * Ed + e];
        }
        __syncthreads();
    } // layers

    // ---------------- write output ----------------
    for (int idx = tid; idx < NT * Ed; idx += NTHREADS)
        out[(size_t)b * (NT * Ed) + idx] = (&sm.feat[0][0])[idx];
}

extern "C" void kernel_launch(void* const* d_in, const int* in_sizes, int n_in,
                              void* d_out, int out_size)
{
    const float* x   = (const float*)d_in[0];
    const float* Wq  = (const float*)d_in[1];
    const float* Wk  = (const float*)d_in[2];
    const float* Wv  = (const float*)d_in[3];
    const float* Wo  = (const float*)d_in[4];
    const float* Wf  = (const float*)d_in[5];
    const float* bfb = (const float*)d_in[6];
    const float* g1  = (const float*)d_in[7];
    const float* b1  = (const float*)d_in[8];
    const float* g2  = (const float*)d_in[9];
    const float* b2  = (const float*)d_in[10];
    float* out = (float*)d_out;

    fold_kernel<<<1, 320>>>(Wq, Wk, Wv, Wo);
    encoder_kernel<<<Bb, NTHREADS>>>(x, Wf, bfb, g1, b1, g2, b2, out);
}

// round 10
// speedup vs baseline: 15.4073x; 1.6439x over previous
#include <cuda_runtime.h>
#include <math.h>
#include <float.h>

#define Bb      1024
#define NW      300
#define NT      100      // tokens
#define Ed      5        // embed dim
#define Hh      4        // heads
#define Dd      64       // head dim
#define Ll      3        // layers
#define NTHREADS 512
#define NPAIR   50       // j-pairs

// folded 5x5 matrices per (layer, head):
//   Mqk = (1/sqrt(D)) * log2(e) * Wq_h^T * Wk_h   (score form, ex2-ready)
//   Wp  = Wo_h * Wv_h                             (value+output fold)
__device__ float Mqk_g[Ll * Hh * Ed * Ed];
__device__ float Wp_g [Ll * Hh * Ed * Ed];

struct SMem {
    float  feat[NT][Ed];          // 2000 B
    float  maskf[NT];             // 400
    float  mqk[Ll * Hh * Ed * Ed];// 1200
    float  wp [Ll * Hh * Ed * Ed];// 1200
    float4 gA[Hh][NPAIR];         // (g0_lo,g0_hi,g1_lo,g1_hi)  3200
    float4 gB[Hh][NPAIR];         // (g2_lo,g2_hi,g3_lo,g3_hi)  3200
    float4 gC[Hh][NPAIR];         // (g4_lo,g4_hi,m_lo,m_hi)    3200
    float4 uA[Hh][NT];            // u[0..3]                    6400
    float2 uB[Hh][NT];            // (u4, mask_j)               3200
    float4 partA[Hh][NT];         // head partial out[0..3]     6400
    float  partB[Hh][NT];         // head partial out[4]        1600
};                                // ~32 KB -> 2 CTAs/SM fits

// ---- packed f32x2 helpers ----
__device__ __forceinline__ unsigned long long pk2(float lo, float hi) {
    unsigned long long r;
    asm("mov.b64 %0, {%1, %2};" : "=l"(r) : "f"(lo), "f"(hi));
    return r;
}
__device__ __forceinline__ unsigned long long splat2(float v) {
    unsigned long long r;
    asm("mov.b64 %0, {%1, %1};" : "=l"(r) : "f"(v));
    return r;
}
__device__ __forceinline__ void unpk2(unsigned long long p, float& lo, float& hi) {
    asm("mov.b64 {%0, %1}, %2;" : "=f"(lo), "=f"(hi) : "l"(p));
}
__device__ __forceinline__ unsigned long long ffma2(unsigned long long a,
                                                    unsigned long long b,
                                                    unsigned long long c) {
    unsigned long long d;
    asm("fma.rn.f32x2 %0, %1, %2, %3;" : "=l"(d) : "l"(a), "l"(b), "l"(c));
    return d;
}
__device__ __forceinline__ float ex2f(float x) {
    float r;
    asm("ex2.approx.f32 %0, %1;" : "=f"(r) : "f"(x));
    return r;
}

// ---- pre-pass: fold the 64-dim head space into 5x5 matrices ----
__global__ void fold_kernel(const float* __restrict__ Wq,
                            const float* __restrict__ Wk,
                            const float* __restrict__ Wv,
                            const float* __restrict__ Wo)
{
    int idx = threadIdx.x;                 // 0 .. 299
    if (idx < Ll * Hh * Ed * Ed) {
        int l   = idx / (Hh * Ed * Ed);
        int rem = idx % (Hh * Ed * Ed);
        int h   = rem / (Ed * Ed);
        int e1  = (rem / Ed) % Ed;
        int e2  = rem % Ed;
        float sq = 0.0f, sp = 0.0f;
        for (int d = 0; d < Dd; ++d) {
            sq = fmaf(Wq[((size_t)((l * Hh + h) * Dd + d)) * Ed + e1],
                      Wk[((size_t)((l * Hh + h) * Dd + d)) * Ed + e2], sq);
            sp = fmaf(Wo[((size_t)(l * Ed + e1)) * (Hh * Dd) + h * Dd + d],
                      Wv[((size_t)((l * Hh + h) * Dd + d)) * Ed + e2], sp);
        }
        Mqk_g[idx] = sq * 0.125f * 1.4426950408889634f;  // scale + log2(e)
        Wp_g[idx]  = sp;
    }
}

__global__ __launch_bounds__(NTHREADS, 2)
void encoder_kernel(const float* __restrict__ x,
                    const float* __restrict__ Wf, const float* __restrict__ bfb,
                    const float* __restrict__ g1, const float* __restrict__ b1,
                    const float* __restrict__ g2, const float* __restrict__ b2,
                    float* __restrict__ out)
{
    __shared__ SMem sm;

    const int b   = blockIdx.x;
    const int tid = threadIdx.x;

    // ---------------- embedding + mask + stage folded weights ----------------
    if (tid < NT) {
        float k0 = x[b * NW + tid * 3 + 0];
        float k1 = x[b * NW + tid * 3 + 1];
        float k2 = x[b * NW + tid * 3 + 2];
        bool  m  = k2 > 0.0f;
        float sn, cs;
        sincosf((float)tid, &sn, &cs);
        sm.maskf[tid]   = m ? 1.0f : 0.0f;
        sm.feat[tid][0] = m ? k0 : 0.0f;
        sm.feat[tid][1] = m ? k1 : 0.0f;
        sm.feat[tid][2] = m ? k2 : 0.0f;
        sm.feat[tid][3] = m ? sn : 0.0f;
        sm.feat[tid][4] = m ? cs : 0.0f;
    }
    if (tid < Ll * Hh * Ed * Ed) {
        sm.mqk[tid] = Mqk_g[tid];
        sm.wp[tid]  = Wp_g[tid];
    }
    __syncthreads();

    // thread -> (head, row) assignment for the mainloop
    const int hmy = tid >> 7;              // 0..3
    const int i   = tid & 127;             // 0..127 (rows >= NT idle)
    const int ii  = (i < NT) ? i : 0;
    const bool mi_on = sm.maskf[ii] > 0.5f;

    #pragma unroll 1
    for (int l = 0; l < Ll; ++l) {
        // ---- phase A: g (pair-interleaved) + u for all heads ----------------
        if (tid < Hh * NT) {
            const int h = tid / NT;
            const int j = tid % NT;
            float f0 = sm.feat[j][0], f1 = sm.feat[j][1], f2 = sm.feat[j][2];
            float f3 = sm.feat[j][3], f4 = sm.feat[j][4];
            const float* mq  = &sm.mqk[(l * Hh + h) * 25];
            const float* wpp = &sm.wp [(l * Hh + h) * 25];
            float gg[Ed], uu[Ed];
            #pragma unroll
            for (int e = 0; e < Ed; ++e) {
                float gs = mq[e * 5 + 0] * f0;
                gs = fmaf(mq[e * 5 + 1], f1, gs);
                gs = fmaf(mq[e * 5 + 2], f2, gs);
                gs = fmaf(mq[e * 5 + 3], f3, gs);
                gs = fmaf(mq[e * 5 + 4], f4, gs);
                gg[e] = gs;
                float us = wpp[e * 5 + 0] * f0;
                us = fmaf(wpp[e * 5 + 1], f1, us);
                us = fmaf(wpp[e * 5 + 2], f2, us);
                us = fmaf(wpp[e * 5 + 3], f3, us);
                us = fmaf(wpp[e * 5 + 4], f4, us);
                uu[e] = us;
            }
            const int   jp = j >> 1;
            const int   lh = j & 1;
            const float mj = sm.maskf[j];
            float* pA = reinterpret_cast<float*>(&sm.gA[h][jp]);
            pA[lh]     = gg[0];
            pA[2 + lh] = gg[1];
            float* pB = reinterpret_cast<float*>(&sm.gB[h][jp]);
            pB[lh]     = gg[2];
            pB[2 + lh] = gg[3];
            float* pC = reinterpret_cast<float*>(&sm.gC[h][jp]);
            pC[lh]     = gg[4];
            pC[2 + lh] = mj;
            sm.uA[h][j] = make_float4(uu[0], uu[1], uu[2], uu[3]);
            sm.uB[h][j] = make_float2(uu[4], mj);
        }
        __syncthreads();

        // ---- mainloop: thread-local softmax + AV over j, zero shuffles ------
        {
            const unsigned long long fs0 = splat2(sm.feat[ii][0]);
            const unsigned long long fs1 = splat2(sm.feat[ii][1]);
            const unsigned long long fs2 = splat2(sm.feat[ii][2]);
            const unsigned long long fs3 = splat2(sm.feat[ii][3]);
            const unsigned long long fs4 = splat2(sm.feat[ii][4]);
            unsigned long long a01 = 0ULL, a23 = 0ULL, a4Z = 0ULL;
            const float4* gAh = sm.gA[hmy];
            const float4* gBh = sm.gB[hmy];
            const float4* gCh = sm.gC[hmy];
            const float4* uAh = sm.uA[hmy];
            const float2* uBh = sm.uB[hmy];

            #pragma unroll 10
            for (int j2 = 0; j2 < NPAIR; ++j2) {
                float4 A = gAh[j2];
                float4 Bq = gBh[j2];
                float4 C = gCh[j2];
                unsigned long long s =
                    ffma2(fs0, pk2(A.x, A.y),
                    ffma2(fs1, pk2(A.z, A.w),
                    ffma2(fs2, pk2(Bq.x, Bq.y),
                    ffma2(fs3, pk2(Bq.z, Bq.w),
                    ffma2(fs4, pk2(C.x, C.y), 0ULL)))));
                float s0, s1;
                unpk2(s, s0, s1);
                float p0 = ex2f(s0) * C.z;
                float p1 = ex2f(s1) * C.w;
                p0 = mi_on ? p0 : 1.0f;
                p1 = mi_on ? p1 : 1.0f;

                float4 U0 = uAh[2 * j2];
                float2 V0 = uBh[2 * j2];
                unsigned long long ps0 = splat2(p0);
                a01 = ffma2(ps0, pk2(U0.x, U0.y), a01);
                a23 = ffma2(ps0, pk2(U0.z, U0.w), a23);
                a4Z = ffma2(ps0, pk2(V0.x, V0.y), a4Z);

                float4 U1 = uAh[2 * j2 + 1];
                float2 V1 = uBh[2 * j2 + 1];
                unsigned long long ps1 = splat2(p1);
                a01 = ffma2(ps1, pk2(U1.x, U1.y), a01);
                a23 = ffma2(ps1, pk2(U1.z, U1.w), a23);
                a4Z = ffma2(ps1, pk2(V1.x, V1.y), a4Z);
            }

            if (i < NT) {
                float o0, o1, o2, o3, o4, Z;
                unpk2(a01, o0, o1);
                unpk2(a23, o2, o3);
                unpk2(a4Z, o4, Z);
                const float inv = mi_on ? __fdividef(1.0f, Z) : 0.01f;
                sm.partA[hmy][i] = make_float4(o0 * inv, o1 * inv, o2 * inv, o3 * inv);
                sm.partB[hmy][i] = o4 * inv;
            }
        }
        __syncthreads();

        // ---- merged epilogue: head-sum + residual + LN1 + FFN + LN2 ---------
        if (tid < NT) {
            float a[Ed];
            #pragma unroll
            for (int e = 0; e < Ed; ++e) a[e] = sm.feat[tid][e];
            #pragma unroll
            for (int h = 0; h < Hh; ++h) {
                float4 pa = sm.partA[h][tid];
                a[0] += pa.x; a[1] += pa.y; a[2] += pa.z; a[3] += pa.w;
                a[4] += sm.partB[h][tid];
            }
            float mu = 0.f;
            #pragma unroll
            for (int e = 0; e < Ed; ++e) mu += a[e];
            mu *= 0.2f;
            float var = 0.f;
            #pragma unroll
            for (int e = 0; e < Ed; ++e) { float dd = a[e] - mu; var = fmaf(dd, dd, var); }
            var *= 0.2f;
            float rinv = rsqrtf(var + 1e-5f);
            float ln1[Ed], fo[Ed];
            #pragma unroll
            for (int e = 0; e < Ed; ++e)
                ln1[e] = (a[e] - mu) * rinv * g1[l * Ed + e] + b1[l * Ed + e];
            #pragma unroll
            for (int e = 0; e < Ed; ++e) {
                float s = bfb[l * Ed + e];
                #pragma unroll
                for (int e2 = 0; e2 < Ed; ++e2)
                    s = fmaf(Wf[((size_t)(l * Ed + e)) * Ed + e2], ln1[e2], s);
                fo[e] = fmaxf(s, 0.0f) + ln1[e];
            }
            float mu2 = 0.f;
            #pragma unroll
            for (int e = 0; e < Ed; ++e) mu2 += fo[e];
            mu2 *= 0.2f;
            float var2 = 0.f;
            #pragma unroll
            for (int e = 0; e < Ed; ++e) { float dd = fo[e] - mu2; var2 = fmaf(dd, dd, var2); }
            var2 *= 0.2f;
            float rinv2 = rsqrtf(var2 + 1e-5f);
            #pragma unroll
            for (int e = 0; e < Ed; ++e)
                sm.feat[tid][e] = (fo[e] - mu2) * rinv2 * g2[l * Ed + e] + b2[l * Ed + e];
        }
        __syncthreads();
    } // layers

    // ---------------- write output ----------------
    for (int idx = tid; idx < NT * Ed; idx += NTHREADS)
        out[(size_t)b * (NT * Ed) + idx] = (&sm.feat[0][0])[idx];
}

extern "C" void kernel_launch(void* const* d_in, const int* in_sizes, int n_in,
                              void* d_out, int out_size)
{
    const float* x   = (const float*)d_in[0];
    const float* Wq  = (const float*)d_in[1];
    const float* Wk  = (const float*)d_in[2];
    const float* Wv  = (const float*)d_in[3];
    const float* Wo  = (const float*)d_in[4];
    const float* Wf  = (const float*)d_in[5];
    const float* bfb = (const float*)d_in[6];
    const float* g1  = (const float*)d_in[7];
    const float* b1  = (const float*)d_in[8];
    const float* g2  = (const float*)d_in[9];
    const float* b2  = (const float*)d_in[10];
    float* out = (float*)d_out;

    fold_kernel<<<1, 320>>>(Wq, Wk, Wv, Wo);
    encoder_kernel<<<Bb, NTHREADS>>>(x, Wf, bfb, g1, b1, g2, b2, out);
}

// round 11
// speedup vs baseline: 18.1219x; 1.1762x over previous
#include <cuda_runtime.h>
#include <math.h>
#include <float.h>

#define Bb      1024
#define NW      300
#define NT      100      // tokens
#define Ed      5        // embed dim
#define Hh      4        // heads
#define Dd      64       // head dim
#define Ll      3        // layers
#define NTHREADS 512
#define NPAIR   50       // j-pairs

// folded 5x5 matrices per (layer, head):
//   Mqk = (1/sqrt(D)) * log2(e) * Wq_h^T * Wk_h   (score form, ex2-ready)
//   Wp  = Wo_h * Wv_h                             (value+output fold)
__device__ float Mqk_g[Ll * Hh * Ed * Ed];
__device__ float Wp_g [Ll * Hh * Ed * Ed];

struct SMem {
    float  feat[NT][Ed];          // 2000 B (linear copy: gq build, epilogue, out)
    float  maskf[NT];             // 400
    float  mqk[Ll * Hh * Ed * Ed];// 1200
    float  wp [Ll * Hh * Ed * Ed];// 1200
    float4 fA[NPAIR];             // (f0_lo,f0_hi,f1_lo,f1_hi)   800
    float4 fB[NPAIR];             // (f2_lo,f2_hi,f3_lo,f3_hi)   800
    float4 fC[NPAIR];             // (f4_lo,f4_hi,m_lo,m_hi)     800
    float4 partA[Hh][NT];         // head partial out[0..3]     6400
    float  partB[Hh][NT];         // head partial out[4]        1600
};                                // ~15.2 KB

// ---- packed f32x2 helpers ----
__device__ __forceinline__ unsigned long long pk2(float lo, float hi) {
    unsigned long long r;
    asm("mov.b64 %0, {%1, %2};" : "=l"(r) : "f"(lo), "f"(hi));
    return r;
}
__device__ __forceinline__ unsigned long long splat2(float v) {
    unsigned long long r;
    asm("mov.b64 %0, {%1, %1};" : "=l"(r) : "f"(v));
    return r;
}
__device__ __forceinline__ void unpk2(unsigned long long p, float& lo, float& hi) {
    asm("mov.b64 {%0, %1}, %2;" : "=f"(lo), "=f"(hi) : "l"(p));
}
__device__ __forceinline__ unsigned long long ffma2(unsigned long long a,
                                                    unsigned long long b,
                                                    unsigned long long c) {
    unsigned long long d;
    asm("fma.rn.f32x2 %0, %1, %2, %3;" : "=l"(d) : "l"(a), "l"(b), "l"(c));
    return d;
}
__device__ __forceinline__ unsigned long long fadd2(unsigned long long a,
                                                    unsigned long long b) {
    unsigned long long d;
    asm("add.rn.f32x2 %0, %1, %2;" : "=l"(d) : "l"(a), "l"(b));
    return d;
}
__device__ __forceinline__ float ex2f(float x) {
    float r;
    asm("ex2.approx.f32 %0, %1;" : "=f"(r) : "f"(x));
    return r;
}

// ---- pre-pass: fold the 64-dim head space into 5x5 matrices ----
__global__ void fold_kernel(const float* __restrict__ Wq,
                            const float* __restrict__ Wk,
                            const float* __restrict__ Wv,
                            const float* __restrict__ Wo)
{
    int idx = threadIdx.x;                 // 0 .. 299
    if (idx < Ll * Hh * Ed * Ed) {
        int l   = idx / (Hh * Ed * Ed);
        int rem = idx % (Hh * Ed * Ed);
        int h   = rem / (Ed * Ed);
        int e1  = (rem / Ed) % Ed;
        int e2  = rem % Ed;
        float sq = 0.0f, sp = 0.0f;
        for (int d = 0; d < Dd; ++d) {
            sq = fmaf(Wq[((size_t)((l * Hh + h) * Dd + d)) * Ed + e1],
                      Wk[((size_t)((l * Hh + h) * Dd + d)) * Ed + e2], sq);
            sp = fmaf(Wo[((size_t)(l * Ed + e1)) * (Hh * Dd) + h * Dd + d],
                      Wv[((size_t)((l * Hh + h) * Dd + d)) * Ed + e2], sp);
        }
        Mqk_g[idx] = sq * 0.125f * 1.4426950408889634f;  // scale + log2(e)
        Wp_g[idx]  = sp;
    }
}

__global__ __launch_bounds__(NTHREADS, 2)
void encoder_kernel(const float* __restrict__ x,
                    const float* __restrict__ Wf, const float* __restrict__ bfb,
                    const float* __restrict__ g1, const float* __restrict__ b1,
                    const float* __restrict__ g2, const float* __restrict__ b2,
                    float* __restrict__ out)
{
    __shared__ SMem sm;

    const int b   = blockIdx.x;
    const int tid = threadIdx.x;

    // ------------- embedding + mask + packed feat + staged weights -----------
    if (tid < NT) {
        float k0 = x[b * NW + tid * 3 + 0];
        float k1 = x[b * NW + tid * 3 + 1];
        float k2 = x[b * NW + tid * 3 + 2];
        bool  m  = k2 > 0.0f;
        float sn, cs;
        sincosf((float)tid, &sn, &cs);
        float f0 = m ? k0 : 0.0f, f1 = m ? k1 : 0.0f, f2 = m ? k2 : 0.0f;
        float f3 = m ? sn : 0.0f, f4 = m ? cs : 0.0f;
        sm.maskf[tid]   = m ? 1.0f : 0.0f;
        sm.feat[tid][0] = f0;
        sm.feat[tid][1] = f1;
        sm.feat[tid][2] = f2;
        sm.feat[tid][3] = f3;
        sm.feat[tid][4] = f4;
        const int jp = tid >> 1, lh = tid & 1;
        float* pA = reinterpret_cast<float*>(&sm.fA[jp]);
        pA[lh] = f0;  pA[2 + lh] = f1;
        float* pB = reinterpret_cast<float*>(&sm.fB[jp]);
        pB[lh] = f2;  pB[2 + lh] = f3;
        float* pC = reinterpret_cast<float*>(&sm.fC[jp]);
        pC[lh] = f4;  pC[2 + lh] = m ? 1.0f : 0.0f;   // mask written ONCE
    }
    if (tid < Ll * Hh * Ed * Ed) {
        sm.mqk[tid] = Mqk_g[tid];
        sm.wp[tid]  = Wp_g[tid];
    }
    __syncthreads();

    // thread -> (head, row) assignment
    const int hmy = tid >> 7;              // 0..3
    const int i   = tid & 127;             // 0..127 (rows >= NT idle)
    const int ii  = (i < NT) ? i : 0;
    const bool mi_on = sm.maskf[ii] > 0.5f;

    #pragma unroll 1
    for (int l = 0; l < Ll; ++l) {
        // ---- mainloop: gq once, then stream packed feat only ----------------
        {
            // gq = Mqk^T . feat_i  (per-thread, per-layer)
            const float* mq = &sm.mqk[(l * Hh + hmy) * 25];
            const float fi0 = sm.feat[ii][0], fi1 = sm.feat[ii][1];
            const float fi2 = sm.feat[ii][2], fi3 = sm.feat[ii][3];
            const float fi4 = sm.feat[ii][4];
            unsigned long long gqs[Ed];
            #pragma unroll
            for (int e2 = 0; e2 < Ed; ++e2) {
                float v = mq[0 * 5 + e2] * fi0;
                v = fmaf(mq[1 * 5 + e2], fi1, v);
                v = fmaf(mq[2 * 5 + e2], fi2, v);
                v = fmaf(mq[3 * 5 + e2], fi3, v);
                v = fmaf(mq[4 * 5 + e2], fi4, v);
                gqs[e2] = splat2(v);
            }

            unsigned long long a0 = 0ULL, a1 = 0ULL, a2 = 0ULL,
                               a3 = 0ULL, a4 = 0ULL, zz = 0ULL;
            #pragma unroll 10
            for (int j2 = 0; j2 < NPAIR; ++j2) {
                float4 A = sm.fA[j2];
                float4 Bq = sm.fB[j2];
                float4 C = sm.fC[j2];
                unsigned long long pA01 = pk2(A.x, A.y);
                unsigned long long pA23 = pk2(A.z, A.w);
                unsigned long long pB01 = pk2(Bq.x, Bq.y);
                unsigned long long pB23 = pk2(Bq.z, Bq.w);
                unsigned long long pC01 = pk2(C.x, C.y);
                unsigned long long s =
                    ffma2(gqs[0], pA01,
                    ffma2(gqs[1], pA23,
                    ffma2(gqs[2], pB01,
                    ffma2(gqs[3], pB23,
                    ffma2(gqs[4], pC01, 0ULL)))));
                float s0, s1;
                unpk2(s, s0, s1);
                float p0 = ex2f(s0) * C.z;
                float p1 = ex2f(s1) * C.w;
                p0 = mi_on ? p0 : 1.0f;
                p1 = mi_on ? p1 : 1.0f;
                unsigned long long pp = pk2(p0, p1);
                a0 = ffma2(pp, pA01, a0);
                a1 = ffma2(pp, pA23, a1);
                a2 = ffma2(pp, pB01, a2);
                a3 = ffma2(pp, pB23, a3);
                a4 = ffma2(pp, pC01, a4);
                zz = fadd2(zz, pp);
            }

            if (i < NT) {
                float lo, hi, af0, af1, af2, af3, af4, Z;
                unpk2(a0, lo, hi); af0 = lo + hi;
                unpk2(a1, lo, hi); af1 = lo + hi;
                unpk2(a2, lo, hi); af2 = lo + hi;
                unpk2(a3, lo, hi); af3 = lo + hi;
                unpk2(a4, lo, hi); af4 = lo + hi;
                unpk2(zz, lo, hi); Z   = lo + hi;
                const float inv = mi_on ? __fdividef(1.0f, Z) : 0.01f;
                const float* wpp = &sm.wp[(l * Hh + hmy) * 25];
                float o[Ed];
                #pragma unroll
                for (int e = 0; e < Ed; ++e) {
                    float s = wpp[e * 5 + 0] * af0;
                    s = fmaf(wpp[e * 5 + 1], af1, s);
                    s = fmaf(wpp[e * 5 + 2], af2, s);
                    s = fmaf(wpp[e * 5 + 3], af3, s);
                    s = fmaf(wpp[e * 5 + 4], af4, s);
                    o[e] = s * inv;
                }
                sm.partA[hmy][i] = make_float4(o[0], o[1], o[2], o[3]);
                sm.partB[hmy][i] = o[4];
            }
        }
        __syncthreads();

        // ---- merged epilogue: head-sum + residual + LN1 + FFN + LN2 ---------
        if (tid < NT) {
            float a[Ed];
            #pragma unroll
            for (int e = 0; e < Ed; ++e) a[e] = sm.feat[tid][e];
            #pragma unroll
            for (int h = 0; h < Hh; ++h) {
                float4 pa = sm.partA[h][tid];
                a[0] += pa.x; a[1] += pa.y; a[2] += pa.z; a[3] += pa.w;
                a[4] += sm.partB[h][tid];
            }
            float mu = 0.f;
            #pragma unroll
            for (int e = 0; e < Ed; ++e) mu += a[e];
            mu *= 0.2f;
            float var = 0.f;
            #pragma unroll
            for (int e = 0; e < Ed; ++e) { float dd = a[e] - mu; var = fmaf(dd, dd, var); }
            var *= 0.2f;
            float rinv = rsqrtf(var + 1e-5f);
            float ln1[Ed], fo[Ed];
            #pragma unroll
            for (int e = 0; e < Ed; ++e)
                ln1[e] = (a[e] - mu) * rinv * g1[l * Ed + e] + b1[l * Ed + e];
            #pragma unroll
            for (int e = 0; e < Ed; ++e) {
                float s = bfb[l * Ed + e];
                #pragma unroll
                for (int e2 = 0; e2 < Ed; ++e2)
                    s = fmaf(Wf[((size_t)(l * Ed + e)) * Ed + e2], ln1[e2], s);
                fo[e] = fmaxf(s, 0.0f) + ln1[e];
            }
            float mu2 = 0.f;
            #pragma unroll
            for (int e = 0; e < Ed; ++e) mu2 += fo[e];
            mu2 *= 0.2f;
            float var2 = 0.f;
            #pragma unroll
            for (int e = 0; e < Ed; ++e) { float dd = fo[e] - mu2; var2 = fmaf(dd, dd, var2); }
            var2 *= 0.2f;
            float rinv2 = rsqrtf(var2 + 1e-5f);
            float nf[Ed];
            #pragma unroll
            for (int e = 0; e < Ed; ++e) {
                nf[e] = (fo[e] - mu2) * rinv2 * g2[l * Ed + e] + b2[l * Ed + e];
                sm.feat[tid][e] = nf[e];
            }
            // refresh packed feat for next layer's mainloop
            const int jp = tid >> 1, lh = tid & 1;
            float* pA = reinterpret_cast<float*>(&sm.fA[jp]);
            pA[lh] = nf[0];  pA[2 + lh] = nf[1];
            float* pB = reinterpret_cast<float*>(&sm.fB[jp]);
            pB[lh] = nf[2];  pB[2 + lh] = nf[3];
            float* pC = reinterpret_cast<float*>(&sm.fC[jp]);
            pC[lh] = nf[4];                      // mask halves untouched
        }
        __syncthreads();
    } // layers

    // ---------------- write output ----------------
    for (int idx = tid; idx < NT * Ed; idx += NTHREADS)
        out[(size_t)b * (NT * Ed) + idx] = (&sm.feat[0][0])[idx];
}

extern "C" void kernel_launch(void* const* d_in, const int* in_sizes, int n_in,
                              void* d_out, int out_size)
{
    const float* x   = (const float*)d_in[0];
    const float* Wq  = (const float*)d_in[1];
    const float* Wk  = (const float*)d_in[2];
    const float* Wv  = (const float*)d_in[3];
    const float* Wo  = (const float*)d_in[4];
    const float* Wf  = (const float*)d_in[5];
    const float* bfb = (const float*)d_in[6];
    const float* g1  = (const float*)d_in[7];
    const float* b1  = (const float*)d_in[8];
    const float* g2  = (const float*)d_in[9];
    const float* b2  = (const float*)d_in[10];
    float* out = (float*)d_out;

    fold_kernel<<<1, 320>>>(Wq, Wk, Wv, Wo);
    encoder_kernel<<<Bb, NTHREADS>>>(x, Wf, bfb, g1, b1, g2, b2, out);
}

// round 13
// speedup vs baseline: 20.8036x; 1.1480x over previous
#include <cuda_runtime.h>
#include <math.h>
#include <float.h>

#define Bb      1024
#define NW      300
#define NT      100      // tokens
#define Ed      5        // embed dim
#define Hh      4        // heads
#define Dd      64       // head dim
#define Ll      3        // layers
#define NTHREADS 512
#define NPAIR   50       // max j-pairs (compacted)

struct SMem {
    float  feat[NT][Ed];          // linear feat (gq build, epilogue, output)
    float  maskf[NT];
    int    cslot[NT];             // compact slot per valid token
    unsigned int bal[4];          // mask ballots
    int    np2;                   // number of compacted j-pairs
    float  fsum[Ed];              // sum of feat over ALL tokens (per layer)
    float  mqk[Ll * Hh * Ed * Ed];// folded score matrices (ex2-ready)
    float  wp [Ll * Hh * Ed * Ed];// folded value+output matrices
    float4 fA[NPAIR];             // compacted (f0_lo,f0_hi,f1_lo,f1_hi)
    float4 fB[NPAIR];             // compacted (f2_lo,f2_hi,f3_lo,f3_hi)
    float4 fC[NPAIR];             // compacted (f4_lo,f4_hi,m_lo,m_hi)
    float4 partA[Hh][NT];         // head partial out[0..3]
    float  partB[Hh][NT];         // head partial out[4]
};

// ---- packed f32x2 helpers ----
__device__ __forceinline__ unsigned long long pk2(float lo, float hi) {
    unsigned long long r;
    asm("mov.b64 %0, {%1, %2};" : "=l"(r) : "f"(lo), "f"(hi));
    return r;
}
__device__ __forceinline__ unsigned long long splat2(float v) {
    unsigned long long r;
    asm("mov.b64 %0, {%1, %1};" : "=l"(r) : "f"(v));
    return r;
}
__device__ __forceinline__ void unpk2(unsigned long long p, float& lo, float& hi) {
    asm("mov.b64 {%0, %1}, %2;" : "=f"(lo), "=f"(hi) : "l"(p));
}
__device__ __forceinline__ unsigned long long ffma2(unsigned long long a,
                                                    unsigned long long b,
                                                    unsigned long long c) {
    unsigned long long d;
    asm("fma.rn.f32x2 %0, %1, %2, %3;" : "=l"(d) : "l"(a), "l"(b), "l"(c));
    return d;
}
__device__ __forceinline__ unsigned long long fadd2(unsigned long long a,
                                                    unsigned long long b) {
    unsigned long long d;
    asm("add.rn.f32x2 %0, %1, %2;" : "=l"(d) : "l"(a), "l"(b));
    return d;
}
__device__ __forceinline__ float ex2f(float x) {
    float r;
    asm("ex2.approx.f32 %0, %1;" : "=f"(r) : "f"(x));
    return r;
}

__global__ __launch_bounds__(NTHREADS, 2)
void encoder_kernel(const float* __restrict__ x,
                    const float* __restrict__ Wq, const float* __restrict__ Wk,
                    const float* __restrict__ Wv, const float* __restrict__ Wo,
                    const float* __restrict__ Wf, const float* __restrict__ bfb,
                    const float* __restrict__ g1, const float* __restrict__ b1,
                    const float* __restrict__ g2, const float* __restrict__ b2,
                    float* __restrict__ out)
{
    __shared__ SMem sm;

    const int b   = blockIdx.x;
    const int tid = threadIdx.x;

    // ---------------- init: embedding + inline fold + zero packed ------------
    bool  mym = false;
    float f0 = 0.f, f1 = 0.f, f2 = 0.f, f3 = 0.f, f4 = 0.f;
    if (tid < NT) {
        float k0 = x[b * NW + tid * 3 + 0];
        float k1 = x[b * NW + tid * 3 + 1];
        float k2 = x[b * NW + tid * 3 + 2];
        mym = k2 > 0.0f;
        float sn, cs;
        sincosf((float)tid, &sn, &cs);
        f0 = mym ? k0 : 0.0f; f1 = mym ? k1 : 0.0f; f2 = mym ? k2 : 0.0f;
        f3 = mym ? sn : 0.0f; f4 = mym ? cs : 0.0f;
        sm.maskf[tid]   = mym ? 1.0f : 0.0f;
        sm.feat[tid][0] = f0;
        sm.feat[tid][1] = f1;
        sm.feat[tid][2] = f2;
        sm.feat[tid][3] = f3;
        sm.feat[tid][4] = f4;
    }
    // inline fold: Mqk = scale*log2e*Wq^T Wk, Wp = Wo Wv  (300 threads)
    if (tid < Ll * Hh * Ed * Ed) {
        const int l   = tid / (Hh * Ed * Ed);
        const int rem = tid % (Hh * Ed * Ed);
        const int h   = rem / (Ed * Ed);
        const int e1  = (rem / Ed) % Ed;
        const int e2  = rem % Ed;
        const float* wqp = Wq + ((size_t)((l * Hh + h) * Dd)) * Ed + e1;
        const float* wkp = Wk + ((size_t)((l * Hh + h) * Dd)) * Ed + e2;
        const float* wvp = Wv + ((size_t)((l * Hh + h) * Dd)) * Ed + e2;
        const float* wop = Wo + ((size_t)(l * Ed + e1)) * (Hh * Dd) + h * Dd;
        float sq = 0.0f, sp = 0.0f;
        #pragma unroll 8
        for (int d = 0; d < Dd; ++d) {
            sq = fmaf(wqp[d * Ed], wkp[d * Ed], sq);
            sp = fmaf(wop[d],      wvp[d * Ed], sp);
        }
        sm.mqk[tid] = sq * (0.125f * 1.4426950408889634f);
        sm.wp[tid]  = sp;
    }
    // zero compacted arrays (pads must be exactly 0)
    if (tid < 3 * NPAIR) {
        float4 z = make_float4(0.f, 0.f, 0.f, 0.f);
        if (tid < NPAIR)          sm.fA[tid] = z;
        else if (tid < 2 * NPAIR) sm.fB[tid - NPAIR] = z;
        else                      sm.fC[tid - 2 * NPAIR] = z;
    }
    // mask ballots (warps 0..3)
    if (tid < 128) {
        unsigned bm = __ballot_sync(0xffffffffu, mym);
        if ((tid & 31) == 0) sm.bal[tid >> 5] = bm;
    }
    __syncthreads();

    // compact slots + packed writes
    if (tid == 0) {
        int nv = __popc(sm.bal[0]) + __popc(sm.bal[1]) +
                 __popc(sm.bal[2]) + __popc(sm.bal[3]);
        sm.np2 = (nv + 1) >> 1;
    }
    if (tid < NT && mym) {
        unsigned bm = sm.bal[tid >> 5];
        int rank = __popc(bm & ((1u << (tid & 31)) - 1u));
        #pragma unroll
        for (int ww = 0; ww < 3; ++ww)
            if (ww < (tid >> 5)) rank += __popc(sm.bal[ww]);
        sm.cslot[tid] = rank;
        const int jp = rank >> 1, lh = rank & 1;
        float* pA = reinterpret_cast<float*>(&sm.fA[jp]);
        pA[lh] = f0;  pA[2 + lh] = f1;
        float* pB = reinterpret_cast<float*>(&sm.fB[jp]);
        pB[lh] = f2;  pB[2 + lh] = f3;
        float* pC = reinterpret_cast<float*>(&sm.fC[jp]);
        pC[lh] = f4;  pC[2 + lh] = 1.0f;       // valid marker (pad stays 0)
    }
    __syncthreads();

    // thread -> (head, row) assignment
    const int hmy = tid >> 7;              // 0..3
    const int i   = tid & 127;             // 0..127 (rows >= NT idle)
    const int ii  = (i < NT) ? i : 0;
    const bool mi_on = sm.maskf[ii] > 0.5f;
    const int np2 = sm.np2;

    #pragma unroll 1
    for (int l = 0; l < Ll; ++l) {
        // ---- phase 0: gq per thread; fsum (all-token feat sum) by idles -----
        const float* mq = &sm.mqk[(l * Hh + hmy) * 25];
        const float fi0 = sm.feat[ii][0], fi1 = sm.feat[ii][1];
        const float fi2 = sm.feat[ii][2], fi3 = sm.feat[ii][3];
        const float fi4 = sm.feat[ii][4];
        unsigned long long gqs[Ed];
        #pragma unroll
        for (int e2 = 0; e2 < Ed; ++e2) {
            float v = mq[0 * 5 + e2] * fi0;
            v = fmaf(mq[1 * 5 + e2], fi1, v);
            v = fmaf(mq[2 * 5 + e2], fi2, v);
            v = fmaf(mq[3 * 5 + e2], fi3, v);
            v = fmaf(mq[4 * 5 + e2], fi4, v);
            gqs[e2] = splat2(v);
        }
        if (tid >= NT && tid < NT + Ed) {       // rows >= NT are idle: use 5
            const int e = tid - NT;
            float s0 = 0.f, s1 = 0.f, s2 = 0.f, s3 = 0.f;
            #pragma unroll 5
            for (int j = 0; j < NT; j += 4) {
                s0 += sm.feat[j + 0][e];
                s1 += sm.feat[j + 1][e];
                s2 += sm.feat[j + 2][e];
                s3 += sm.feat[j + 3][e];
            }
            sm.fsum[e] = (s0 + s1) + (s2 + s3);
        }
        __syncthreads();

        // ---- mainloop: stream compacted packed feat (valid tokens only) -----
        {
            unsigned long long a0 = 0ULL, a1 = 0ULL, a2 = 0ULL,
                               a3 = 0ULL, a4 = 0ULL, zz = 0ULL;
            #pragma unroll 2
            for (int j2 = 0; j2 < np2; ++j2) {
                float4 A = sm.fA[j2];
                float4 Bq = sm.fB[j2];
                float4 C = sm.fC[j2];
                unsigned long long pA01 = pk2(A.x, A.y);
                unsigned long long pA23 = pk2(A.z, A.w);
                unsigned long long pB01 = pk2(Bq.x, Bq.y);
                unsigned long long pB23 = pk2(Bq.z, Bq.w);
                unsigned long long pC01 = pk2(C.x, C.y);
                unsigned long long s =
                    ffma2(gqs[0], pA01,
                    ffma2(gqs[1], pA23,
                    ffma2(gqs[2], pB01,
                    ffma2(gqs[3], pB23,
                    ffma2(gqs[4], pC01, 0ULL)))));
                float s0, s1;
                unpk2(s, s0, s1);
                float p0 = ex2f(s0) * C.z;     // pad -> 0
                float p1 = ex2f(s1) * C.w;
                unsigned long long pp = pk2(p0, p1);
                a0 = ffma2(pp, pA01, a0);
                a1 = ffma2(pp, pA23, a1);
                a2 = ffma2(pp, pB01, a2);
                a3 = ffma2(pp, pB23, a3);
                a4 = ffma2(pp, pC01, a4);
                zz = fadd2(zz, pp);
            }

            if (i < NT) {
                float lo, hi, af0, af1, af2, af3, af4, Z;
                unpk2(a0, lo, hi); af0 = lo + hi;
                unpk2(a1, lo, hi); af1 = lo + hi;
                unpk2(a2, lo, hi); af2 = lo + hi;
                unpk2(a3, lo, hi); af3 = lo + hi;
                unpk2(a4, lo, hi); af4 = lo + hi;
                unpk2(zz, lo, hi); Z   = lo + hi;
                float inv;
                if (mi_on) {
                    inv = __fdividef(1.0f, Z);
                } else {
                    // masked row: uniform attention over ALL tokens
                    af0 = sm.fsum[0]; af1 = sm.fsum[1]; af2 = sm.fsum[2];
                    af3 = sm.fsum[3]; af4 = sm.fsum[4];
                    inv = 0.01f;
                }
                const float* wpp = &sm.wp[(l * Hh + hmy) * 25];
                float o[Ed];
                #pragma unroll
                for (int e = 0; e < Ed; ++e) {
                    float s = wpp[e * 5 + 0] * af0;
                    s = fmaf(wpp[e * 5 + 1], af1, s);
                    s = fmaf(wpp[e * 5 + 2], af2, s);
                    s = fmaf(wpp[e * 5 + 3], af3, s);
                    s = fmaf(wpp[e * 5 + 4], af4, s);
                    o[e] = s * inv;
                }
                sm.partA[hmy][i] = make_float4(o[0], o[1], o[2], o[3]);
                sm.partB[hmy][i] = o[4];
            }
        }
        __syncthreads();

        // ---- merged epilogue: head-sum + residual + LN1 + FFN + LN2 ---------
        if (tid < NT) {
            float a[Ed];
            #pragma unroll
            for (int e = 0; e < Ed; ++e) a[e] = sm.feat[tid][e];
            #pragma unroll
            for (int h = 0; h < Hh; ++h) {
                float4 pa = sm.partA[h][tid];
                a[0] += pa.x; a[1] += pa.y; a[2] += pa.z; a[3] += pa.w;
                a[4] += sm.partB[h][tid];
            }
            float mu = 0.f;
            #pragma unroll
            for (int e = 0; e < Ed; ++e) mu += a[e];
            mu *= 0.2f;
            float var = 0.f;
            #pragma unroll
            for (int e = 0; e < Ed; ++e) { float dd = a[e] - mu; var = fmaf(dd, dd, var); }
            var *= 0.2f;
            float rinv = rsqrtf(var + 1e-5f);
            float ln1[Ed], fo[Ed];
            #pragma unroll
            for (int e = 0; e < Ed; ++e)
                ln1[e] = (a[e] - mu) * rinv * g1[l * Ed + e] + b1[l * Ed + e];
            #pragma unroll
            for (int e = 0; e < Ed; ++e) {
                float s = bfb[l * Ed + e];
                #pragma unroll
                for (int e2 = 0; e2 < Ed; ++e2)
                    s = fmaf(Wf[((size_t)(l * Ed + e)) * Ed + e2], ln1[e2], s);
                fo[e] = fmaxf(s, 0.0f) + ln1[e];
            }
            float mu2 = 0.f;
            #pragma unroll
            for (int e = 0; e < Ed; ++e) mu2 += fo[e];
            mu2 *= 0.2f;
            float var2 = 0.f;
            #pragma unroll
            for (int e = 0; e < Ed; ++e) { float dd = fo[e] - mu2; var2 = fmaf(dd, dd, var2); }
            var2 *= 0.2f;
            float rinv2 = rsqrtf(var2 + 1e-5f);
            float nf[Ed];
            #pragma unroll
            for (int e = 0; e < Ed; ++e) {
                nf[e] = (fo[e] - mu2) * rinv2 * g2[l * Ed + e] + b2[l * Ed + e];
                sm.feat[tid][e] = nf[e];
            }
            // refresh compacted feat for next layer (valid tokens only)
            if (sm.maskf[tid] > 0.5f) {
                const int slot = sm.cslot[tid];
                const int jp = slot >> 1, lh = slot & 1;
                float* pA = reinterpret_cast<float*>(&sm.fA[jp]);
                pA[lh] = nf[0];  pA[2 + lh] = nf[1];
                float* pB = reinterpret_cast<float*>(&sm.fB[jp]);
                pB[lh] = nf[2];  pB[2 + lh] = nf[3];
                float* pC = reinterpret_cast<float*>(&sm.fC[jp]);
                pC[lh] = nf[4];                  // marker halves untouched
            }
        }
        __syncthreads();
    } // layers

    // ---------------- write output ----------------
    for (int idx = tid; idx < NT * Ed; idx += NTHREADS)
        out[(size_t)b * (NT * Ed) + idx] = (&sm.feat[0][0])[idx];
}

extern "C" void kernel_launch(void* const* d_in, const int* in_sizes, int n_in,
                              void* d_out, int out_size)
{
    const float* x   = (const float*)d_in[0];
    const float* Wq  = (const float*)d_in[1];
    const float* Wk  = (const float*)d_in[2];
    const float* Wv  = (const float*)d_in[3];
    const float* Wo  = (const float*)d_in[4];
    const float* Wf  = (const float*)d_in[5];
    const float* bfb = (const float*)d_in[6];
    const float* g1  = (const float*)d_in[7];
    const float* b1  = (const float*)d_in[8];
    const float* g2  = (const float*)d_in[9];
    const float* b2  = (const float*)d_in[10];
    float* out = (float*)d_out;

    encoder_kernel<<<Bb, NTHREADS>>>(x, Wq, Wk, Wv, Wo, Wf, bfb,
                                     g1, b1, g2, b2, out);
}

// round 14
// speedup vs baseline: 22.1795x; 1.0661x over previous
#include <cuda_runtime.h>
#include <math.h>
#include <float.h>

#define Bb      1024
#define NW      300
#define NT      100      // tokens
#define Ed      5        // embed dim
#define Hh      4        // heads
#define Dd      64       // head dim
#define Ll      3        // layers
#define NTHREADS 512
#define NPAIR   50       // max j-pairs (compacted)

struct SMem {
    float  feat[NT][Ed];          // linear feat (gq build, epilogue, output)
    float  maskf[NT];
    int    cslot[NT];             // valid token -> compact slot
    int    islot[NT];             // compact row -> token (valid first, then masked)
    unsigned int bal[4];          // valid ballots
    unsigned int bal2[4];         // masked-token ballots
    int    nv;                    // number of valid tokens
    int    np2;                   // compacted j-pairs
    float  fsum[Ed];              // sum of feat over ALL tokens (per layer)
    float  mqk[Ll * Hh * Ed * Ed];// folded score matrices (ex2-ready)
    float  wp [Ll * Hh * Ed * Ed];// folded value+output matrices
    float4 fA[NPAIR];             // compacted (f0_lo,f0_hi,f1_lo,f1_hi)
    float4 fB[NPAIR];             // compacted (f2_lo,f2_hi,f3_lo,f3_hi)
    float2 fC2[NPAIR];            // compacted (f4_lo,f4_hi)
    float4 partA[Hh][NT];         // head partial out[0..3]
    float  partB[Hh][NT];         // head partial out[4]
};

// ---- packed f32x2 helpers ----
__device__ __forceinline__ unsigned long long pk2(float lo, float hi) {
    unsigned long long r;
    asm("mov.b64 %0, {%1, %2};" : "=l"(r) : "f"(lo), "f"(hi));
    return r;
}
__device__ __forceinline__ unsigned long long splat2(float v) {
    unsigned long long r;
    asm("mov.b64 %0, {%1, %1};" : "=l"(r) : "f"(v));
    return r;
}
__device__ __forceinline__ void unpk2(unsigned long long p, float& lo, float& hi) {
    asm("mov.b64 {%0, %1}, %2;" : "=f"(lo), "=f"(hi) : "l"(p));
}
__device__ __forceinline__ unsigned long long ffma2(unsigned long long a,
                                                    unsigned long long b,
                                                    unsigned long long c) {
    unsigned long long d;
    asm("fma.rn.f32x2 %0, %1, %2, %3;" : "=l"(d) : "l"(a), "l"(b), "l"(c));
    return d;
}
__device__ __forceinline__ unsigned long long fadd2(unsigned long long a,
                                                    unsigned long long b) {
    unsigned long long d;
    asm("add.rn.f32x2 %0, %1, %2;" : "=l"(d) : "l"(a), "l"(b));
    return d;
}
__device__ __forceinline__ float ex2f(float x) {
    float r;
    asm("ex2.approx.f32 %0, %1;" : "=f"(r) : "f"(x));
    return r;
}

__global__ __launch_bounds__(NTHREADS, 2)
void encoder_kernel(const float* __restrict__ x,
                    const float* __restrict__ Wq, const float* __restrict__ Wk,
                    const float* __restrict__ Wv, const float* __restrict__ Wo,
                    const float* __restrict__ Wf, const float* __restrict__ bfb,
                    const float* __restrict__ g1, const float* __restrict__ b1,
                    const float* __restrict__ g2, const float* __restrict__ b2,
                    float* __restrict__ out)
{
    __shared__ SMem sm;

    const int b   = blockIdx.x;
    const int tid = threadIdx.x;

    // ---------------- init: embedding + inline fold + zero packed ------------
    bool  mym = false;
    float f0 = 0.f, f1 = 0.f, f2 = 0.f, f3 = 0.f, f4 = 0.f;
    if (tid < NT) {
        float k0 = x[b * NW + tid * 3 + 0];
        float k1 = x[b * NW + tid * 3 + 1];
        float k2 = x[b * NW + tid * 3 + 2];
        mym = k2 > 0.0f;
        float sn, cs;
        sincosf((float)tid, &sn, &cs);
        f0 = mym ? k0 : 0.0f; f1 = mym ? k1 : 0.0f; f2 = mym ? k2 : 0.0f;
        f3 = mym ? sn : 0.0f; f4 = mym ? cs : 0.0f;
        sm.maskf[tid]   = mym ? 1.0f : 0.0f;
        sm.feat[tid][0] = f0;
        sm.feat[tid][1] = f1;
        sm.feat[tid][2] = f2;
        sm.feat[tid][3] = f3;
        sm.feat[tid][4] = f4;
    }
    // inline fold: Mqk = scale*log2e*Wq^T Wk, Wp = Wo Wv  (300 threads)
    if (tid < Ll * Hh * Ed * Ed) {
        const int l   = tid / (Hh * Ed * Ed);
        const int rem = tid % (Hh * Ed * Ed);
        const int h   = rem / (Ed * Ed);
        const int e1  = (rem / Ed) % Ed;
        const int e2  = rem % Ed;
        const float* wqp = Wq + ((size_t)((l * Hh + h) * Dd)) * Ed + e1;
        const float* wkp = Wk + ((size_t)((l * Hh + h) * Dd)) * Ed + e2;
        const float* wvp = Wv + ((size_t)((l * Hh + h) * Dd)) * Ed + e2;
        const float* wop = Wo + ((size_t)(l * Ed + e1)) * (Hh * Dd) + h * Dd;
        float sq = 0.0f, sp = 0.0f;
        #pragma unroll 8
        for (int d = 0; d < Dd; ++d) {
            sq = fmaf(wqp[d * Ed], wkp[d * Ed], sq);
            sp = fmaf(wop[d],      wvp[d * Ed], sp);
        }
        sm.mqk[tid] = sq * (0.125f * 1.4426950408889634f);
        sm.wp[tid]  = sp;
    }
    // zero compacted arrays (pads must be exactly 0)
    if (tid < 3 * NPAIR) {
        if (tid < NPAIR)          sm.fA[tid] = make_float4(0.f, 0.f, 0.f, 0.f);
        else if (tid < 2 * NPAIR) sm.fB[tid - NPAIR] = make_float4(0.f, 0.f, 0.f, 0.f);
        else                      sm.fC2[tid - 2 * NPAIR] = make_float2(0.f, 0.f);
    }
    // ballots (warps 0..3)
    if (tid < 128) {
        unsigned bmV = __ballot_sync(0xffffffffu, mym);
        unsigned bmM = __ballot_sync(0xffffffffu, (tid < NT) && !mym);
        if ((tid & 31) == 0) { sm.bal[tid >> 5] = bmV; sm.bal2[tid >> 5] = bmM; }
    }
    __syncthreads();

    // compact maps + packed writes
    {
        const int nv_loc = __popc(sm.bal[0]) + __popc(sm.bal[1]) +
                           __popc(sm.bal[2]) + __popc(sm.bal[3]);
        if (tid == 0) { sm.nv = nv_loc; sm.np2 = (nv_loc + 1) >> 1; }
        if (tid < NT) {
            if (mym) {
                unsigned bm = sm.bal[tid >> 5];
                int rank = __popc(bm & ((1u << (tid & 31)) - 1u));
                #pragma unroll
                for (int ww = 0; ww < 3; ++ww)
                    if (ww < (tid >> 5)) rank += __popc(sm.bal[ww]);
                sm.cslot[tid] = rank;
                sm.islot[rank] = tid;
                const int jp = rank >> 1, lh = rank & 1;
                float* pA = reinterpret_cast<float*>(&sm.fA[jp]);
                pA[lh] = f0;  pA[2 + lh] = f1;
                float* pB = reinterpret_cast<float*>(&sm.fB[jp]);
                pB[lh] = f2;  pB[2 + lh] = f3;
                float* pC = reinterpret_cast<float*>(&sm.fC2[jp]);
                pC[lh] = f4;
            } else {
                unsigned bm = sm.bal2[tid >> 5];
                int rank = __popc(bm & ((1u << (tid & 31)) - 1u));
                #pragma unroll
                for (int ww = 0; ww < 3; ++ww)
                    if (ww < (tid >> 5)) rank += __popc(sm.bal2[ww]);
                sm.islot[nv_loc + rank] = tid;
            }
        }
    }
    __syncthreads();

    // thread -> (head, compact row)
    const int hmy   = tid >> 7;            // 0..3
    const int r     = tid & 127;           // compact row id
    const int nv    = sm.nv;
    const int np2   = sm.np2;
    const bool heavy = (r < nv);
    const bool light = (r >= nv) && (r < NT);
    const int tok   = (r < NT) ? sm.islot[r] : 0;
    const float padZ = (nv & 1) ? 1.0f : 0.0f;  // odd-pad pollution of Z

    #pragma unroll 1
    for (int l = 0; l < Ll; ++l) {
        // ---- phase 0: gq for heavy threads; fsum by idle threads ------------
        unsigned long long gqs[Ed];
        if (heavy) {
            const float* mq = &sm.mqk[(l * Hh + hmy) * 25];
            const float fi0 = sm.feat[tok][0], fi1 = sm.feat[tok][1];
            const float fi2 = sm.feat[tok][2], fi3 = sm.feat[tok][3];
            const float fi4 = sm.feat[tok][4];
            #pragma unroll
            for (int e2 = 0; e2 < Ed; ++e2) {
                float v = mq[0 * 5 + e2] * fi0;
                v = fmaf(mq[1 * 5 + e2], fi1, v);
                v = fmaf(mq[2 * 5 + e2], fi2, v);
                v = fmaf(mq[3 * 5 + e2], fi3, v);
                v = fmaf(mq[4 * 5 + e2], fi4, v);
                gqs[e2] = splat2(v);
            }
        }
        if (tid >= NT + Hh * NT - NT && false) {}   // (placeholder removed)
        if (tid >= 4 * 128 - 28 && tid < 4 * 128 - 23) {
            // threads 484..488 (hmy=3, r=100..104 idle): compute fsum
            const int e = tid - (4 * 128 - 28);
            float s0 = 0.f, s1 = 0.f, s2 = 0.f, s3 = 0.f;
            #pragma unroll 5
            for (int j = 0; j < NT; j += 4) {
                s0 += sm.feat[j + 0][e];
                s1 += sm.feat[j + 1][e];
                s2 += sm.feat[j + 2][e];
                s3 += sm.feat[j + 3][e];
            }
            sm.fsum[e] = (s0 + s1) + (s2 + s3);
        }
        __syncthreads();

        // ---- mainloop (heavy) / closed form (light) -------------------------
        if (heavy) {
            unsigned long long a0 = 0ULL, a1 = 0ULL, a2 = 0ULL,
                               a3 = 0ULL, a4 = 0ULL, zz = 0ULL;
            #pragma unroll 2
            for (int j2 = 0; j2 < np2; ++j2) {
                ulonglong2 A = *reinterpret_cast<const ulonglong2*>(&sm.fA[j2]);
                ulonglong2 Bq = *reinterpret_cast<const ulonglong2*>(&sm.fB[j2]);
                unsigned long long Cp =
                    *reinterpret_cast<const unsigned long long*>(&sm.fC2[j2]);
                unsigned long long s =
                    ffma2(gqs[0], A.x,
                    ffma2(gqs[1], A.y,
                    ffma2(gqs[2], Bq.x,
                    ffma2(gqs[3], Bq.y,
                    ffma2(gqs[4], Cp, 0ULL)))));
                float s0, s1;
                unpk2(s, s0, s1);
                unsigned long long pp = pk2(ex2f(s0), ex2f(s1));
                a0 = ffma2(pp, A.x, a0);
                a1 = ffma2(pp, A.y, a1);
                a2 = ffma2(pp, Bq.x, a2);
                a3 = ffma2(pp, Bq.y, a3);
                a4 = ffma2(pp, Cp, a4);
                zz = fadd2(zz, pp);
            }
            float lo, hi, af0, af1, af2, af3, af4, Z;
            unpk2(a0, lo, hi); af0 = lo + hi;
            unpk2(a1, lo, hi); af1 = lo + hi;
            unpk2(a2, lo, hi); af2 = lo + hi;
            unpk2(a3, lo, hi); af3 = lo + hi;
            unpk2(a4, lo, hi); af4 = lo + hi;
            unpk2(zz, lo, hi); Z   = (lo + hi) - padZ;
            const float inv = __fdividef(1.0f, Z);
            const float* wpp = &sm.wp[(l * Hh + hmy) * 25];
            float o[Ed];
            #pragma unroll
            for (int e = 0; e < Ed; ++e) {
                float s = wpp[e * 5 + 0] * af0;
                s = fmaf(wpp[e * 5 + 1], af1, s);
                s = fmaf(wpp[e * 5 + 2], af2, s);
                s = fmaf(wpp[e * 5 + 3], af3, s);
                s = fmaf(wpp[e * 5 + 4], af4, s);
                o[e] = s * inv;
            }
            sm.partA[hmy][tok] = make_float4(o[0], o[1], o[2], o[3]);
            sm.partB[hmy][tok] = o[4];
        } else if (light) {
            // masked row: uniform attention over ALL tokens, closed form
            const float af0 = sm.fsum[0], af1 = sm.fsum[1], af2 = sm.fsum[2];
            const float af3 = sm.fsum[3], af4 = sm.fsum[4];
            const float* wpp = &sm.wp[(l * Hh + hmy) * 25];
            float o[Ed];
            #pragma unroll
            for (int e = 0; e < Ed; ++e) {
                float s = wpp[e * 5 + 0] * af0;
                s = fmaf(wpp[e * 5 + 1], af1, s);
                s = fmaf(wpp[e * 5 + 2], af2, s);
                s = fmaf(wpp[e * 5 + 3], af3, s);
                s = fmaf(wpp[e * 5 + 4], af4, s);
                o[e] = s * 0.01f;
            }
            sm.partA[hmy][tok] = make_float4(o[0], o[1], o[2], o[3]);
            sm.partB[hmy][tok] = o[4];
        }
        __syncthreads();

        // ---- merged epilogue: head-sum + residual + LN1 + FFN + LN2 ---------
        if (tid < NT) {
            float a[Ed];
            #pragma unroll
            for (int e = 0; e < Ed; ++e) a[e] = sm.feat[tid][e];
            #pragma unroll
            for (int h = 0; h < Hh; ++h) {
                float4 pa = sm.partA[h][tid];
                a[0] += pa.x; a[1] += pa.y; a[2] += pa.z; a[3] += pa.w;
                a[4] += sm.partB[h][tid];
            }
            float mu = 0.f;
            #pragma unroll
            for (int e = 0; e < Ed; ++e) mu += a[e];
            mu *= 0.2f;
            float var = 0.f;
            #pragma unroll
            for (int e = 0; e < Ed; ++e) { float dd = a[e] - mu; var = fmaf(dd, dd, var); }
            var *= 0.2f;
            float rinv = rsqrtf(var + 1e-5f);
            float ln1[Ed], fo[Ed];
            #pragma unroll
            for (int e = 0; e < Ed; ++e)
                ln1[e] = (a[e] - mu) * rinv * g1[l * Ed + e] + b1[l * Ed + e];
            #pragma unroll
            for (int e = 0; e < Ed; ++e) {
                float s = bfb[l * Ed + e];
                #pragma unroll
                for (int e2 = 0; e2 < Ed; ++e2)
                    s = fmaf(Wf[((size_t)(l * Ed + e)) * Ed + e2], ln1[e2], s);
                fo[e] = fmaxf(s, 0.0f) + ln1[e];
            }
            float mu2 = 0.f;
            #pragma unroll
            for (int e = 0; e < Ed; ++e) mu2 += fo[e];
            mu2 *= 0.2f;
            float var2 = 0.f;
            #pragma unroll
            for (int e = 0; e < Ed; ++e) { float dd = fo[e] - mu2; var2 = fmaf(dd, dd, var2); }
            var2 *= 0.2f;
            float rinv2 = rsqrtf(var2 + 1e-5f);
            float nf[Ed];
            #pragma unroll
            for (int e = 0; e < Ed; ++e) {
                nf[e] = (fo[e] - mu2) * rinv2 * g2[l * Ed + e] + b2[l * Ed + e];
                sm.feat[tid][e] = nf[e];
            }
            // refresh compacted feat for next layer (valid tokens only)
            if (sm.maskf[tid] > 0.5f) {
                const int slot = sm.cslot[tid];
                const int jp = slot >> 1, lh = slot & 1;
                float* pA = reinterpret_cast<float*>(&sm.fA[jp]);
                pA[lh] = nf[0];  pA[2 + lh] = nf[1];
                float* pB = reinterpret_cast<float*>(&sm.fB[jp]);
                pB[lh] = nf[2];  pB[2 + lh] = nf[3];
                float* pC = reinterpret_cast<float*>(&sm.fC2[jp]);
                pC[lh] = nf[4];
            }
        }
        __syncthreads();
    } // layers

    // ---------------- write output ----------------
    for (int idx = tid; idx < NT * Ed; idx += NTHREADS)
        out[(size_t)b * (NT * Ed) + idx] = (&sm.feat[0][0])[idx];
}

extern "C" void kernel_launch(void* const* d_in, const int* in_sizes, int n_in,
                              void* d_out, int out_size)
{
    const float* x   = (const float*)d_in[0];
    const float* Wq  = (const float*)d_in[1];
    const float* Wk  = (const float*)d_in[2];
    const float* Wv  = (const float*)d_in[3];
    const float* Wo  = (const float*)d_in[4];
    const float* Wf  = (const float*)d_in[5];
    const float* bfb = (const float*)d_in[6];
    const float* g1  = (const float*)d_in[7];
    const float* b1  = (const float*)d_in[8];
    const float* g2  = (const float*)d_in[9];
    const float* b2  = (const float*)d_in[10];
    float* out = (float*)d_out;

    encoder_kernel<<<Bb, NTHREADS>>>(x, Wq, Wk, Wv, Wo, Wf, bfb,
                                     g1, b1, g2, b2, out);
}

// round 15
// speedup vs baseline: 27.0080x; 1.2177x over previous
#include <cuda_runtime.h>
#include <math.h>
#include <float.h>

#define Bb      1024
#define NW      300
#define NT      100      // tokens
#define Ed      5        // embed dim
#define Hh      4        // heads
#define Dd      64       // head dim
#define Ll      3        // layers
#define NTHREADS 512
#define NPAIR   50       // max j-pairs (compacted)

struct SMem {
    float  feat[NT][Ed];          // linear feat (gq build, epilogue, output)
    float  maskf[NT];
    int    cslot[NT];             // valid token -> compact slot
    int    islot[NT];             // compact row -> token (valid first, then masked)
    unsigned int bal[4];          // valid ballots
    unsigned int bal2[4];         // masked-token ballots
    int    nv;                    // number of valid tokens
    float  fsum[Ed];              // sum of feat over ALL tokens (per layer)
    float  mqk[Ll * Hh * Ed * Ed];// folded score matrices (ex2-ready)
    float  wp [Ll * Hh * Ed * Ed];// folded value+output matrices
    float4 fA[NPAIR];             // compacted (f0_lo,f0_hi,f1_lo,f1_hi)
    float4 fB[NPAIR];             // compacted (f2_lo,f2_hi,f3_lo,f3_hi)
    float2 fC2[NPAIR];            // compacted (f4_lo,f4_hi)
    float4 partA[Hh][NT];         // head partial out[0..3]
    float  partB[Hh][NT];         // head partial out[4]
};

// ---- packed f32x2 helpers ----
__device__ __forceinline__ unsigned long long pk2(float lo, float hi) {
    unsigned long long r;
    asm("mov.b64 %0, {%1, %2};" : "=l"(r) : "f"(lo), "f"(hi));
    return r;
}
__device__ __forceinline__ unsigned long long splat2(float v) {
    unsigned long long r;
    asm("mov.b64 %0, {%1, %1};" : "=l"(r) : "f"(v));
    return r;
}
__device__ __forceinline__ void unpk2(unsigned long long p, float& lo, float& hi) {
    asm("mov.b64 {%0, %1}, %2;" : "=f"(lo), "=f"(hi) : "l"(p));
}
__device__ __forceinline__ unsigned long long ffma2(unsigned long long a,
                                                    unsigned long long b,
                                                    unsigned long long c) {
    unsigned long long d;
    asm("fma.rn.f32x2 %0, %1, %2, %3;" : "=l"(d) : "l"(a), "l"(b), "l"(c));
    return d;
}
__device__ __forceinline__ unsigned long long fadd2(unsigned long long a,
                                                    unsigned long long b) {
    unsigned long long d;
    asm("add.rn.f32x2 %0, %1, %2;" : "=l"(d) : "l"(a), "l"(b));
    return d;
}
__device__ __forceinline__ float ex2f(float x) {
    float r;
    asm("ex2.approx.f32 %0, %1;" : "=f"(r) : "f"(x));
    return r;
}

__global__ __launch_bounds__(NTHREADS, 2)
void encoder_kernel(const float* __restrict__ x,
                    const float* __restrict__ Wq, const float* __restrict__ Wk,
                    const float* __restrict__ Wv, const float* __restrict__ Wo,
                    const float* __restrict__ Wf, const float* __restrict__ bfb,
                    const float* __restrict__ g1, const float* __restrict__ b1,
                    const float* __restrict__ g2, const float* __restrict__ b2,
                    float* __restrict__ out)
{
    __shared__ SMem sm;

    const int b   = blockIdx.x;
    const int tid = threadIdx.x;

    // ---------------- init: embedding + inline fold + zero packed ------------
    bool  mym = false;
    float f0 = 0.f, f1 = 0.f, f2 = 0.f, f3 = 0.f, f4 = 0.f;
    if (tid < NT) {
        float k0 = x[b * NW + tid * 3 + 0];
        float k1 = x[b * NW + tid * 3 + 1];
        float k2 = x[b * NW + tid * 3 + 2];
        mym = k2 > 0.0f;
        float sn, cs;
        sincosf((float)tid, &sn, &cs);
        f0 = mym ? k0 : 0.0f; f1 = mym ? k1 : 0.0f; f2 = mym ? k2 : 0.0f;
        f3 = mym ? sn : 0.0f; f4 = mym ? cs : 0.0f;
        sm.maskf[tid]   = mym ? 1.0f : 0.0f;
        sm.feat[tid][0] = f0;
        sm.feat[tid][1] = f1;
        sm.feat[tid][2] = f2;
        sm.feat[tid][3] = f3;
        sm.feat[tid][4] = f4;
    }
    // inline fold: Mqk = scale*log2e*Wq^T Wk, Wp = Wo Wv  (300 threads)
    if (tid < Ll * Hh * Ed * Ed) {
        const int l   = tid / (Hh * Ed * Ed);
        const int rem = tid % (Hh * Ed * Ed);
        const int h   = rem / (Ed * Ed);
        const int e1  = (rem / Ed) % Ed;
        const int e2  = rem % Ed;
        const float* wqp = Wq + ((size_t)((l * Hh + h) * Dd)) * Ed + e1;
        const float* wkp = Wk + ((size_t)((l * Hh + h) * Dd)) * Ed + e2;
        const float* wvp = Wv + ((size_t)((l * Hh + h) * Dd)) * Ed + e2;
        const float* wop = Wo + ((size_t)(l * Ed + e1)) * (Hh * Dd) + h * Dd;
        float sq = 0.0f, sp = 0.0f;
        #pragma unroll 8
        for (int d = 0; d < Dd; ++d) {
            sq = fmaf(wqp[d * Ed], wkp[d * Ed], sq);
            sp = fmaf(wop[d],      wvp[d * Ed], sp);
        }
        sm.mqk[tid] = sq * (0.125f * 1.4426950408889634f);
        sm.wp[tid]  = sp;
    }
    // zero compacted arrays (pads must be exactly 0)
    if (tid < 3 * NPAIR) {
        if (tid < NPAIR)          sm.fA[tid] = make_float4(0.f, 0.f, 0.f, 0.f);
        else if (tid < 2 * NPAIR) sm.fB[tid - NPAIR] = make_float4(0.f, 0.f, 0.f, 0.f);
        else                      sm.fC2[tid - 2 * NPAIR] = make_float2(0.f, 0.f);
    }
    // ballots (warps 0..3)
    if (tid < 128) {
        unsigned bmV = __ballot_sync(0xffffffffu, mym);
        unsigned bmM = __ballot_sync(0xffffffffu, (tid < NT) && !mym);
        if ((tid & 31) == 0) { sm.bal[tid >> 5] = bmV; sm.bal2[tid >> 5] = bmM; }
    }
    __syncthreads();

    // compact maps + packed writes
    {
        const int nv_loc = __popc(sm.bal[0]) + __popc(sm.bal[1]) +
                           __popc(sm.bal[2]) + __popc(sm.bal[3]);
        if (tid == 0) sm.nv = nv_loc;
        if (tid < NT) {
            if (mym) {
                unsigned bm = sm.bal[tid >> 5];
                int rank = __popc(bm & ((1u << (tid & 31)) - 1u));
                #pragma unroll
                for (int ww = 0; ww < 3; ++ww)
                    if (ww < (tid >> 5)) rank += __popc(sm.bal[ww]);
                sm.cslot[tid] = rank;
                sm.islot[rank] = tid;
                const int jp = rank >> 1, lh = rank & 1;
                float* pA = reinterpret_cast<float*>(&sm.fA[jp]);
                pA[lh] = f0;  pA[2 + lh] = f1;
                float* pB = reinterpret_cast<float*>(&sm.fB[jp]);
                pB[lh] = f2;  pB[2 + lh] = f3;
                float* pC = reinterpret_cast<float*>(&sm.fC2[jp]);
                pC[lh] = f4;
            } else {
                unsigned bm = sm.bal2[tid >> 5];
                int rank = __popc(bm & ((1u << (tid & 31)) - 1u));
                #pragma unroll
                for (int ww = 0; ww < 3; ++ww)
                    if (ww < (tid >> 5)) rank += __popc(sm.bal2[ww]);
                sm.islot[nv_loc + rank] = tid;
            }
        }
    }
    __syncthreads();

    // ---- work partition (constant across layers) ----------------------------
    const int nv   = sm.nv;
    const int nm   = NT - nv;
    const int np2  = (nv + 1) >> 1;            // compacted j-pairs
    const int heavyItems = Hh * nv;
    // split factor 2 when paired threads + >=1 light warp fit
    const int sf = (2 * heavyItems + ((nm > 0) ? 32 : 0) <= NTHREADS) ? 2 : 1;
    const int heavyThreads = sf * heavyItems;
    const int heavyWarps   = (heavyThreads + 31) >> 5;
    const bool inHeavy     = (tid >> 5) < heavyWarps;
    const bool realHeavy   = inHeavy && (tid < heavyThreads);
    int hitem = 0, half = 0, hhead = 0, htok = 0;
    if (inHeavy && heavyItems > 0) {
        int it = (sf == 2) ? (tid >> 1) : tid;
        hitem = (it < heavyItems) ? it : (heavyItems - 1);
        half  = (sf == 2) ? (tid & 1) : 0;
        hhead = hitem / nv;
        htok  = sm.islot[hitem - hhead * nv];
    }
    const int lightBase   = tid - heavyWarps * 32;   // valid when !inHeavy
    const int lightStride = NTHREADS - heavyWarps * 32;
    const int lightItems  = Hh * nm;
    const float padZ = ((nv & 1) ? 1.0f : 0.0f);
    const int np2h = (sf == 2) ? ((np2 + 1) >> 1) : np2;
    const int jlo  = (half == 1) ? np2h : 0;
    const int jhi  = (half == 1) ? np2 : np2h;

    #pragma unroll 1
    for (int l = 0; l < Ll; ++l) {
        // ---- phase 0: gq for heavy threads; fsum by threads 480-484 ---------
        unsigned long long gqs[Ed];
        if (inHeavy) {
            const float* mq = &sm.mqk[(l * Hh + hhead) * 25];
            const float fi0 = sm.feat[htok][0], fi1 = sm.feat[htok][1];
            const float fi2 = sm.feat[htok][2], fi3 = sm.feat[htok][3];
            const float fi4 = sm.feat[htok][4];
            #pragma unroll
            for (int e2 = 0; e2 < Ed; ++e2) {
                float v = mq[0 * 5 + e2] * fi0;
                v = fmaf(mq[1 * 5 + e2], fi1, v);
                v = fmaf(mq[2 * 5 + e2], fi2, v);
                v = fmaf(mq[3 * 5 + e2], fi3, v);
                v = fmaf(mq[4 * 5 + e2], fi4, v);
                gqs[e2] = splat2(v);
            }
        }
        if (tid >= 480 && tid < 480 + Ed) {   // never heavy (heavyThreads<=480)
            const int e = tid - 480;
            float s0 = 0.f, s1 = 0.f, s2 = 0.f, s3 = 0.f;
            #pragma unroll 5
            for (int j = 0; j < NT; j += 4) {
                s0 += sm.feat[j + 0][e];
                s1 += sm.feat[j + 1][e];
                s2 += sm.feat[j + 2][e];
                s3 += sm.feat[j + 3][e];
            }
            sm.fsum[e] = (s0 + s1) + (s2 + s3);
        }
        __syncthreads();

        // ---- mainloop: heavy warps (split-j) / light warps (closed form) ----
        if (inHeavy) {
            unsigned long long a0 = 0ULL, a1 = 0ULL, a2 = 0ULL,
                               a3 = 0ULL, a4 = 0ULL, zz = 0ULL;
            #pragma unroll 4
            for (int j2 = jlo; j2 < jhi; ++j2) {
                ulonglong2 A = *reinterpret_cast<const ulonglong2*>(&sm.fA[j2]);
                ulonglong2 Bq = *reinterpret_cast<const ulonglong2*>(&sm.fB[j2]);
                unsigned long long Cp =
                    *reinterpret_cast<const unsigned long long*>(&sm.fC2[j2]);
                // two parallel trees + join: depth 3 instead of 5
                unsigned long long sA = ffma2(gqs[0], A.x, ffma2(gqs[1], A.y, 0ULL));
                unsigned long long sB = ffma2(gqs[2], Bq.x,
                                        ffma2(gqs[3], Bq.y,
                                        ffma2(gqs[4], Cp, 0ULL)));
                unsigned long long s = fadd2(sA, sB);
                float s0, s1;
                unpk2(s, s0, s1);
                unsigned long long pp = pk2(ex2f(s0), ex2f(s1));
                a0 = ffma2(pp, A.x, a0);
                a1 = ffma2(pp, A.y, a1);
                a2 = ffma2(pp, Bq.x, a2);
                a3 = ffma2(pp, Bq.y, a3);
                a4 = ffma2(pp, Cp, a4);
                zz = fadd2(zz, pp);
            }
            if (sf == 2) {   // combine halves (warp-converged in heavy warps)
                a0 = fadd2(a0, __shfl_xor_sync(0xffffffffu, a0, 1));
                a1 = fadd2(a1, __shfl_xor_sync(0xffffffffu, a1, 1));
                a2 = fadd2(a2, __shfl_xor_sync(0xffffffffu, a2, 1));
                a3 = fadd2(a3, __shfl_xor_sync(0xffffffffu, a3, 1));
                a4 = fadd2(a4, __shfl_xor_sync(0xffffffffu, a4, 1));
                zz = fadd2(zz, __shfl_xor_sync(0xffffffffu, zz, 1));
            }
            if (realHeavy && half == 0) {
                float lo, hi, af0, af1, af2, af3, af4, Z;
                unpk2(a0, lo, hi); af0 = lo + hi;
                unpk2(a1, lo, hi); af1 = lo + hi;
                unpk2(a2, lo, hi); af2 = lo + hi;
                unpk2(a3, lo, hi); af3 = lo + hi;
                unpk2(a4, lo, hi); af4 = lo + hi;
                unpk2(zz, lo, hi); Z   = (lo + hi) - padZ;
                const float inv = __fdividef(1.0f, Z);
                const float* wpp = &sm.wp[(l * Hh + hhead) * 25];
                float o[Ed];
                #pragma unroll
                for (int e = 0; e < Ed; ++e) {
                    float s = wpp[e * 5 + 0] * af0;
                    s = fmaf(wpp[e * 5 + 1], af1, s);
                    s = fmaf(wpp[e * 5 + 2], af2, s);
                    s = fmaf(wpp[e * 5 + 3], af3, s);
                    s = fmaf(wpp[e * 5 + 4], af4, s);
                    o[e] = s * inv;
                }
                sm.partA[hhead][htok] = make_float4(o[0], o[1], o[2], o[3]);
                sm.partB[hhead][htok] = o[4];
            }
        } else {
            // light warps: masked rows, uniform attention closed form
            const float af0 = sm.fsum[0], af1 = sm.fsum[1], af2 = sm.fsum[2];
            const float af3 = sm.fsum[3], af4 = sm.fsum[4];
            for (int li = lightBase; li < lightItems; li += lightStride) {
                const int lhead = li / nm;
                const int ltok  = sm.islot[nv + (li - lhead * nm)];
                const float* wpp = &sm.wp[(l * Hh + lhead) * 25];
                float o[Ed];
                #pragma unroll
                for (int e = 0; e < Ed; ++e) {
                    float s = wpp[e * 5 + 0] * af0;
                    s = fmaf(wpp[e * 5 + 1], af1, s);
                    s = fmaf(wpp[e * 5 + 2], af2, s);
                    s = fmaf(wpp[e * 5 + 3], af3, s);
                    s = fmaf(wpp[e * 5 + 4], af4, s);
                    o[e] = s * 0.01f;
                }
                sm.partA[lhead][ltok] = make_float4(o[0], o[1], o[2], o[3]);
                sm.partB[lhead][ltok] = o[4];
            }
        }
        __syncthreads();

        // ---- merged epilogue: head-sum + residual + LN1 + FFN + LN2 ---------
        if (tid < NT) {
            float a[Ed];
            #pragma unroll
            for (int e = 0; e < Ed; ++e) a[e] = sm.feat[tid][e];
            #pragma unroll
            for (int h = 0; h < Hh; ++h) {
                float4 pa = sm.partA[h][tid];
                a[0] += pa.x; a[1] += pa.y; a[2] += pa.z; a[3] += pa.w;
                a[4] += sm.partB[h][tid];
            }
            float mu = 0.f;
            #pragma unroll
            for (int e = 0; e < Ed; ++e) mu += a[e];
            mu *= 0.2f;
            float var = 0.f;
            #pragma unroll
            for (int e = 0; e < Ed; ++e) { float dd = a[e] - mu; var = fmaf(dd, dd, var); }
            var *= 0.2f;
            float rinv = rsqrtf(var + 1e-5f);
            float ln1[Ed], fo[Ed];
            #pragma unroll
            for (int e = 0; e < Ed; ++e)
                ln1[e] = (a[e] - mu) * rinv * g1[l * Ed + e] + b1[l * Ed + e];
            #pragma unroll
            for (int e = 0; e < Ed; ++e) {
                float s = bfb[l * Ed + e];
                #pragma unroll
                for (int e2 = 0; e2 < Ed; ++e2)
                    s = fmaf(Wf[((size_t)(l * Ed + e)) * Ed + e2], ln1[e2], s);
                fo[e] = fmaxf(s, 0.0f) + ln1[e];
            }
            float mu2 = 0.f;
            #pragma unroll
            for (int e = 0; e < Ed; ++e) mu2 += fo[e];
            mu2 *= 0.2f;
            float var2 = 0.f;
            #pragma unroll
            for (int e = 0; e < Ed; ++e) { float dd = fo[e] - mu2; var2 = fmaf(dd, dd, var2); }
            var2 *= 0.2f;
            float rinv2 = rsqrtf(var2 + 1e-5f);
            float nf[Ed];
            #pragma unroll
            for (int e = 0; e < Ed; ++e) {
                nf[e] = (fo[e] - mu2) * rinv2 * g2[l * Ed + e] + b2[l * Ed + e];
                sm.feat[tid][e] = nf[e];
            }
            // refresh compacted feat for next layer (valid tokens only)
            if (sm.maskf[tid] > 0.5f) {
                const int slot = sm.cslot[tid];
                const int jp = slot >> 1, lh = slot & 1;
                float* pA = reinterpret_cast<float*>(&sm.fA[jp]);
                pA[lh] = nf[0];  pA[2 + lh] = nf[1];
                float* pB = reinterpret_cast<float*>(&sm.fB[jp]);
                pB[lh] = nf[2];  pB[2 + lh] = nf[3];
                float* pC = reinterpret_cast<float*>(&sm.fC2[jp]);
                pC[lh] = nf[4];
            }
        }
        __syncthreads();
    } // layers

    // ---------------- write output ----------------
    for (int idx = tid; idx < NT * Ed; idx += NTHREADS)
        out[(size_t)b * (NT * Ed) + idx] = (&sm.feat[0][0])[idx];
}

extern "C" void kernel_launch(void* const* d_in, const int* in_sizes, int n_in,
                              void* d_out, int out_size)
{
    const float* x   = (const float*)d_in[0];
    const float* Wq  = (const float*)d_in[1];
    const float* Wk  = (const float*)d_in[2];
    const float* Wv  = (const float*)d_in[3];
    const float* Wo  = (const float*)d_in[4];
    const float* Wf  = (const float*)d_in[5];
    const float* bfb = (const float*)d_in[6];
    const float* g1  = (const float*)d_in[7];
    const float* b1  = (const float*)d_in[8];
    const float* g2  = (const float*)d_in[9];
    const float* b2  = (const float*)d_in[10];
    float* out = (float*)d_out;

    encoder_kernel<<<Bb, NTHREADS>>>(x, Wq, Wk, Wv, Wo, Wf, bfb,
                                     g1, b1, g2, b2, out);
}

// round 16
// speedup vs baseline: 29.3870x; 1.0881x over previous
#include <cuda_runtime.h>
#include <math.h>
#include <float.h>

#define Bb      1024
#define NW      300
#define NT      100      // tokens
#define Ed      5        // embed dim
#define Hh      4        // heads
#define Dd      64       // head dim
#define Ll      3        // layers
#define NTHREADS 512
#define EPC     2        // batch elements per CTA
#define ETH     256      // threads per element group
#define NPAIR   50       // max j-pairs (compacted)

struct Elem {
    float  feat[NT][Ed];
    float  maskf[NT];
    int    cslot[NT];
    int    islot[NT];              // compact row -> token (valid first, then masked)
    unsigned int bal[4], bal2[4];
    int    nv;
    float  wsum[4][Ed];            // per-warp partial sums of feat (for fsum)
    float4 fA[NPAIR];              // compacted (f0_lo,f0_hi,f1_lo,f1_hi)
    float4 fB[NPAIR];              // compacted (f2_lo,f2_hi,f3_lo,f3_hi)
    float2 fC2[NPAIR];             // compacted (f4_lo,f4_hi)
    float4 partA[Hh][NT];
    float  partB[Hh][NT];
};
struct SMem {
    float mqk[Ll * Hh * Ed * Ed];  // folded score matrices (ex2-ready)
    float wp [Ll * Hh * Ed * Ed];  // folded value+output matrices
    Elem  el[EPC];
};

// ---- packed f32x2 helpers ----
__device__ __forceinline__ unsigned long long pk2(float lo, float hi) {
    unsigned long long r;
    asm("mov.b64 %0, {%1, %2};" : "=l"(r) : "f"(lo), "f"(hi));
    return r;
}
__device__ __forceinline__ unsigned long long splat2(float v) {
    unsigned long long r;
    asm("mov.b64 %0, {%1, %1};" : "=l"(r) : "f"(v));
    return r;
}
__device__ __forceinline__ void unpk2(unsigned long long p, float& lo, float& hi) {
    asm("mov.b64 {%0, %1}, %2;" : "=f"(lo), "=f"(hi) : "l"(p));
}
__device__ __forceinline__ unsigned long long ffma2(unsigned long long a,
                                                    unsigned long long b,
                                                    unsigned long long c) {
    unsigned long long d;
    asm("fma.rn.f32x2 %0, %1, %2, %3;" : "=l"(d) : "l"(a), "l"(b), "l"(c));
    return d;
}
__device__ __forceinline__ unsigned long long fadd2(unsigned long long a,
                                                    unsigned long long b) {
    unsigned long long d;
    asm("add.rn.f32x2 %0, %1, %2;" : "=l"(d) : "l"(a), "l"(b));
    return d;
}
__device__ __forceinline__ float ex2f(float x) {
    float r;
    asm("ex2.approx.f32 %0, %1;" : "=f"(r) : "f"(x));
    return r;
}
#define BAR_EL() asm volatile("bar.sync %0, %1;" :: "r"(1 + eg), "r"(ETH) : "memory")

__global__ __launch_bounds__(NTHREADS, 2)
void encoder_kernel(const float* __restrict__ x,
                    const float* __restrict__ Wq, const float* __restrict__ Wk,
                    const float* __restrict__ Wv, const float* __restrict__ Wo,
                    const float* __restrict__ Wf, const float* __restrict__ bfb,
                    const float* __restrict__ g1, const float* __restrict__ b1,
                    const float* __restrict__ g2, const float* __restrict__ b2,
                    float* __restrict__ out)
{
    __shared__ SMem sm;

    const int tid = threadIdx.x;
    const int eg  = tid >> 8;              // element group 0/1
    const int et  = tid & (ETH - 1);       // thread id within group
    const int bb  = blockIdx.x * EPC + eg; // batch element
    Elem& E = sm.el[eg];

    // ---------------- init: embedding + fold + ballots + layer0 wsum ---------
    bool  mym = false;
    float f0 = 0.f, f1 = 0.f, f2 = 0.f, f3 = 0.f, f4 = 0.f;
    if (et < NT) {
        float k0 = x[bb * NW + et * 3 + 0];
        float k1 = x[bb * NW + et * 3 + 1];
        float k2 = x[bb * NW + et * 3 + 2];
        mym = k2 > 0.0f;
        float sn, cs;
        sincosf((float)et, &sn, &cs);
        f0 = mym ? k0 : 0.0f; f1 = mym ? k1 : 0.0f; f2 = mym ? k2 : 0.0f;
        f3 = mym ? sn : 0.0f; f4 = mym ? cs : 0.0f;
        E.maskf[et]   = mym ? 1.0f : 0.0f;
        E.feat[et][0] = f0;
        E.feat[et][1] = f1;
        E.feat[et][2] = f2;
        E.feat[et][3] = f3;
        E.feat[et][4] = f4;
    }
    // inline fold (once per CTA, amortized over 2 elements)
    if (tid < Ll * Hh * Ed * Ed) {
        const int l   = tid / (Hh * Ed * Ed);
        const int rem = tid % (Hh * Ed * Ed);
        const int h   = rem / (Ed * Ed);
        const int e1  = (rem / Ed) % Ed;
        const int e2  = rem % Ed;
        const float* wqp = Wq + ((size_t)((l * Hh + h) * Dd)) * Ed + e1;
        const float* wkp = Wk + ((size_t)((l * Hh + h) * Dd)) * Ed + e2;
        const float* wvp = Wv + ((size_t)((l * Hh + h) * Dd)) * Ed + e2;
        const float* wop = Wo + ((size_t)(l * Ed + e1)) * (Hh * Dd) + h * Dd;
        float sq = 0.0f, sp = 0.0f;
        #pragma unroll 8
        for (int d = 0; d < Dd; ++d) {
            sq = fmaf(wqp[d * Ed], wkp[d * Ed], sq);
            sp = fmaf(wop[d],      wvp[d * Ed], sp);
        }
        sm.mqk[tid] = sq * (0.125f * 1.4426950408889634f);
        sm.wp[tid]  = sp;
    }
    // zero compacted arrays (pads must be exactly 0)
    if (et < 3 * NPAIR) {
        if (et < NPAIR)          E.fA[et] = make_float4(0.f, 0.f, 0.f, 0.f);
        else if (et < 2 * NPAIR) E.fB[et - NPAIR] = make_float4(0.f, 0.f, 0.f, 0.f);
        else                     E.fC2[et - 2 * NPAIR] = make_float2(0.f, 0.f);
    }
    // ballots + layer-0 wsum partials (warps 0..3 of the group)
    if (et < 128) {
        unsigned bmV = __ballot_sync(0xffffffffu, mym);
        unsigned bmM = __ballot_sync(0xffffffffu, (et < NT) && !mym);
        if ((et & 31) == 0) { E.bal[et >> 5] = bmV; E.bal2[et >> 5] = bmM; }
        float vv[Ed] = {f0, f1, f2, f3, f4};
        #pragma unroll
        for (int e = 0; e < Ed; ++e) {
            float v = vv[e];
            #pragma unroll
            for (int off = 16; off > 0; off >>= 1)
                v += __shfl_xor_sync(0xffffffffu, v, off);
            if ((et & 31) == 0) E.wsum[et >> 5][e] = v;
        }
    }
    __syncthreads();

    // compact maps + packed writes
    {
        const int nv_loc = __popc(E.bal[0]) + __popc(E.bal[1]) +
                           __popc(E.bal[2]) + __popc(E.bal[3]);
        if (et == 0) E.nv = nv_loc;
        if (et < NT) {
            if (mym) {
                unsigned bm = E.bal[et >> 5];
                int rank = __popc(bm & ((1u << (et & 31)) - 1u));
                #pragma unroll
                for (int ww = 0; ww < 3; ++ww)
                    if (ww < (et >> 5)) rank += __popc(E.bal[ww]);
                E.cslot[et] = rank;
                E.islot[rank] = et;
                const int jp = rank >> 1, lh = rank & 1;
                float* pA = reinterpret_cast<float*>(&E.fA[jp]);
                pA[lh] = f0;  pA[2 + lh] = f1;
                float* pB = reinterpret_cast<float*>(&E.fB[jp]);
                pB[lh] = f2;  pB[2 + lh] = f3;
                float* pC = reinterpret_cast<float*>(&E.fC2[jp]);
                pC[lh] = f4;
            } else {
                unsigned bm = E.bal2[et >> 5];
                int rank = __popc(bm & ((1u << (et & 31)) - 1u));
                #pragma unroll
                for (int ww = 0; ww < 3; ++ww)
                    if (ww < (et >> 5)) rank += __popc(E.bal2[ww]);
                E.islot[nv_loc + rank] = et;
            }
        }
    }
    __syncthreads();

    const int nv  = E.nv;
    const int nm  = NT - nv;
    const int np2 = (nv + 1) >> 1;
    const int heavyItems = Hh * nv;
    const int lightItems = Hh * nm;
    const float padZ = (nv & 1) ? 1.0f : 0.0f;

    #pragma unroll 1
    for (int l = 0; l < Ll; ++l) {
        // ---- mainloop: heavy items strided over 256 threads -----------------
        for (int it = et; it < heavyItems; it += ETH) {
            int head = 0, row = it;
            if (row >= nv) { ++head; row -= nv; }
            if (row >= nv) { ++head; row -= nv; }
            if (row >= nv) { ++head; row -= nv; }
            const int tok = E.islot[row];
            // gq = Mqk^T . feat_tok
            const float* mq = &sm.mqk[(l * Hh + head) * 25];
            const float fi0 = E.feat[tok][0], fi1 = E.feat[tok][1];
            const float fi2 = E.feat[tok][2], fi3 = E.feat[tok][3];
            const float fi4 = E.feat[tok][4];
            unsigned long long gqs[Ed];
            #pragma unroll
            for (int e2 = 0; e2 < Ed; ++e2) {
                float v = mq[0 * 5 + e2] * fi0;
                v = fmaf(mq[1 * 5 + e2], fi1, v);
                v = fmaf(mq[2 * 5 + e2], fi2, v);
                v = fmaf(mq[3 * 5 + e2], fi3, v);
                v = fmaf(mq[4 * 5 + e2], fi4, v);
                gqs[e2] = splat2(v);
            }
            unsigned long long a0 = 0ULL, a1 = 0ULL, a2 = 0ULL,
                               a3 = 0ULL, a4 = 0ULL, zz = 0ULL;
            #pragma unroll 4
            for (int j2 = 0; j2 < np2; ++j2) {
                ulonglong2 A = *reinterpret_cast<const ulonglong2*>(&E.fA[j2]);
                ulonglong2 Bq = *reinterpret_cast<const ulonglong2*>(&E.fB[j2]);
                unsigned long long Cp =
                    *reinterpret_cast<const unsigned long long*>(&E.fC2[j2]);
                unsigned long long sA = ffma2(gqs[0], A.x, ffma2(gqs[1], A.y, 0ULL));
                unsigned long long sB = ffma2(gqs[2], Bq.x,
                                        ffma2(gqs[3], Bq.y,
                                        ffma2(gqs[4], Cp, 0ULL)));
                unsigned long long s = fadd2(sA, sB);
                float s0, s1;
                unpk2(s, s0, s1);
                unsigned long long pp = pk2(ex2f(s0), ex2f(s1));
                a0 = ffma2(pp, A.x, a0);
                a1 = ffma2(pp, A.y, a1);
                a2 = ffma2(pp, Bq.x, a2);
                a3 = ffma2(pp, Bq.y, a3);
                a4 = ffma2(pp, Cp, a4);
                zz = fadd2(zz, pp);
            }
            float lo, hi, af0, af1, af2, af3, af4, Z;
            unpk2(a0, lo, hi); af0 = lo + hi;
            unpk2(a1, lo, hi); af1 = lo + hi;
            unpk2(a2, lo, hi); af2 = lo + hi;
            unpk2(a3, lo, hi); af3 = lo + hi;
            unpk2(a4, lo, hi); af4 = lo + hi;
            unpk2(zz, lo, hi); Z   = (lo + hi) - padZ;
            const float inv = __fdividef(1.0f, Z);
            const float* wpp = &sm.wp[(l * Hh + head) * 25];
            float o[Ed];
            #pragma unroll
            for (int e = 0; e < Ed; ++e) {
                float s = wpp[e * 5 + 0] * af0;
                s = fmaf(wpp[e * 5 + 1], af1, s);
                s = fmaf(wpp[e * 5 + 2], af2, s);
                s = fmaf(wpp[e * 5 + 3], af3, s);
                s = fmaf(wpp[e * 5 + 4], af4, s);
                o[e] = s * inv;
            }
            E.partA[head][tok] = make_float4(o[0], o[1], o[2], o[3]);
            E.partB[head][tok] = o[4];
        }
        // light items: masked rows, uniform attention closed form
        if (et < lightItems) {
            const float af0 = E.wsum[0][0] + E.wsum[1][0] + E.wsum[2][0] + E.wsum[3][0];
            const float af1 = E.wsum[0][1] + E.wsum[1][1] + E.wsum[2][1] + E.wsum[3][1];
            const float af2 = E.wsum[0][2] + E.wsum[1][2] + E.wsum[2][2] + E.wsum[3][2];
            const float af3 = E.wsum[0][3] + E.wsum[1][3] + E.wsum[2][3] + E.wsum[3][3];
            const float af4 = E.wsum[0][4] + E.wsum[1][4] + E.wsum[2][4] + E.wsum[3][4];
            for (int li = et; li < lightItems; li += ETH) {
                int head = 0, rowm = li;
                if (rowm >= nm) { ++head; rowm -= nm; }
                if (rowm >= nm) { ++head; rowm -= nm; }
                if (rowm >= nm) { ++head; rowm -= nm; }
                const int tok = E.islot[nv + rowm];
                const float* wpp = &sm.wp[(l * Hh + head) * 25];
                float o[Ed];
                #pragma unroll
                for (int e = 0; e < Ed; ++e) {
                    float s = wpp[e * 5 + 0] * af0;
                    s = fmaf(wpp[e * 5 + 1], af1, s);
                    s = fmaf(wpp[e * 5 + 2], af2, s);
                    s = fmaf(wpp[e * 5 + 3], af3, s);
                    s = fmaf(wpp[e * 5 + 4], af4, s);
                    o[e] = s * 0.01f;
                }
                E.partA[head][tok] = make_float4(o[0], o[1], o[2], o[3]);
                E.partB[head][tok] = o[4];
            }
        }
        BAR_EL();

        // ---- epilogue: head-sum + residual + LN1 + FFN + LN2 + wsum ---------
        float nf[Ed] = {0.f, 0.f, 0.f, 0.f, 0.f};
        if (et < NT) {
            float a[Ed];
            #pragma unroll
            for (int e = 0; e < Ed; ++e) a[e] = E.feat[et][e];
            #pragma unroll
            for (int h = 0; h < Hh; ++h) {
                float4 pa = E.partA[h][et];
                a[0] += pa.x; a[1] += pa.y; a[2] += pa.z; a[3] += pa.w;
                a[4] += E.partB[h][et];
            }
            float mu = 0.f;
            #pragma unroll
            for (int e = 0; e < Ed; ++e) mu += a[e];
            mu *= 0.2f;
            float var = 0.f;
            #pragma unroll
            for (int e = 0; e < Ed; ++e) { float dd = a[e] - mu; var = fmaf(dd, dd, var); }
            var *= 0.2f;
            float rinv = rsqrtf(var + 1e-5f);
            float ln1[Ed], fo[Ed];
            #pragma unroll
            for (int e = 0; e < Ed; ++e)
                ln1[e] = (a[e] - mu) * rinv * g1[l * Ed + e] + b1[l * Ed + e];
            #pragma unroll
            for (int e = 0; e < Ed; ++e) {
                float s = bfb[l * Ed + e];
                #pragma unroll
                for (int e2 = 0; e2 < Ed; ++e2)
                    s = fmaf(Wf[((size_t)(l * Ed + e)) * Ed + e2], ln1[e2], s);
                fo[e] = fmaxf(s, 0.0f) + ln1[e];
            }
            float mu2 = 0.f;
            #pragma unroll
            for (int e = 0; e < Ed; ++e) mu2 += fo[e];
            mu2 *= 0.2f;
            float var2 = 0.f;
            #pragma unroll
            for (int e = 0; e < Ed; ++e) { float dd = fo[e] - mu2; var2 = fmaf(dd, dd, var2); }
            var2 *= 0.2f;
            float rinv2 = rsqrtf(var2 + 1e-5f);
            #pragma unroll
            for (int e = 0; e < Ed; ++e) {
                nf[e] = (fo[e] - mu2) * rinv2 * g2[l * Ed + e] + b2[l * Ed + e];
                E.feat[et][e] = nf[e];
            }
            // refresh compacted feat for next layer (valid tokens only)
            if (E.maskf[et] > 0.5f) {
                const int slot = E.cslot[et];
                const int jp = slot >> 1, lh = slot & 1;
                float* pA = reinterpret_cast<float*>(&E.fA[jp]);
                pA[lh] = nf[0];  pA[2 + lh] = nf[1];
                float* pB = reinterpret_cast<float*>(&E.fB[jp]);
                pB[lh] = nf[2];  pB[2 + lh] = nf[3];
                float* pC = reinterpret_cast<float*>(&E.fC2[jp]);
                pC[lh] = nf[4];
            }
        }
        // wsum partials for next layer's fsum (warps 0..3; et>=100 contribute 0)
        if (et < 128) {
            #pragma unroll
            for (int e = 0; e < Ed; ++e) {
                float v = nf[e];
                #pragma unroll
                for (int off = 16; off > 0; off >>= 1)
                    v += __shfl_xor_sync(0xffffffffu, v, off);
                if ((et & 31) == 0) E.wsum[et >> 5][e] = v;
            }
        }
        BAR_EL();
    } // layers

    // ---------------- write output ----------------
    for (int idx = et; idx < NT * Ed; idx += ETH)
        out[(size_t)bb * (NT * Ed) + idx] = (&E.feat[0][0])[idx];
}

extern "C" void kernel_launch(void* const* d_in, const int* in_sizes, int n_in,
                              void* d_out, int out_size)
{
    const float* x   = (const float*)d_in[0];
    const float* Wq  = (const float*)d_in[1];
    const float* Wk  = (const float*)d_in[2];
    const float* Wv  = (const float*)d_in[3];
    const float* Wo  = (const float*)d_in[4];
    const float* Wf  = (const float*)d_in[5];
    const float* bfb = (const float*)d_in[6];
    const float* g1  = (const float*)d_in[7];
    const float* b1  = (const float*)d_in[8];
    const float* g2  = (const float*)d_in[9];
    const float* b2  = (const float*)d_in[10];
    float* out = (float*)d_out;

    encoder_kernel<<<Bb / EPC, NTHREADS>>>(x, Wq, Wk, Wv, Wo, Wf, bfb,
                                           g1, b1, g2, b2, out);
}

// round 17
// speedup vs baseline: 32.1935x; 1.0955x over previous
#include <cuda_runtime.h>
#include <math.h>
#include <float.h>

#define Bb      1024
#define NW      300
#define NT      100      // tokens
#define Ed      5        // embed dim
#define Hh      4        // heads
#define Dd      64       // head dim
#define Ll      3        // layers
#define NTHREADS 512
#define EPC     2        // batch elements per CTA
#define ETH     256      // threads per element group
#define NPAIR   50       // max j-pairs (compacted)

struct Elem {
    float  feat[NT][Ed];
    float  maskf[NT];
    int    cslot[NT];
    int    islot[NT];              // compact row -> token (valid first, then masked)
    unsigned int bal[4], bal2[4];
    int    nv;
    float  wsum[4][Ed];            // per-warp partial sums of feat (for fsum)
    float4 fA[NPAIR];              // compacted (f0_lo,f0_hi,f1_lo,f1_hi)
    float4 fB[NPAIR];              // compacted (f2_lo,f2_hi,f3_lo,f3_hi)
    float2 fC2[NPAIR];             // compacted (f4_lo,f4_hi)
    float4 partA[Hh][NT];
    float  partB[Hh][NT];
};
struct SMem {
    float mqk[Ll * Hh * Ed * Ed];  // folded score matrices (ex2-ready)
    float wp [Ll * Hh * Ed * Ed];  // folded value+output matrices
    Elem  el[EPC];
};

// ---- packed f32x2 helpers ----
__device__ __forceinline__ unsigned long long pk2(float lo, float hi) {
    unsigned long long r;
    asm("mov.b64 %0, {%1, %2};" : "=l"(r) : "f"(lo), "f"(hi));
    return r;
}
__device__ __forceinline__ unsigned long long splat2(float v) {
    unsigned long long r;
    asm("mov.b64 %0, {%1, %1};" : "=l"(r) : "f"(v));
    return r;
}
__device__ __forceinline__ void unpk2(unsigned long long p, float& lo, float& hi) {
    asm("mov.b64 {%0, %1}, %2;" : "=f"(lo), "=f"(hi) : "l"(p));
}
__device__ __forceinline__ unsigned long long ffma2(unsigned long long a,
                                                    unsigned long long b,
                                                    unsigned long long c) {
    unsigned long long d;
    asm("fma.rn.f32x2 %0, %1, %2, %3;" : "=l"(d) : "l"(a), "l"(b), "l"(c));
    return d;
}
__device__ __forceinline__ unsigned long long fadd2(unsigned long long a,
                                                    unsigned long long b) {
    unsigned long long d;
    asm("add.rn.f32x2 %0, %1, %2;" : "=l"(d) : "l"(a), "l"(b));
    return d;
}
__device__ __forceinline__ float ex2f(float x) {
    float r;
    asm("ex2.approx.f32 %0, %1;" : "=f"(r) : "f"(x));
    return r;
}

__global__ __launch_bounds__(NTHREADS, 2)
void encoder_kernel(const float* __restrict__ x,
                    const float* __restrict__ Wq, const float* __restrict__ Wk,
                    const float* __restrict__ Wv, const float* __restrict__ Wo,
                    const float* __restrict__ Wf, const float* __restrict__ bfb,
                    const float* __restrict__ g1, const float* __restrict__ b1,
                    const float* __restrict__ g2, const float* __restrict__ b2,
                    float* __restrict__ out)
{
    __shared__ SMem sm;

    const int tid = threadIdx.x;
    const int eg  = tid >> 8;              // element group 0/1
    const int et  = tid & (ETH - 1);       // thread id within group
    const int bb  = blockIdx.x * EPC + eg; // batch element
    Elem& E = sm.el[eg];

    // ---------------- init: embedding + fold + ballots + layer0 wsum ---------
    bool  mym = false;
    float f0 = 0.f, f1 = 0.f, f2 = 0.f, f3 = 0.f, f4 = 0.f;
    if (et < NT) {
        float k0 = x[bb * NW + et * 3 + 0];
        float k1 = x[bb * NW + et * 3 + 1];
        float k2 = x[bb * NW + et * 3 + 2];
        mym = k2 > 0.0f;
        float sn, cs;
        __sincosf((float)et, &sn, &cs);
        f0 = mym ? k0 : 0.0f; f1 = mym ? k1 : 0.0f; f2 = mym ? k2 : 0.0f;
        f3 = mym ? sn : 0.0f; f4 = mym ? cs : 0.0f;
        E.maskf[et]   = mym ? 1.0f : 0.0f;
        E.feat[et][0] = f0;
        E.feat[et][1] = f1;
        E.feat[et][2] = f2;
        E.feat[et][3] = f3;
        E.feat[et][4] = f4;
    }
    // inline fold (once per CTA, amortized over 2 elements)
    if (tid < Ll * Hh * Ed * Ed) {
        const int l   = tid / (Hh * Ed * Ed);
        const int rem = tid % (Hh * Ed * Ed);
        const int h   = rem / (Ed * Ed);
        const int e1  = (rem / Ed) % Ed;
        const int e2  = rem % Ed;
        const float* wqp = Wq + ((size_t)((l * Hh + h) * Dd)) * Ed + e1;
        const float* wkp = Wk + ((size_t)((l * Hh + h) * Dd)) * Ed + e2;
        const float* wvp = Wv + ((size_t)((l * Hh + h) * Dd)) * Ed + e2;
        const float* wop = Wo + ((size_t)(l * Ed + e1)) * (Hh * Dd) + h * Dd;
        float sq0 = 0.f, sq1 = 0.f, sp0 = 0.f, sp1 = 0.f;
        #pragma unroll 4
        for (int d = 0; d < Dd; d += 2) {
            sq0 = fmaf(wqp[d * Ed], wkp[d * Ed], sq0);
            sp0 = fmaf(wop[d],      wvp[d * Ed], sp0);
            sq1 = fmaf(wqp[(d + 1) * Ed], wkp[(d + 1) * Ed], sq1);
            sp1 = fmaf(wop[d + 1],        wvp[(d + 1) * Ed], sp1);
        }
        sm.mqk[tid] = (sq0 + sq1) * (0.125f * 1.4426950408889634f);
        sm.wp[tid]  = sp0 + sp1;
    }
    // zero compacted arrays (pads must be exactly 0)
    if (et < 3 * NPAIR) {
        if (et < NPAIR)          E.fA[et] = make_float4(0.f, 0.f, 0.f, 0.f);
        else if (et < 2 * NPAIR) E.fB[et - NPAIR] = make_float4(0.f, 0.f, 0.f, 0.f);
        else                     E.fC2[et - 2 * NPAIR] = make_float2(0.f, 0.f);
    }
    // ballots + layer-0 wsum partials (warps 0..3 of the group)
    if (et < 128) {
        unsigned bmV = __ballot_sync(0xffffffffu, mym);
        unsigned bmM = __ballot_sync(0xffffffffu, (et < NT) && !mym);
        if ((et & 31) == 0) { E.bal[et >> 5] = bmV; E.bal2[et >> 5] = bmM; }
        float vv[Ed] = {f0, f1, f2, f3, f4};
        #pragma unroll
        for (int e = 0; e < Ed; ++e) {
            float v = vv[e];
            #pragma unroll
            for (int off = 16; off > 0; off >>= 1)
                v += __shfl_xor_sync(0xffffffffu, v, off);
            if ((et & 31) == 0) E.wsum[et >> 5][e] = v;
        }
    }
    __syncthreads();

    // compact maps + packed writes
    {
        const int nv_loc = __popc(E.bal[0]) + __popc(E.bal[1]) +
                           __popc(E.bal[2]) + __popc(E.bal[3]);
        if (et == 0) E.nv = nv_loc;
        if (et < NT) {
            if (mym) {
                unsigned bm = E.bal[et >> 5];
                int rank = __popc(bm & ((1u << (et & 31)) - 1u));
                #pragma unroll
                for (int ww = 0; ww < 3; ++ww)
                    if (ww < (et >> 5)) rank += __popc(E.bal[ww]);
                E.cslot[et] = rank;
                E.islot[rank] = et;
                const int jp = rank >> 1, lh = rank & 1;
                float* pA = reinterpret_cast<float*>(&E.fA[jp]);
                pA[lh] = f0;  pA[2 + lh] = f1;
                float* pB = reinterpret_cast<float*>(&E.fB[jp]);
                pB[lh] = f2;  pB[2 + lh] = f3;
                float* pC = reinterpret_cast<float*>(&E.fC2[jp]);
                pC[lh] = f4;
            } else {
                unsigned bm = E.bal2[et >> 5];
                int rank = __popc(bm & ((1u << (et & 31)) - 1u));
                #pragma unroll
                for (int ww = 0; ww < 3; ++ww)
                    if (ww < (et >> 5)) rank += __popc(E.bal2[ww]);
                E.islot[nv_loc + rank] = et;
            }
        }
    }
    __syncthreads();

    const int nv0 = sm.el[0].nv;
    const int nv1 = sm.el[1].nv;
    const int hv0 = Hh * nv0;                 // heavy items of element 0
    const int totHeavy = Hh * (nv0 + nv1);
    const int totLight = Hh * (2 * NT - nv0 - nv1);

    #pragma unroll 1
    for (int l = 0; l < Ll; ++l) {
        // ---- mainloop: pooled heavy items over the whole CTA ----------------
        for (int it = tid; it < totHeavy; it += NTHREADS) {
            int ege = 0, local = it;
            if (it >= hv0) { ege = 1; local = it - hv0; }
            Elem& EE = sm.el[ege];
            const int nvE = ege ? nv1 : nv0;
            int head = 0, row = local;
            if (row >= nvE) { ++head; row -= nvE; }
            if (row >= nvE) { ++head; row -= nvE; }
            if (row >= nvE) { ++head; row -= nvE; }
            const int tok = EE.islot[row];
            const int np2 = (nvE + 1) >> 1;
            const float padZ = (nvE & 1) ? 1.0f : 0.0f;
            // gq = Mqk^T . feat_tok
            const float* mq = &sm.mqk[(l * Hh + head) * 25];
            const float fi0 = EE.feat[tok][0], fi1 = EE.feat[tok][1];
            const float fi2 = EE.feat[tok][2], fi3 = EE.feat[tok][3];
            const float fi4 = EE.feat[tok][4];
            unsigned long long gqs[Ed];
            #pragma unroll
            for (int e2 = 0; e2 < Ed; ++e2) {
                float v = mq[0 * 5 + e2] * fi0;
                v = fmaf(mq[1 * 5 + e2], fi1, v);
                v = fmaf(mq[2 * 5 + e2], fi2, v);
                v = fmaf(mq[3 * 5 + e2], fi3, v);
                v = fmaf(mq[4 * 5 + e2], fi4, v);
                gqs[e2] = splat2(v);
            }
            unsigned long long a0 = 0ULL, a1 = 0ULL, a2 = 0ULL,
                               a3 = 0ULL, a4 = 0ULL, zz = 0ULL;
            #pragma unroll 4
            for (int j2 = 0; j2 < np2; ++j2) {
                ulonglong2 A = *reinterpret_cast<const ulonglong2*>(&EE.fA[j2]);
                ulonglong2 Bq = *reinterpret_cast<const ulonglong2*>(&EE.fB[j2]);
                unsigned long long Cp =
                    *reinterpret_cast<const unsigned long long*>(&EE.fC2[j2]);
                unsigned long long sA = ffma2(gqs[0], A.x, ffma2(gqs[1], A.y, 0ULL));
                unsigned long long sB = ffma2(gqs[2], Bq.x,
                                        ffma2(gqs[3], Bq.y,
                                        ffma2(gqs[4], Cp, 0ULL)));
                unsigned long long s = fadd2(sA, sB);
                float s0, s1;
                unpk2(s, s0, s1);
                unsigned long long pp = pk2(ex2f(s0), ex2f(s1));
                a0 = ffma2(pp, A.x, a0);
                a1 = ffma2(pp, A.y, a1);
                a2 = ffma2(pp, Bq.x, a2);
                a3 = ffma2(pp, Bq.y, a3);
                a4 = ffma2(pp, Cp, a4);
                zz = fadd2(zz, pp);
            }
            float lo, hi, af0, af1, af2, af3, af4, Z;
            unpk2(a0, lo, hi); af0 = lo + hi;
            unpk2(a1, lo, hi); af1 = lo + hi;
            unpk2(a2, lo, hi); af2 = lo + hi;
            unpk2(a3, lo, hi); af3 = lo + hi;
            unpk2(a4, lo, hi); af4 = lo + hi;
            unpk2(zz, lo, hi); Z   = (lo + hi) - padZ;
            const float inv = __fdividef(1.0f, Z);
            const float* wpp = &sm.wp[(l * Hh + head) * 25];
            float o[Ed];
            #pragma unroll
            for (int e = 0; e < Ed; ++e) {
                float s = wpp[e * 5 + 0] * af0;
                s = fmaf(wpp[e * 5 + 1], af1, s);
                s = fmaf(wpp[e * 5 + 2], af2, s);
                s = fmaf(wpp[e * 5 + 3], af3, s);
                s = fmaf(wpp[e * 5 + 4], af4, s);
                o[e] = s * inv;
            }
            EE.partA[head][tok] = make_float4(o[0], o[1], o[2], o[3]);
            EE.partB[head][tok] = o[4];
        }
        // ---- pooled light items (masked rows: uniform closed form) ----------
        for (int li = tid; li < totLight; li += NTHREADS) {
            const int lm0 = Hh * (NT - nv0);
            int ege = 0, local = li;
            if (li >= lm0) { ege = 1; local = li - lm0; }
            Elem& EE = sm.el[ege];
            const int nvE = ege ? nv1 : nv0;
            const int nmE = NT - nvE;
            int head = 0, rowm = local;
            if (rowm >= nmE) { ++head; rowm -= nmE; }
            if (rowm >= nmE) { ++head; rowm -= nmE; }
            if (rowm >= nmE) { ++head; rowm -= nmE; }
            const int tok = EE.islot[nvE + rowm];
            const float af0 = EE.wsum[0][0] + EE.wsum[1][0] + EE.wsum[2][0] + EE.wsum[3][0];
            const float af1 = EE.wsum[0][1] + EE.wsum[1][1] + EE.wsum[2][1] + EE.wsum[3][1];
            const float af2 = EE.wsum[0][2] + EE.wsum[1][2] + EE.wsum[2][2] + EE.wsum[3][2];
            const float af3 = EE.wsum[0][3] + EE.wsum[1][3] + EE.wsum[2][3] + EE.wsum[3][3];
            const float af4 = EE.wsum[0][4] + EE.wsum[1][4] + EE.wsum[2][4] + EE.wsum[3][4];
            const float* wpp = &sm.wp[(l * Hh + head) * 25];
            float o[Ed];
            #pragma unroll
            for (int e = 0; e < Ed; ++e) {
                float s = wpp[e * 5 + 0] * af0;
                s = fmaf(wpp[e * 5 + 1], af1, s);
                s = fmaf(wpp[e * 5 + 2], af2, s);
                s = fmaf(wpp[e * 5 + 3], af3, s);
                s = fmaf(wpp[e * 5 + 4], af4, s);
                o[e] = s * 0.01f;
            }
            EE.partA[head][tok] = make_float4(o[0], o[1], o[2], o[3]);
            EE.partB[head][tok] = o[4];
        }
        __syncthreads();

        // ---- epilogue: head-sum + residual + LN1 + FFN + LN2 + wsum ---------
        float nf[Ed] = {0.f, 0.f, 0.f, 0.f, 0.f};
        if (et < NT) {
            float a[Ed];
            #pragma unroll
            for (int e = 0; e < Ed; ++e) a[e] = E.feat[et][e];
            #pragma unroll
            for (int h = 0; h < Hh; ++h) {
                float4 pa = E.partA[h][et];
                a[0] += pa.x; a[1] += pa.y; a[2] += pa.z; a[3] += pa.w;
                a[4] += E.partB[h][et];
            }
            float mu = 0.f;
            #pragma unroll
            for (int e = 0; e < Ed; ++e) mu += a[e];
            mu *= 0.2f;
            float var = 0.f;
            #pragma unroll
            for (int e = 0; e < Ed; ++e) { float dd = a[e] - mu; var = fmaf(dd, dd, var); }
            var *= 0.2f;
            float rinv = rsqrtf(var + 1e-5f);
            float ln1[Ed], fo[Ed];
            #pragma unroll
            for (int e = 0; e < Ed; ++e)
                ln1[e] = (a[e] - mu) * rinv * g1[l * Ed + e] + b1[l * Ed + e];
            #pragma unroll
            for (int e = 0; e < Ed; ++e) {
                float s = bfb[l * Ed + e];
                #pragma unroll
                for (int e2 = 0; e2 < Ed; ++e2)
                    s = fmaf(Wf[((size_t)(l * Ed + e)) * Ed + e2], ln1[e2], s);
                fo[e] = fmaxf(s, 0.0f) + ln1[e];
            }
            float mu2 = 0.f;
            #pragma unroll
            for (int e = 0; e < Ed; ++e) mu2 += fo[e];
            mu2 *= 0.2f;
            float var2 = 0.f;
            #pragma unroll
            for (int e = 0; e < Ed; ++e) { float dd = fo[e] - mu2; var2 = fmaf(dd, dd, var2); }
            var2 *= 0.2f;
            float rinv2 = rsqrtf(var2 + 1e-5f);
            #pragma unroll
            for (int e = 0; e < Ed; ++e) {
                nf[e] = (fo[e] - mu2) * rinv2 * g2[l * Ed + e] + b2[l * Ed + e];
                E.feat[et][e] = nf[e];
            }
            // refresh compacted feat for next layer (valid tokens only)
            if (E.maskf[et] > 0.5f) {
                const int slot = E.cslot[et];
                const int jp = slot >> 1, lh = slot & 1;
                float* pA = reinterpret_cast<float*>(&E.fA[jp]);
                pA[lh] = nf[0];  pA[2 + lh] = nf[1];
                float* pB = reinterpret_cast<float*>(&E.fB[jp]);
                pB[lh] = nf[2];  pB[2 + lh] = nf[3];
                float* pC = reinterpret_cast<float*>(&E.fC2[jp]);
                pC[lh] = nf[4];
            }
        }
        // wsum partials for next layer's fsum (warps 0..3; et>=100 contribute 0)
        if (et < 128) {
            #pragma unroll
            for (int e = 0; e < Ed; ++e) {
                float v = nf[e];
                #pragma unroll
                for (int off = 16; off > 0; off >>= 1)
                    v += __shfl_xor_sync(0xffffffffu, v, off);
                if ((et & 31) == 0) E.wsum[et >> 5][e] = v;
            }
        }
        __syncthreads();
    } // layers

    // ---------------- write output ----------------
    for (int idx = et; idx < NT * Ed; idx += ETH)
        out[(size_t)bb * (NT * Ed) + idx] = (&E.feat[0][0])[idx];
}

extern "C" void kernel_launch(void* const* d_in, const int* in_sizes, int n_in,
                              void* d_out, int out_size)
{
    const float* x   = (const float*)d_in[0];
    const float* Wq  = (const float*)d_in[1];
    const float* Wk  = (const float*)d_in[2];
    const float* Wv  = (const float*)d_in[3];
    const float* Wo  = (const float*)d_in[4];
    const float* Wf  = (const float*)d_in[5];
    const float* bfb = (const float*)d_in[6];
    const float* g1  = (const float*)d_in[7];
    const float* b1  = (const float*)d_in[8];
    const float* g2  = (const float*)d_in[9];
    const float* b2  = (const float*)d_in[10];
    float* out = (float*)d_out;

    encoder_kernel<<<Bb / EPC, NTHREADS>>>(x, Wq, Wk, Wv, Wo, Wf, bfb,
                                           g1, b1, g2, b2, out);
}